// round 1
// baseline (speedup 1.0000x reference)
#include <cuda_runtime.h>
#include <math.h>

#define BATCH 256
#define C1 256
#define IMGD 28
#define H1 20
#define NPRIM 1152
#define NC 10
#define PCD 8
#define DCD 16

// ---------------- scratch (static device allocations are allowed) ----------------
__device__ float g_x[BATCH * C1 * H1 * H1];        // conv1 output  [b][ic][20*20]   100 MB
__device__ float g_pc[BATCH * C1 * 36];            // pc conv out   [b][oc][36]      9.4 MB
__device__ float g_u[BATCH * NPRIM * PCD];         // squashed caps [b][n][8]        9.4 MB
__device__ float g_WU[(size_t)BATCH * NPRIM * NC * DCD]; // u_hat  [b][n][c*16+d]   189 MB
__device__ float g_v[BATCH * NC * DCD];            // routed caps   [b][c*16+d]

// ---------------- conv1 + relu: [256,1,28,28] -> [256,256,20,20] ----------------
// grid (4 ocg, 256 b), 256 threads. smem: image + transposed weights (stride 66).
__global__ void conv1_kernel(const float* __restrict__ in,
                             const float* __restrict__ w,
                             const float* __restrict__ bias) {
    __shared__ float s_img[IMGD * IMGD];
    __shared__ float s_w[81 * 66];
    const int b = blockIdx.y, ocg = blockIdx.x, tid = threadIdx.x;
    const int oc0 = ocg * 64;
    for (int i = tid; i < IMGD * IMGD; i += 256) s_img[i] = in[b * IMGD * IMGD + i];
    for (int i = tid; i < 64 * 81; i += 256) {
        int o = i / 81, k = i % 81;
        s_w[k * 66 + o] = w[(oc0 + o) * 81 + k];
    }
    __syncthreads();

    const int ocp = tid >> 3;        // 0..31 (oc pair)
    const int slot = tid & 7;        // 0..7
    const float bv0 = bias[oc0 + 2 * ocp];
    const float bv1 = bias[oc0 + 2 * ocp + 1];

    for (int it = 0; it < 25; ++it) {
        const int pp = it * 8 + slot;      // 0..199
        const int px0 = 2 * pp;            // even -> ox0 <= 18, same row as px0+1
        const int oy = px0 / 20, ox = px0 % 20;
        float a00 = 0.f, a01 = 0.f, a10 = 0.f, a11 = 0.f;
        #pragma unroll 3
        for (int ky = 0; ky < 9; ++ky) {
            const float* r = &s_img[(oy + ky) * IMGD + ox];
            #pragma unroll
            for (int kx = 0; kx < 9; ++kx) {
                float2 wv = *(const float2*)&s_w[(ky * 9 + kx) * 66 + 2 * ocp];
                float i0 = r[kx], i1 = r[kx + 1];
                a00 += wv.x * i0; a01 += wv.x * i1;
                a10 += wv.y * i0; a11 += wv.y * i1;
            }
        }
        const int base0 = (b * C1 + oc0 + 2 * ocp) * 400;
        g_x[base0 + px0]       = fmaxf(a00 + bv0, 0.f);
        g_x[base0 + px0 + 1]   = fmaxf(a01 + bv0, 0.f);
        g_x[base0 + 400 + px0]     = fmaxf(a10 + bv1, 0.f);
        g_x[base0 + 400 + px0 + 1] = fmaxf(a11 + bv1, 0.f);
    }
}

// ---------------- pc conv stride 2: [256,256,20,20] -> [256,256,6,6] ----------------
// grid (4 ocg, 256 b), 288 threads (9 warps). Thread tile: 2 oc x 4 spatial.
__global__ void pcconv_kernel(const float* __restrict__ w,
                              const float* __restrict__ bias) {
    __shared__ float s_x[400];
    __shared__ float s_w[81 * 66];
    const int b = blockIdx.y, ocg = blockIdx.x, tid = threadIdx.x;
    const int oc0 = ocg * 64;
    const int ocp = tid / 9;   // 0..31
    const int spg = tid % 9;   // 0..8, covers spatial spg*4..spg*4+3

    int row[4], col[4];
    #pragma unroll
    for (int j = 0; j < 4; ++j) {
        int sp = spg * 4 + j;
        row[j] = 2 * (sp / 6);
        col[j] = 2 * (sp % 6);
    }
    float acc0[4] = {0.f, 0.f, 0.f, 0.f};
    float acc1[4] = {0.f, 0.f, 0.f, 0.f};

    for (int ic = 0; ic < 256; ++ic) {
        __syncthreads();
        for (int i = tid; i < 400; i += 288) s_x[i] = g_x[(b * C1 + ic) * 400 + i];
        for (int i = tid; i < 64 * 81; i += 288) {
            int o = i / 81, k = i % 81;
            s_w[k * 66 + o] = w[(oc0 + o) * (256 * 81) + ic * 81 + k];
        }
        __syncthreads();
        #pragma unroll 3
        for (int ky = 0; ky < 9; ++ky) {
            #pragma unroll
            for (int kx = 0; kx < 9; ++kx) {
                float2 wv = *(const float2*)&s_w[(ky * 9 + kx) * 66 + 2 * ocp];
                #pragma unroll
                for (int j = 0; j < 4; ++j) {
                    float xv = s_x[(row[j] + ky) * 20 + col[j] + kx];
                    acc0[j] += wv.x * xv;
                    acc1[j] += wv.y * xv;
                }
            }
        }
    }
    const float bv0 = bias[oc0 + 2 * ocp];
    const float bv1 = bias[oc0 + 2 * ocp + 1];
    const int base0 = (b * C1 + oc0 + 2 * ocp) * 36;
    #pragma unroll
    for (int j = 0; j < 4; ++j) {
        int sp = spg * 4 + j;
        g_pc[base0 + sp]      = acc0[j] + bv0;
        g_pc[base0 + 36 + sp] = acc1[j] + bv1;
    }
}

// ---------------- squash primary capsules: pc[b, d*32+m, s] -> u[b, n=m*36+s, d] ----------------
__global__ void squash_u_kernel() {
    const int idx = blockIdx.x * 256 + threadIdx.x;
    if (idx >= BATCH * NPRIM) return;
    const int b = idx / NPRIM, n = idx % NPRIM;
    const int m = n / 36, s = n % 36;
    const float* base = &g_pc[b * (C1 * 36) + m * 36 + s];
    float v[PCD];
    float sq = 0.f;
    #pragma unroll
    for (int d = 0; d < PCD; ++d) {
        v[d] = base[d * 32 * 36];
        sq += v[d] * v[d];
    }
    const float sc = sq / (1.f + sq) / sqrtf(sq + 1e-7f);
    #pragma unroll
    for (int d = 0; d < PCD; ++d) g_u[idx * PCD + d] = v[d] * sc;
}

// ---------------- u_hat: WU[b,n,c,d] = sum_p W[n,c,d,p] * u[b,n,p] ----------------
// grid 1152 (n), 160 threads (c*16+d).
__global__ void wu_kernel(const float* __restrict__ W) {
    const int n = blockIdx.x;
    const int t = threadIdx.x;   // 0..159
    float wreg[PCD];
    #pragma unroll
    for (int p = 0; p < PCD; ++p) wreg[p] = W[n * (NC * DCD * PCD) + t * PCD + p];
    for (int b = 0; b < BATCH; ++b) {
        const float* up = &g_u[(b * NPRIM + n) * PCD];
        float dot = 0.f;
        #pragma unroll
        for (int p = 0; p < PCD; ++p) dot += wreg[p] * __ldg(&up[p]);
        g_WU[((size_t)(b * NPRIM + n)) * 160 + t] = dot;
    }
}

// ---------------- dynamic routing, 3 iters, one block per batch element ----------------
// 320 threads. dyn smem: bij[11520] + c[11520] + v[160] + red[320] + scale[10]
__global__ void routing_kernel(float* __restrict__ out) {
    extern __shared__ float sm[];
    float* s_bij   = sm;
    float* s_c     = sm + 11520;
    float* s_v     = sm + 23040;
    float* s_red   = sm + 23200;
    float* s_scale = sm + 23520;
    const int b = blockIdx.x;
    const int tid = threadIdx.x;   // 0..319
    const size_t wubase = (size_t)b * NPRIM * 160;
    const int half = tid / 160;    // 0 or 1
    const int pair = tid % 160;    // c*16+d
    const int c = pair / 16, d = pair & 15;

    for (int i = tid; i < NPRIM * NC; i += 320) s_bij[i] = 0.f;

    for (int it = 0; it < 3; ++it) {
        __syncthreads();
        // softmax over classes
        for (int n = tid; n < NPRIM; n += 320) {
            float vals[NC], mx = -1e30f;
            #pragma unroll
            for (int k = 0; k < NC; ++k) { vals[k] = s_bij[n * NC + k]; mx = fmaxf(mx, vals[k]); }
            float ssum = 0.f;
            #pragma unroll
            for (int k = 0; k < NC; ++k) { vals[k] = expf(vals[k] - mx); ssum += vals[k]; }
            const float inv = 1.f / ssum;
            #pragma unroll
            for (int k = 0; k < NC; ++k) s_c[n * NC + k] = vals[k] * inv;
        }
        __syncthreads();
        // v = sum_n c * WU
        float acc = 0.f;
        for (int n = half; n < NPRIM; n += 2)
            acc += s_c[n * NC + c] * g_WU[wubase + n * 160 + pair];
        s_red[tid] = acc;
        __syncthreads();
        if (tid < 160) s_v[tid] = s_red[tid] + s_red[tid + 160];
        __syncthreads();
        if (tid < NC) {
            float sq = 0.f;
            #pragma unroll
            for (int k = 0; k < DCD; ++k) { float x = s_v[tid * DCD + k]; sq += x * x; }
            s_scale[tid] = sq / (1.f + sq) / sqrtf(sq + 1e-7f);
        }
        __syncthreads();
        if (tid < 160) s_v[tid] *= s_scale[c];
        __syncthreads();
        if (it < 2) {
            // b_ij += sum_d v * (c * WU)
            for (int n = half; n < NPRIM; n += 2) {
                float val = s_v[pair] * s_c[n * NC + c] * g_WU[wubase + n * 160 + pair];
                #pragma unroll
                for (int o = 8; o >= 1; o >>= 1) val += __shfl_xor_sync(0xffffffffu, val, o);
                if (d == 0) s_bij[n * NC + c] += val;
            }
        }
    }
    if (tid < 160) g_v[b * 160 + tid] = s_v[tid];
    if (tid < NC) {
        float sq = 0.f;
        #pragma unroll
        for (int k = 0; k < DCD; ++k) { float x = s_v[tid * DCD + k]; sq += x * x; }
        out[b * NC + tid] = sqrtf(sq);  // clf
    }
}

// ---------------- masked decoder: 3 FC layers, 2 batch elems per block ----------------
__global__ void decoder_kernel(const int* __restrict__ labels,
                               const float* __restrict__ w1, const float* __restrict__ bb1,
                               const float* __restrict__ w2, const float* __restrict__ bb2,
                               const float* __restrict__ w3, const float* __restrict__ bb3,
                               float* __restrict__ out) {
    __shared__ float h0[2][DCD];      // only the labeled class's 16 dims are nonzero
    __shared__ float h1[2][512];
    __shared__ float h2[2][1024];
    __shared__ int   lab[2];
    const int t = threadIdx.x;        // 0..255
    const int b0 = blockIdx.x * 2, b1i = b0 + 1;
    if (t < 2) lab[t] = labels[b0 + t];
    __syncthreads();
    if (t < DCD) {
        h0[0][t] = g_v[b0 * 160 + lab[0] * DCD + t];
        h0[1][t] = g_v[b1i * 160 + lab[1] * DCD + t];
    }
    __syncthreads();
    // layer 1: only rows [lab*16, lab*16+16) of w1 contribute
    for (int j = t; j < 512; j += 256) {
        float a0 = bb1[j], a1 = bb1[j];
        #pragma unroll
        for (int k = 0; k < DCD; ++k) {
            a0 += h0[0][k] * w1[(lab[0] * DCD + k) * 512 + j];
            a1 += h0[1][k] * w1[(lab[1] * DCD + k) * 512 + j];
        }
        h1[0][j] = fmaxf(a0, 0.f);
        h1[1][j] = fmaxf(a1, 0.f);
    }
    __syncthreads();
    for (int j = t; j < 1024; j += 256) {
        float a0 = bb2[j], a1 = bb2[j];
        for (int i = 0; i < 512; ++i) {
            float wv = w2[i * 1024 + j];
            a0 += h1[0][i] * wv;
            a1 += h1[1][i] * wv;
        }
        h2[0][j] = fmaxf(a0, 0.f);
        h2[1][j] = fmaxf(a1, 0.f);
    }
    __syncthreads();
    for (int j = t; j < 784; j += 256) {
        float a0 = bb3[j], a1 = bb3[j];
        for (int i = 0; i < 1024; ++i) {
            float wv = w3[i * 784 + j];
            a0 += h2[0][i] * wv;
            a1 += h2[1][i] * wv;
        }
        out[BATCH * NC + b0 * 784 + j]  = 1.f / (1.f + expf(-a0));
        out[BATCH * NC + b1i * 784 + j] = 1.f / (1.f + expf(-a1));
    }
}

// ---------------- launch ----------------
extern "C" void kernel_launch(void* const* d_in, const int* in_sizes, int n_in,
                              void* d_out, int out_size) {
    const float* inputs  = (const float*)d_in[0];
    const int*   labels  = (const int*)d_in[1];
    const float* conv1_w = (const float*)d_in[2];
    const float* conv1_b = (const float*)d_in[3];
    const float* pc_w    = (const float*)d_in[4];
    const float* pc_b    = (const float*)d_in[5];
    const float* rw      = (const float*)d_in[6];
    const float* dw1     = (const float*)d_in[7];
    const float* db1     = (const float*)d_in[8];
    const float* dw2     = (const float*)d_in[9];
    const float* db2     = (const float*)d_in[10];
    const float* dw3     = (const float*)d_in[11];
    const float* db3     = (const float*)d_in[12];
    float* out = (float*)d_out;

    conv1_kernel<<<dim3(4, BATCH), 256>>>(inputs, conv1_w, conv1_b);
    pcconv_kernel<<<dim3(4, BATCH), 288>>>(pc_w, pc_b);
    squash_u_kernel<<<(BATCH * NPRIM) / 256, 256>>>();
    wu_kernel<<<NPRIM, 160>>>(rw);

    const int routing_smem = (11520 + 11520 + 160 + 320 + 16) * (int)sizeof(float);
    cudaFuncSetAttribute(routing_kernel, cudaFuncAttributeMaxDynamicSharedMemorySize,
                         routing_smem);
    routing_kernel<<<BATCH, 320, routing_smem>>>(out);

    decoder_kernel<<<BATCH / 2, 256>>>(labels, dw1, db1, dw2, db2, dw3, db3, out);
}

// round 3
// speedup vs baseline: 3.5707x; 3.5707x over previous
#include <cuda_runtime.h>
#include <cuda_bf16.h>
#include <math.h>
#include <stdint.h>

#define BATCH 256
#define C1 256
#define IMGD 28
#define H1 20
#define NPRIM 1152
#define NC 10
#define PCD 8
#define DCD 16
#define KTOT 20736           // 256 ic * 81
#define MTOT 9216            // 256 b * 36 sp
#define KTILE 64             // bf16 per K-tile (128 bytes)
#define NKT (KTOT / KTILE)   // 324
#define TOTKT (3 * NKT)      // 972 (3 bf16x3 passes)

// ---------------- scratch ----------------
__device__ float g_x[BATCH * C1 * H1 * H1];          // conv1 out [b][ic][400]
__device__ float g_pc[(size_t)MTOT * C1];            // pc conv out [m=b*36+sp][oc]
__device__ float g_u[BATCH * NPRIM * PCD];           // squashed, TRANSPOSED: [n][b][p]
__device__ float g_WU[(size_t)BATCH * NPRIM * NC * DCD];
__device__ float g_v[BATCH * NC * DCD];
__device__ __align__(16) __nv_bfloat16 g_Ahi[(size_t)MTOT * KTOT];
__device__ __align__(16) __nv_bfloat16 g_Alo[(size_t)MTOT * KTOT];
__device__ __align__(16) __nv_bfloat16 g_Bhi[(size_t)C1 * KTOT];
__device__ __align__(16) __nv_bfloat16 g_Blo[(size_t)C1 * KTOT];

__device__ __forceinline__ uint32_t smem_u32(const void* p) {
    uint32_t a;
    asm("{ .reg .u64 t; cvta.to.shared.u64 t, %1; cvt.u32.u64 %0, t; }" : "=r"(a) : "l"(p));
    return a;
}
#define CP_ASYNC16(sa, ga) \
    asm volatile("cp.async.cg.shared.global [%0], [%1], 16;" :: "r"(sa), "l"(ga))
#define CP_COMMIT() asm volatile("cp.async.commit_group;" ::: "memory")
#define CP_WAIT2()  asm volatile("cp.async.wait_group 2;" ::: "memory")
#define CP_WAIT0()  asm volatile("cp.async.wait_group 0;" ::: "memory")
#define LDMX4(r0, r1, r2, r3, a) \
    asm volatile("ldmatrix.sync.aligned.m8n8.x4.shared.b16 {%0,%1,%2,%3}, [%4];" \
        : "=r"(r0), "=r"(r1), "=r"(r2), "=r"(r3) : "r"(a))
#define MMA16816(c, a, b0, b1) \
    asm volatile("mma.sync.aligned.m16n8k16.row.col.f32.bf16.bf16.f32 " \
        "{%0,%1,%2,%3},{%4,%5,%6,%7},{%8,%9},{%0,%1,%2,%3};" \
        : "+f"((c)[0]), "+f"((c)[1]), "+f"((c)[2]), "+f"((c)[3]) \
        : "r"((a)[0]), "r"((a)[1]), "r"((a)[2]), "r"((a)[3]), "r"(b0), "r"(b1))

// ---------------- conv1 + relu: [256,1,28,28] -> [256,256,20,20] ----------------
__global__ void conv1_kernel(const float* __restrict__ in,
                             const float* __restrict__ w,
                             const float* __restrict__ bias) {
    __shared__ float s_img[IMGD * IMGD];
    __shared__ float s_w[81 * 66];
    const int b = blockIdx.y, ocg = blockIdx.x, tid = threadIdx.x;
    const int oc0 = ocg * 64;
    for (int i = tid; i < IMGD * IMGD; i += 256) s_img[i] = in[b * IMGD * IMGD + i];
    for (int i = tid; i < 64 * 81; i += 256) {
        int o = i / 81, k = i % 81;
        s_w[k * 66 + o] = w[(oc0 + o) * 81 + k];
    }
    __syncthreads();
    const int ocp = tid >> 3;
    const int slot = tid & 7;
    const float bv0 = bias[oc0 + 2 * ocp];
    const float bv1 = bias[oc0 + 2 * ocp + 1];
    for (int it = 0; it < 25; ++it) {
        const int px0 = 2 * (it * 8 + slot);
        const int oy = px0 / 20, ox = px0 % 20;
        float a00 = 0.f, a01 = 0.f, a10 = 0.f, a11 = 0.f;
        #pragma unroll 3
        for (int ky = 0; ky < 9; ++ky) {
            const float* r = &s_img[(oy + ky) * IMGD + ox];
            #pragma unroll
            for (int kx = 0; kx < 9; ++kx) {
                float2 wv = *(const float2*)&s_w[(ky * 9 + kx) * 66 + 2 * ocp];
                float i0 = r[kx], i1 = r[kx + 1];
                a00 += wv.x * i0; a01 += wv.x * i1;
                a10 += wv.y * i0; a11 += wv.y * i1;
            }
        }
        const int base0 = (b * C1 + oc0 + 2 * ocp) * 400;
        g_x[base0 + px0]           = fmaxf(a00 + bv0, 0.f);
        g_x[base0 + px0 + 1]       = fmaxf(a01 + bv0, 0.f);
        g_x[base0 + 400 + px0]     = fmaxf(a10 + bv1, 0.f);
        g_x[base0 + 400 + px0 + 1] = fmaxf(a11 + bv1, 0.f);
    }
}

// ---------------- split pc_w into bf16 hi/lo ----------------
__global__ void convert_w_kernel(const float* __restrict__ w) {
    const size_t i4 = (size_t)blockIdx.x * 256 + threadIdx.x;
    if (i4 >= (size_t)C1 * KTOT / 4) return;
    float4 v = ((const float4*)w)[i4];
    __nv_bfloat16 h[4], l[4];
    float xs[4] = {v.x, v.y, v.z, v.w};
    #pragma unroll
    for (int j = 0; j < 4; ++j) {
        h[j] = __float2bfloat16_rn(xs[j]);
        l[j] = __float2bfloat16_rn(xs[j] - __bfloat162float(h[j]));
    }
    *(uint2*)&g_Bhi[i4 * 4] = *(uint2*)h;
    *(uint2*)&g_Blo[i4 * 4] = *(uint2*)l;
}

// ---------------- im2col: g_x -> A[m][k] bf16 hi/lo (k = ic*81 + ky*9 + kx) ----------------
__global__ void im2col_kernel() {
    extern __shared__ char sm[];
    __nv_bfloat16* s_hi = (__nv_bfloat16*)sm;
    __nv_bfloat16* s_lo = (__nv_bfloat16*)(sm + KTOT * 2);
    const int m = blockIdx.x;
    const int tid = threadIdx.x;
    const int b = m / 36, sp = m % 36;
    const int sr2 = 2 * (sp / 6), sc2 = 2 * (sp % 6);
    {
        const int ic = tid;
        const float* src = &g_x[((size_t)(b * C1 + ic)) * 400 + sr2 * 20 + sc2];
        #pragma unroll
        for (int ky = 0; ky < 9; ++ky) {
            #pragma unroll
            for (int kx = 0; kx < 9; ++kx) {
                float x = src[ky * 20 + kx];
                __nv_bfloat16 h = __float2bfloat16_rn(x);
                __nv_bfloat16 l = __float2bfloat16_rn(x - __bfloat162float(h));
                s_hi[ic * 81 + ky * 9 + kx] = h;
                s_lo[ic * 81 + ky * 9 + kx] = l;
            }
        }
    }
    __syncthreads();
    const uint4* sh = (const uint4*)s_hi;
    const uint4* sl = (const uint4*)s_lo;
    uint4* dh = (uint4*)((char*)g_Ahi + (size_t)m * (KTOT * 2));
    uint4* dl = (uint4*)((char*)g_Alo + (size_t)m * (KTOT * 2));
    for (int i = tid; i < KTOT * 2 / 16; i += 256) { dh[i] = sh[i]; dl[i] = sl[i]; }
}

// ---------------- bf16x3 mma.sync GEMM: g_pc[m][oc] = A·B^T + bias ----------------
// grid (72 mtile, 2 ntile), 256 threads (8 warps, 4m x 2n). dyn smem 99328B.
#define STAGE_BYTES 32768
#define GEMM_SMEM (1024 + 3 * STAGE_BYTES)

__global__ void __launch_bounds__(256, 1) gemm_kernel(const float* __restrict__ bias) {
    extern __shared__ char sm[];
    float* s_bias = (float*)sm;
    const uint32_t smb = smem_u32(sm);
    const int tid = threadIdx.x, lane = tid & 31, wid = tid >> 5;
    const int mtile = blockIdx.x, ntile = blockIdx.y;
    if (tid < 128) s_bias[tid] = bias[ntile * 128 + tid];

    const char* Ahi = (const char*)g_Ahi + (size_t)mtile * 128 * (KTOT * 2);
    const char* Alo = (const char*)g_Alo + (size_t)mtile * 128 * (KTOT * 2);
    const char* Bhi = (const char*)g_Bhi + (size_t)ntile * 128 * (KTOT * 2);
    const char* Blo = (const char*)g_Blo + (size_t)ntile * 128 * (KTOT * 2);
    const char* pA[3] = {Ahi, Ahi, Alo};
    const char* pB[3] = {Bhi, Blo, Bhi};

    // per-thread cp.async geometry (4 chunks A + 4 chunks B per stage)
    int l_row[4], l_so[4];
    #pragma unroll
    for (int i = 0; i < 4; ++i) {
        int lin = tid + i * 256;          // 0..1023
        int row = lin >> 3, ch = lin & 7;
        l_row[i] = row;
        l_so[i] = row * 128 + ((ch ^ (row & 7)) << 4);
    }
    int l_ch[4];
    #pragma unroll
    for (int i = 0; i < 4; ++i) l_ch[i] = (tid + i * 256) & 7;

    // ldmatrix lane geometry
    const int warp_m = wid >> 1, warp_n = wid & 1;
    int a_off[2], a_sw[2];
    #pragma unroll
    for (int sub = 0; sub < 2; ++sub) {
        int row = warp_m * 32 + sub * 16 + ((lane >> 3) & 1) * 8 + (lane & 7);
        a_off[sub] = row * 128; a_sw[sub] = row & 7;
    }
    const int a_cb = lane >> 4;
    int b_off[4], b_sw[4];
    #pragma unroll
    for (int j = 0; j < 4; ++j) {
        int row = warp_n * 64 + j * 16 + ((lane >> 4) << 3) + (lane & 7);
        b_off[j] = row * 128; b_sw[j] = row & 7;
    }
    const int b_cb = (lane >> 3) & 1;

    float acc[2][8][4];
    #pragma unroll
    for (int m = 0; m < 2; ++m)
        #pragma unroll
        for (int j = 0; j < 8; ++j)
            #pragma unroll
            for (int q = 0; q < 4; ++q) acc[m][j][q] = 0.f;

    // --- pipelined main loop ---
    auto issue = [&](int t, int buf) {
        const int pass = t / NKT, kk = t % NKT;
        const char* A = pA[pass];
        const char* B = pB[pass];
        const size_t kbyte = (size_t)kk * 128;
        const uint32_t sA = smb + 1024 + buf * STAGE_BYTES;
        const uint32_t sB = sA + 16384;
        #pragma unroll
        for (int i = 0; i < 4; ++i) {
            const size_t go = (size_t)l_row[i] * (KTOT * 2) + kbyte + l_ch[i] * 16;
            CP_ASYNC16(sA + l_so[i], A + go);
            CP_ASYNC16(sB + l_so[i], B + go);
        }
        CP_COMMIT();
    };

    issue(0, 0);
    issue(1, 1);

    for (int t = 0; t < TOTKT; ++t) {
        const int buf = t % 3;
        if (t + 2 < TOTKT) issue(t + 2, (t + 2) % 3);
        else CP_COMMIT();
        CP_WAIT2();
        __syncthreads();

        const uint32_t sA = smb + 1024 + buf * STAGE_BYTES;
        const uint32_t sB = sA + 16384;
        #pragma unroll
        for (int ks = 0; ks < 4; ++ks) {
            uint32_t a[2][4];
            #pragma unroll
            for (int sub = 0; sub < 2; ++sub) {
                uint32_t ad = sA + a_off[sub] + ((((ks << 1) + a_cb) ^ a_sw[sub]) << 4);
                LDMX4(a[sub][0], a[sub][1], a[sub][2], a[sub][3], ad);
            }
            uint32_t bf[4][4];
            #pragma unroll
            for (int j = 0; j < 4; ++j) {
                uint32_t ad = sB + b_off[j] + ((((ks << 1) + b_cb) ^ b_sw[j]) << 4);
                LDMX4(bf[j][0], bf[j][1], bf[j][2], bf[j][3], ad);
            }
            #pragma unroll
            for (int m = 0; m < 2; ++m)
                #pragma unroll
                for (int j = 0; j < 4; ++j) {
                    MMA16816(acc[m][2 * j],     a[m], bf[j][0], bf[j][1]);
                    MMA16816(acc[m][2 * j + 1], a[m], bf[j][2], bf[j][3]);
                }
        }
        __syncthreads();
    }
    CP_WAIT0();

    // --- epilogue: g_pc[m][oc] = acc + bias ---
    const int r = lane >> 2, cpair = (lane & 3) * 2;
    #pragma unroll
    for (int msub = 0; msub < 2; ++msub) {
        const int gm0 = mtile * 128 + warp_m * 32 + msub * 16 + r;
        #pragma unroll
        for (int j = 0; j < 8; ++j) {
            const int ln = warp_n * 64 + j * 8 + cpair;
            const int gn = ntile * 128 + ln;
            const float b0 = s_bias[ln], b1 = s_bias[ln + 1];
            float2 v0 = {acc[msub][j][0] + b0, acc[msub][j][1] + b1};
            float2 v1 = {acc[msub][j][2] + b0, acc[msub][j][3] + b1};
            *(float2*)&g_pc[(size_t)gm0 * C1 + gn] = v0;
            *(float2*)&g_pc[(size_t)(gm0 + 8) * C1 + gn] = v1;
        }
    }
}

// ---------------- squash: g_pc[m][oc] -> g_u (transposed [n][b][p]) ----------------
__global__ void squash_u_kernel() {
    const int idx = blockIdx.x * 256 + threadIdx.x;   // idx = n*256 + b
    if (idx >= BATCH * NPRIM) return;
    const int n = idx / BATCH, b = idx % BATCH;
    const int m32 = n / 36, s = n % 36;
    const float* row = &g_pc[(size_t)(b * 36 + s) * C1 + m32];
    float v[PCD];
    float sq = 0.f;
    #pragma unroll
    for (int d = 0; d < PCD; ++d) {
        v[d] = row[d * 32];
        sq += v[d] * v[d];
    }
    const float sc = sq / (1.f + sq) / sqrtf(sq + 1e-7f);
    #pragma unroll
    for (int d = 0; d < PCD; ++d) g_u[(size_t)idx * PCD + d] = v[d] * sc;
}

// ---------------- u_hat: WU[b,n,c,d] = sum_p W[n,c,d,p] * u[n,b,p] ----------------
__global__ void wu_kernel(const float* __restrict__ W) {
    __shared__ float s_u[64 * PCD];
    const int n = blockIdx.x;
    const int t = threadIdx.x;   // 0..159
    float wr[PCD];
    #pragma unroll
    for (int p = 0; p < PCD; ++p) wr[p] = W[n * (NC * DCD * PCD) + t * PCD + p];
    for (int b0 = 0; b0 < BATCH; b0 += 64) {
        __syncthreads();
        const uint4* src = (const uint4*)(g_u + ((size_t)n * BATCH + b0) * PCD);
        for (int i = t; i < 128; i += 160) ((uint4*)s_u)[i] = src[i];
        __syncthreads();
        for (int bb = 0; bb < 64; ++bb) {
            const float* up = &s_u[bb * PCD];
            float dot = 0.f;
            #pragma unroll
            for (int p = 0; p < PCD; ++p) dot += wr[p] * up[p];
            g_WU[((size_t)((b0 + bb) * NPRIM + n)) * 160 + t] = dot;
        }
    }
}

// ---------------- dynamic routing ----------------
__global__ void routing_kernel(float* __restrict__ out) {
    extern __shared__ float smf[];
    float* s_bij   = smf;
    float* s_c     = smf + 11520;
    float* s_v     = smf + 23040;
    float* s_red   = smf + 23200;
    float* s_scale = smf + 23520;
    const int b = blockIdx.x;
    const int tid = threadIdx.x;
    const size_t wubase = (size_t)b * NPRIM * 160;
    const int half = tid / 160;
    const int pair = tid % 160;
    const int c = pair / 16, d = pair & 15;

    for (int i = tid; i < NPRIM * NC; i += 320) s_bij[i] = 0.f;

    for (int it = 0; it < 3; ++it) {
        __syncthreads();
        for (int n = tid; n < NPRIM; n += 320) {
            float vals[NC], mx = -1e30f;
            #pragma unroll
            for (int k = 0; k < NC; ++k) { vals[k] = s_bij[n * NC + k]; mx = fmaxf(mx, vals[k]); }
            float ssum = 0.f;
            #pragma unroll
            for (int k = 0; k < NC; ++k) { vals[k] = expf(vals[k] - mx); ssum += vals[k]; }
            const float inv = 1.f / ssum;
            #pragma unroll
            for (int k = 0; k < NC; ++k) s_c[n * NC + k] = vals[k] * inv;
        }
        __syncthreads();
        float acc = 0.f;
        for (int n = half; n < NPRIM; n += 2)
            acc += s_c[n * NC + c] * g_WU[wubase + n * 160 + pair];
        s_red[tid] = acc;
        __syncthreads();
        if (tid < 160) s_v[tid] = s_red[tid] + s_red[tid + 160];
        __syncthreads();
        if (tid < NC) {
            float sq = 0.f;
            #pragma unroll
            for (int k = 0; k < DCD; ++k) { float x = s_v[tid * DCD + k]; sq += x * x; }
            s_scale[tid] = sq / (1.f + sq) / sqrtf(sq + 1e-7f);
        }
        __syncthreads();
        if (tid < 160) s_v[tid] *= s_scale[c];
        __syncthreads();
        if (it < 2) {
            for (int n = half; n < NPRIM; n += 2) {
                float val = s_v[pair] * s_c[n * NC + c] * g_WU[wubase + n * 160 + pair];
                #pragma unroll
                for (int o = 8; o >= 1; o >>= 1) val += __shfl_xor_sync(0xffffffffu, val, o);
                if (d == 0) s_bij[n * NC + c] += val;
            }
        }
    }
    if (tid < 160) g_v[b * 160 + tid] = s_v[tid];
    if (tid < NC) {
        float sq = 0.f;
        #pragma unroll
        for (int k = 0; k < DCD; ++k) { float x = s_v[tid * DCD + k]; sq += x * x; }
        out[b * NC + tid] = sqrtf(sq);
    }
}

// ---------------- masked decoder ----------------
__global__ void decoder_kernel(const int* __restrict__ labels,
                               const float* __restrict__ w1, const float* __restrict__ bb1,
                               const float* __restrict__ w2, const float* __restrict__ bb2,
                               const float* __restrict__ w3, const float* __restrict__ bb3,
                               float* __restrict__ out) {
    __shared__ float h0[2][DCD];
    __shared__ float h1[2][512];
    __shared__ float h2[2][1024];
    __shared__ int   lab[2];
    const int t = threadIdx.x;
    const int b0 = blockIdx.x * 2, b1i = b0 + 1;
    if (t < 2) lab[t] = labels[b0 + t];
    __syncthreads();
    if (t < DCD) {
        h0[0][t] = g_v[b0 * 160 + lab[0] * DCD + t];
        h0[1][t] = g_v[b1i * 160 + lab[1] * DCD + t];
    }
    __syncthreads();
    for (int j = t; j < 512; j += 256) {
        float a0 = bb1[j], a1 = bb1[j];
        #pragma unroll
        for (int k = 0; k < DCD; ++k) {
            a0 += h0[0][k] * w1[(lab[0] * DCD + k) * 512 + j];
            a1 += h0[1][k] * w1[(lab[1] * DCD + k) * 512 + j];
        }
        h1[0][j] = fmaxf(a0, 0.f);
        h1[1][j] = fmaxf(a1, 0.f);
    }
    __syncthreads();
    for (int j = t; j < 1024; j += 256) {
        float a0 = bb2[j], a1 = bb2[j];
        for (int i = 0; i < 512; ++i) {
            float wv = w2[i * 1024 + j];
            a0 += h1[0][i] * wv;
            a1 += h1[1][i] * wv;
        }
        h2[0][j] = fmaxf(a0, 0.f);
        h2[1][j] = fmaxf(a1, 0.f);
    }
    __syncthreads();
    for (int j = t; j < 784; j += 256) {
        float a0 = bb3[j], a1 = bb3[j];
        for (int i = 0; i < 1024; ++i) {
            float wv = w3[i * 784 + j];
            a0 += h2[0][i] * wv;
            a1 += h2[1][i] * wv;
        }
        out[BATCH * NC + b0 * 784 + j]  = 1.f / (1.f + expf(-a0));
        out[BATCH * NC + b1i * 784 + j] = 1.f / (1.f + expf(-a1));
    }
}

// ---------------- launch ----------------
extern "C" void kernel_launch(void* const* d_in, const int* in_sizes, int n_in,
                              void* d_out, int out_size) {
    const float* inputs  = (const float*)d_in[0];
    const int*   labels  = (const int*)d_in[1];
    const float* conv1_w = (const float*)d_in[2];
    const float* conv1_b = (const float*)d_in[3];
    const float* pc_w    = (const float*)d_in[4];
    const float* pc_b    = (const float*)d_in[5];
    const float* rw      = (const float*)d_in[6];
    const float* dw1     = (const float*)d_in[7];
    const float* db1     = (const float*)d_in[8];
    const float* dw2     = (const float*)d_in[9];
    const float* db2     = (const float*)d_in[10];
    const float* dw3     = (const float*)d_in[11];
    const float* db3     = (const float*)d_in[12];
    float* out = (float*)d_out;

    conv1_kernel<<<dim3(4, BATCH), 256>>>(inputs, conv1_w, conv1_b);

    convert_w_kernel<<<(C1 * KTOT / 4 + 255) / 256, 256>>>(pc_w);

    const int im2col_smem = KTOT * 2 * 2;  // 82944
    cudaFuncSetAttribute(im2col_kernel, cudaFuncAttributeMaxDynamicSharedMemorySize, im2col_smem);
    im2col_kernel<<<MTOT, 256, im2col_smem>>>();

    cudaFuncSetAttribute(gemm_kernel, cudaFuncAttributeMaxDynamicSharedMemorySize, GEMM_SMEM);
    gemm_kernel<<<dim3(72, 2), 256, GEMM_SMEM>>>(pc_b);

    squash_u_kernel<<<(BATCH * NPRIM) / 256, 256>>>();
    wu_kernel<<<NPRIM, 160>>>(rw);

    const int routing_smem = (11520 + 11520 + 160 + 320 + 16) * (int)sizeof(float);
    cudaFuncSetAttribute(routing_kernel, cudaFuncAttributeMaxDynamicSharedMemorySize, routing_smem);
    routing_kernel<<<BATCH, 320, routing_smem>>>(out);

    decoder_kernel<<<BATCH / 2, 256>>>(labels, dw1, db1, dw2, db2, dw3, db3, out);
}

// round 5
// speedup vs baseline: 3.8793x; 1.0864x over previous
#include <cuda_runtime.h>
#include <cuda_bf16.h>
#include <math.h>
#include <stdint.h>

#define BATCH 256
#define C1 256
#define IMGD 28
#define H1 20
#define NPRIM 1152
#define NC 10
#define PCD 8
#define DCD 16
#define KTOT 20736           // 256 ic * 81
#define MTOT 9216            // 256 b * 36 sp
#define KTILE 64             // bf16 per K-chunk
#define NKT (KTOT / KTILE)   // 324

// ---------------- scratch ----------------
__device__ float g_x[BATCH * C1 * H1 * H1];          // conv1 out [b][ic][400]
__device__ float g_pc[(size_t)MTOT * C1];            // pc conv out [m][oc]
__device__ float g_u[BATCH * NPRIM * PCD];           // squashed, [n][b][p]
__device__ float g_WU[(size_t)BATCH * NPRIM * NC * DCD];
__device__ float g_v[BATCH * NC * DCD];
__device__ __align__(16) __nv_bfloat16 g_Ahi[(size_t)MTOT * KTOT];
__device__ __align__(16) __nv_bfloat16 g_Alo[(size_t)MTOT * KTOT];
__device__ __align__(16) __nv_bfloat16 g_Bhi[(size_t)C1 * KTOT];
__device__ __align__(16) __nv_bfloat16 g_Blo[(size_t)C1 * KTOT];

__device__ __forceinline__ uint32_t smem_u32(const void* p) {
    uint32_t a;
    asm("{ .reg .u64 t; cvta.to.shared.u64 t, %1; cvt.u32.u64 %0, t; }" : "=r"(a) : "l"(p));
    return a;
}
#define CP_ASYNC16(sa, ga) \
    asm volatile("cp.async.cg.shared.global [%0], [%1], 16;" :: "r"(sa), "l"(ga))
#define CP_COMMIT() asm volatile("cp.async.commit_group;" ::: "memory")
#define CP_WAIT1()  asm volatile("cp.async.wait_group 1;" ::: "memory")
#define CP_WAIT0()  asm volatile("cp.async.wait_group 0;" ::: "memory")
#define LDMX4(r0, r1, r2, r3, a) \
    asm volatile("ldmatrix.sync.aligned.m8n8.x4.shared.b16 {%0,%1,%2,%3}, [%4];" \
        : "=r"(r0), "=r"(r1), "=r"(r2), "=r"(r3) : "r"(a))
#define MMA16816(c, a, b0, b1) \
    asm volatile("mma.sync.aligned.m16n8k16.row.col.f32.bf16.bf16.f32 " \
        "{%0,%1,%2,%3},{%4,%5,%6,%7},{%8,%9},{%0,%1,%2,%3};" \
        : "+f"((c)[0]), "+f"((c)[1]), "+f"((c)[2]), "+f"((c)[3]) \
        : "r"((a)[0]), "r"((a)[1]), "r"((a)[2]), "r"((a)[3]), "r"(b0), "r"(b1))

// ---------------- conv1 + relu ----------------
__global__ void conv1_kernel(const float* __restrict__ in,
                             const float* __restrict__ w,
                             const float* __restrict__ bias) {
    __shared__ float s_img[IMGD * IMGD];
    __shared__ float s_w[81 * 66];
    const int b = blockIdx.y, ocg = blockIdx.x, tid = threadIdx.x;
    const int oc0 = ocg * 64;
    for (int i = tid; i < IMGD * IMGD; i += 256) s_img[i] = in[b * IMGD * IMGD + i];
    for (int i = tid; i < 64 * 81; i += 256) {
        int o = i / 81, k = i % 81;
        s_w[k * 66 + o] = w[(oc0 + o) * 81 + k];
    }
    __syncthreads();
    const int ocp = tid >> 3;
    const int slot = tid & 7;
    const float bv0 = bias[oc0 + 2 * ocp];
    const float bv1 = bias[oc0 + 2 * ocp + 1];
    for (int it = 0; it < 25; ++it) {
        const int px0 = 2 * (it * 8 + slot);
        const int oy = px0 / 20, ox = px0 % 20;
        float a00 = 0.f, a01 = 0.f, a10 = 0.f, a11 = 0.f;
        #pragma unroll 3
        for (int ky = 0; ky < 9; ++ky) {
            const float* r = &s_img[(oy + ky) * IMGD + ox];
            #pragma unroll
            for (int kx = 0; kx < 9; ++kx) {
                float2 wv = *(const float2*)&s_w[(ky * 9 + kx) * 66 + 2 * ocp];
                float i0 = r[kx], i1 = r[kx + 1];
                a00 += wv.x * i0; a01 += wv.x * i1;
                a10 += wv.y * i0; a11 += wv.y * i1;
            }
        }
        const int base0 = (b * C1 + oc0 + 2 * ocp) * 400;
        g_x[base0 + px0]           = fmaxf(a00 + bv0, 0.f);
        g_x[base0 + px0 + 1]       = fmaxf(a01 + bv0, 0.f);
        g_x[base0 + 400 + px0]     = fmaxf(a10 + bv1, 0.f);
        g_x[base0 + 400 + px0 + 1] = fmaxf(a11 + bv1, 0.f);
    }
}

// ---------------- split pc_w into bf16 hi/lo ----------------
__global__ void convert_w_kernel(const float* __restrict__ w) {
    const size_t i4 = (size_t)blockIdx.x * 256 + threadIdx.x;
    if (i4 >= (size_t)C1 * KTOT / 4) return;
    float4 v = ((const float4*)w)[i4];
    __nv_bfloat16 h[4], l[4];
    float xs[4] = {v.x, v.y, v.z, v.w};
    #pragma unroll
    for (int j = 0; j < 4; ++j) {
        h[j] = __float2bfloat16_rn(xs[j]);
        l[j] = __float2bfloat16_rn(xs[j] - __bfloat162float(h[j]));
    }
    *(uint2*)&g_Bhi[i4 * 4] = *(uint2*)h;
    *(uint2*)&g_Blo[i4 * 4] = *(uint2*)l;
}

// ---------------- im2col ----------------
__global__ void im2col_kernel() {
    extern __shared__ char sm[];
    __nv_bfloat16* s_hi = (__nv_bfloat16*)sm;
    __nv_bfloat16* s_lo = (__nv_bfloat16*)(sm + KTOT * 2);
    const int m = blockIdx.x;
    const int tid = threadIdx.x;
    const int b = m / 36, sp = m % 36;
    const int sr2 = 2 * (sp / 6), sc2 = 2 * (sp % 6);
    {
        const int ic = tid;
        const float* src = &g_x[((size_t)(b * C1 + ic)) * 400 + sr2 * 20 + sc2];
        #pragma unroll
        for (int ky = 0; ky < 9; ++ky) {
            #pragma unroll
            for (int kx = 0; kx < 9; ++kx) {
                float x = src[ky * 20 + kx];
                __nv_bfloat16 h = __float2bfloat16_rn(x);
                __nv_bfloat16 l = __float2bfloat16_rn(x - __bfloat162float(h));
                s_hi[ic * 81 + ky * 9 + kx] = h;
                s_lo[ic * 81 + ky * 9 + kx] = l;
            }
        }
    }
    __syncthreads();
    const uint4* sh = (const uint4*)s_hi;
    const uint4* sl = (const uint4*)s_lo;
    uint4* dh = (uint4*)((char*)g_Ahi + (size_t)m * (KTOT * 2));
    uint4* dl = (uint4*)((char*)g_Alo + (size_t)m * (KTOT * 2));
    for (int i = tid; i < KTOT * 2 / 16; i += 256) { dh[i] = sh[i]; dl[i] = sl[i]; }
}

// ---------------- bf16x3 mma.sync GEMM: 64x128 tile, fused hi/lo, 2 CTA/SM ----------------
#define STG 49152
#define GEMM_SMEM (1024 + 2 * STG)

__global__ void __launch_bounds__(256, 2) gemm_kernel(const float* __restrict__ bias) {
    extern __shared__ char sm[];
    float* s_bias = (float*)sm;
    const uint32_t smb = smem_u32(sm);
    const int tid = threadIdx.x, lane = tid & 31, wid = tid >> 5;
    const int mtile = blockIdx.x, ntile = blockIdx.y;
    if (tid < 128) s_bias[tid] = bias[ntile * 128 + tid];

    const char* Ahi = (const char*)g_Ahi + (size_t)mtile * 64 * (KTOT * 2);
    const char* Alo = (const char*)g_Alo + (size_t)mtile * 64 * (KTOT * 2);
    const char* Bhi = (const char*)g_Bhi + (size_t)ntile * 128 * (KTOT * 2);
    const char* Blo = (const char*)g_Blo + (size_t)ntile * 128 * (KTOT * 2);

    // cp.async geometry: A 2 chunks, B 4 chunks per thread per array
    int arow[2], aso[2], ach[2];
    #pragma unroll
    for (int i = 0; i < 2; ++i) {
        int lin = tid + i * 256;
        arow[i] = lin >> 3; ach[i] = lin & 7;
        aso[i] = arow[i] * 128 + ((ach[i] ^ (arow[i] & 7)) << 4);
    }
    int brow[4], bso[4], bch[4];
    #pragma unroll
    for (int i = 0; i < 4; ++i) {
        int lin = tid + i * 256;
        brow[i] = lin >> 3; bch[i] = lin & 7;
        bso[i] = brow[i] * 128 + ((bch[i] ^ (brow[i] & 7)) << 4);
    }

    // ldmatrix geometry: warps 2m x 4n, warp tile 32x32
    const int warp_m = wid >> 2, warp_n = wid & 3;
    int a_off[2], a_sw[2];
    #pragma unroll
    for (int sub = 0; sub < 2; ++sub) {
        int row = warp_m * 32 + sub * 16 + (lane & 15);
        a_off[sub] = row * 128; a_sw[sub] = row & 7;
    }
    const int a_cb = lane >> 4;
    int b_off[2], b_sw[2];
    #pragma unroll
    for (int j = 0; j < 2; ++j) {
        int row = warp_n * 32 + j * 16 + ((lane >> 4) << 3) + (lane & 7);
        b_off[j] = row * 128; b_sw[j] = row & 7;
    }
    const int b_cb = (lane >> 3) & 1;

    float acc[2][4][4];
    #pragma unroll
    for (int m = 0; m < 2; ++m)
        #pragma unroll
        for (int j = 0; j < 4; ++j)
            #pragma unroll
            for (int q = 0; q < 4; ++q) acc[m][j][q] = 0.f;

    auto issue = [&](int kk, int buf) {
        const size_t kbyte = (size_t)kk * 128;
        const uint32_t sAh = smb + 1024 + buf * STG;
        const uint32_t sAl = sAh + 8192;
        const uint32_t sBh = sAh + 16384;
        const uint32_t sBl = sAh + 32768;
        #pragma unroll
        for (int i = 0; i < 2; ++i) {
            const size_t go = (size_t)arow[i] * (KTOT * 2) + kbyte + ach[i] * 16;
            CP_ASYNC16(sAh + aso[i], Ahi + go);
            CP_ASYNC16(sAl + aso[i], Alo + go);
        }
        #pragma unroll
        for (int i = 0; i < 4; ++i) {
            const size_t go = (size_t)brow[i] * (KTOT * 2) + kbyte + bch[i] * 16;
            CP_ASYNC16(sBh + bso[i], Bhi + go);
            CP_ASYNC16(sBl + bso[i], Blo + go);
        }
        CP_COMMIT();
    };

    issue(0, 0);
    for (int t = 0; t < NKT; ++t) {
        if (t + 1 < NKT) issue(t + 1, (t + 1) & 1);
        else CP_COMMIT();
        CP_WAIT1();
        __syncthreads();
        const uint32_t sAh = smb + 1024 + (t & 1) * STG;
        const uint32_t sAl = sAh + 8192;
        const uint32_t sBh = sAh + 16384;
        const uint32_t sBl = sAh + 32768;
        #pragma unroll
        for (int ks = 0; ks < 4; ++ks) {
            uint32_t ah[2][4], al[2][4], bh[2][4], bl[2][4];
            #pragma unroll
            for (int sub = 0; sub < 2; ++sub) {
                uint32_t co = ((((ks << 1) + a_cb) ^ a_sw[sub]) << 4);
                LDMX4(ah[sub][0], ah[sub][1], ah[sub][2], ah[sub][3], sAh + a_off[sub] + co);
                LDMX4(al[sub][0], al[sub][1], al[sub][2], al[sub][3], sAl + a_off[sub] + co);
            }
            #pragma unroll
            for (int j = 0; j < 2; ++j) {
                uint32_t co = ((((ks << 1) + b_cb) ^ b_sw[j]) << 4);
                LDMX4(bh[j][0], bh[j][1], bh[j][2], bh[j][3], sBh + b_off[j] + co);
                LDMX4(bl[j][0], bl[j][1], bl[j][2], bl[j][3], sBl + b_off[j] + co);
            }
            #pragma unroll
            for (int msub = 0; msub < 2; ++msub)
                #pragma unroll
                for (int j = 0; j < 2; ++j) {
                    MMA16816(acc[msub][2 * j],     ah[msub], bh[j][0], bh[j][1]);
                    MMA16816(acc[msub][2 * j + 1], ah[msub], bh[j][2], bh[j][3]);
                    MMA16816(acc[msub][2 * j],     ah[msub], bl[j][0], bl[j][1]);
                    MMA16816(acc[msub][2 * j + 1], ah[msub], bl[j][2], bl[j][3]);
                    MMA16816(acc[msub][2 * j],     al[msub], bh[j][0], bh[j][1]);
                    MMA16816(acc[msub][2 * j + 1], al[msub], bh[j][2], bh[j][3]);
                }
        }
        __syncthreads();
    }
    CP_WAIT0();

    // epilogue
    const int r = lane >> 2, cpair = (lane & 3) * 2;
    #pragma unroll
    for (int msub = 0; msub < 2; ++msub) {
        const int gm0 = mtile * 64 + warp_m * 32 + msub * 16 + r;
        #pragma unroll
        for (int j = 0; j < 4; ++j) {
            const int ln = warp_n * 32 + j * 8 + cpair;
            const int gn = ntile * 128 + ln;
            const float b0 = s_bias[ln], b1 = s_bias[ln + 1];
            float2 v0 = {acc[msub][j][0] + b0, acc[msub][j][1] + b1};
            float2 v1 = {acc[msub][j][2] + b0, acc[msub][j][3] + b1};
            *(float2*)&g_pc[(size_t)gm0 * C1 + gn] = v0;
            *(float2*)&g_pc[(size_t)(gm0 + 8) * C1 + gn] = v1;
        }
    }
}

// ---------------- squash ----------------
__global__ void squash_u_kernel() {
    const int idx = blockIdx.x * 256 + threadIdx.x;
    if (idx >= BATCH * NPRIM) return;
    const int n = idx / BATCH, b = idx % BATCH;
    const int m32 = n / 36, s = n % 36;
    const float* row = &g_pc[(size_t)(b * 36 + s) * C1 + m32];
    float v[PCD];
    float sq = 0.f;
    #pragma unroll
    for (int d = 0; d < PCD; ++d) {
        v[d] = row[d * 32];
        sq += v[d] * v[d];
    }
    const float sc = sq / (1.f + sq) / sqrtf(sq + 1e-7f);
    #pragma unroll
    for (int d = 0; d < PCD; ++d) g_u[(size_t)idx * PCD + d] = v[d] * sc;
}

// ---------------- u_hat ----------------
__global__ void wu_kernel(const float* __restrict__ W) {
    __shared__ float s_u[64 * PCD];
    const int n = blockIdx.x;
    const int t = threadIdx.x;
    float wr[PCD];
    #pragma unroll
    for (int p = 0; p < PCD; ++p) wr[p] = W[n * (NC * DCD * PCD) + t * PCD + p];
    for (int b0 = 0; b0 < BATCH; b0 += 64) {
        __syncthreads();
        const uint4* src = (const uint4*)(g_u + ((size_t)n * BATCH + b0) * PCD);
        for (int i = t; i < 128; i += 160) ((uint4*)s_u)[i] = src[i];
        __syncthreads();
        for (int bb = 0; bb < 64; ++bb) {
            const float* up = &s_u[bb * PCD];
            float dot = 0.f;
            #pragma unroll
            for (int p = 0; p < PCD; ++p) dot += wr[p] * up[p];
            g_WU[((size_t)((b0 + bb) * NPRIM + n)) * 160 + t] = dot;
        }
    }
}

// ---------------- dynamic routing: warp-per-n, 3 WU passes ----------------
// 320 threads = 10 warps. dyn smem: s_b[11520] + s_red[1600] + s_v[160] + s_scale[16]
#define ROUT_SMEM ((11520 + 1600 + 160 + 16) * 4)

__device__ __forceinline__ void rout_reduce_squash(
    float* s_red, float* s_v, float* s_scale, const float* acc,
    int tid, int w, int l, float cs) {
    #pragma unroll
    for (int j = 0; j < 5; ++j) s_red[w * 160 + 32 * j + l] = acc[j];
    __syncthreads();
    if (tid < 160) {
        float v = 0.f;
        #pragma unroll
        for (int ww = 0; ww < 10; ++ww) v += s_red[ww * 160 + tid];
        s_v[tid] = v * cs;
    }
    __syncthreads();
    if (tid < NC) {
        float sq = 0.f;
        #pragma unroll
        for (int d = 0; d < DCD; ++d) { float x = s_v[tid * DCD + d]; sq += x * x; }
        s_scale[tid] = sq / (1.f + sq) / sqrtf(sq + 1e-7f);
    }
    __syncthreads();
    if (tid < 160) s_v[tid] *= s_scale[tid >> 4];
    __syncthreads();
}

__global__ void routing_kernel(float* __restrict__ out) {
    extern __shared__ float smf[];
    float* s_b     = smf;            // 11520
    float* s_red   = smf + 11520;    // 1600
    float* s_v     = smf + 13120;    // 160
    float* s_scale = smf + 13280;    // 16
    const int b = blockIdx.x, tid = threadIdx.x;
    const int w = tid >> 5, l = tid & 31;
    const int myh = l >> 4;
    const size_t wub = (size_t)b * NPRIM * 160;
    const unsigned FULL = 0xffffffffu;
    float acc[5];

    // ---- pass 0: v0 = squash(0.1 * colsum WU) ----
    #pragma unroll
    for (int j = 0; j < 5; ++j) acc[j] = 0.f;
    for (int n = w; n < NPRIM; n += 10) {
        const float* row = g_WU + wub + (size_t)n * 160;
        #pragma unroll
        for (int j = 0; j < 5; ++j) acc[j] += row[l + 32 * j];
    }
    rout_reduce_squash(s_red, s_v, s_scale, acc, tid, w, l, 0.1f);

    // ---- pass 1: b1 = sum_d v0*(0.1*WU); c1 = softmax(b1); acc = sum c1*WU ----
    #pragma unroll
    for (int j = 0; j < 5; ++j) acc[j] = 0.f;
    for (int n = w; n < NPRIM; n += 10) {
        const float* row = g_WU + wub + (size_t)n * 160;
        float wv[5], t[5];
        #pragma unroll
        for (int j = 0; j < 5; ++j) wv[j] = row[l + 32 * j];
        #pragma unroll
        for (int j = 0; j < 5; ++j) t[j] = s_v[l + 32 * j] * wv[j];
        #pragma unroll
        for (int j = 0; j < 5; ++j) {
            t[j] += __shfl_xor_sync(FULL, t[j], 8);
            t[j] += __shfl_xor_sync(FULL, t[j], 4);
            t[j] += __shfl_xor_sync(FULL, t[j], 2);
            t[j] += __shfl_xor_sync(FULL, t[j], 1);
            t[j] *= 0.1f;
        }
        float o[5];
        #pragma unroll
        for (int j = 0; j < 5; ++j) o[j] = __shfl_xor_sync(FULL, t[j], 16);
        float selt = t[0], selo = o[0];
        #pragma unroll
        for (int jj = 1; jj < 5; ++jj) {
            bool p = ((l >> 1) == jj);
            selt = p ? t[jj] : selt;
            selo = p ? o[jj] : selo;
        }
        const float bv = (l & 1) ? selo : selt;   // lane c<10: b1[n][c]
        if (l < NC) s_b[n * NC + l] = bv;
        float m = (l < NC) ? bv : -1e30f;
        m = fmaxf(m, __shfl_xor_sync(FULL, m, 16));
        m = fmaxf(m, __shfl_xor_sync(FULL, m, 8));
        m = fmaxf(m, __shfl_xor_sync(FULL, m, 4));
        m = fmaxf(m, __shfl_xor_sync(FULL, m, 2));
        m = fmaxf(m, __shfl_xor_sync(FULL, m, 1));
        float e = (l < NC) ? __expf(bv - m) : 0.f;
        float S = e;
        S += __shfl_xor_sync(FULL, S, 16);
        S += __shfl_xor_sync(FULL, S, 8);
        S += __shfl_xor_sync(FULL, S, 4);
        S += __shfl_xor_sync(FULL, S, 2);
        S += __shfl_xor_sync(FULL, S, 1);
        const float en = e / S;
        #pragma unroll
        for (int j = 0; j < 5; ++j) {
            float cf = __shfl_sync(FULL, en, 2 * j + myh);
            acc[j] += cf * wv[j];
        }
    }
    rout_reduce_squash(s_red, s_v, s_scale, acc, tid, w, l, 1.f);

    // ---- pass 2: b2 = b1 + sum_d v1*c1*WU; c2 = softmax(b2); acc = sum c2*WU ----
    #pragma unroll
    for (int j = 0; j < 5; ++j) acc[j] = 0.f;
    for (int n = w; n < NPRIM; n += 10) {
        const float* row = g_WU + wub + (size_t)n * 160;
        float wv[5];
        #pragma unroll
        for (int j = 0; j < 5; ++j) wv[j] = row[l + 32 * j];
        const float bv1 = (l < NC) ? s_b[n * NC + l] : 0.f;
        float m1 = (l < NC) ? bv1 : -1e30f;
        m1 = fmaxf(m1, __shfl_xor_sync(FULL, m1, 16));
        m1 = fmaxf(m1, __shfl_xor_sync(FULL, m1, 8));
        m1 = fmaxf(m1, __shfl_xor_sync(FULL, m1, 4));
        m1 = fmaxf(m1, __shfl_xor_sync(FULL, m1, 2));
        m1 = fmaxf(m1, __shfl_xor_sync(FULL, m1, 1));
        float e1 = (l < NC) ? __expf(bv1 - m1) : 0.f;
        float S1 = e1;
        S1 += __shfl_xor_sync(FULL, S1, 16);
        S1 += __shfl_xor_sync(FULL, S1, 8);
        S1 += __shfl_xor_sync(FULL, S1, 4);
        S1 += __shfl_xor_sync(FULL, S1, 2);
        S1 += __shfl_xor_sync(FULL, S1, 1);
        const float en1 = e1 / S1;
        float t2[5];
        #pragma unroll
        for (int j = 0; j < 5; ++j) {
            float cf1 = __shfl_sync(FULL, en1, 2 * j + myh);
            t2[j] = s_v[l + 32 * j] * cf1 * wv[j];
            t2[j] += __shfl_xor_sync(FULL, t2[j], 8);
            t2[j] += __shfl_xor_sync(FULL, t2[j], 4);
            t2[j] += __shfl_xor_sync(FULL, t2[j], 2);
            t2[j] += __shfl_xor_sync(FULL, t2[j], 1);
        }
        float o2[5];
        #pragma unroll
        for (int j = 0; j < 5; ++j) o2[j] = __shfl_xor_sync(FULL, t2[j], 16);
        float selt = t2[0], selo = o2[0];
        #pragma unroll
        for (int jj = 1; jj < 5; ++jj) {
            bool p = ((l >> 1) == jj);
            selt = p ? t2[jj] : selt;
            selo = p ? o2[jj] : selo;
        }
        const float b2v = bv1 + ((l & 1) ? selo : selt);
        float m2 = (l < NC) ? b2v : -1e30f;
        m2 = fmaxf(m2, __shfl_xor_sync(FULL, m2, 16));
        m2 = fmaxf(m2, __shfl_xor_sync(FULL, m2, 8));
        m2 = fmaxf(m2, __shfl_xor_sync(FULL, m2, 4));
        m2 = fmaxf(m2, __shfl_xor_sync(FULL, m2, 2));
        m2 = fmaxf(m2, __shfl_xor_sync(FULL, m2, 1));
        float e2 = (l < NC) ? __expf(b2v - m2) : 0.f;
        float S2 = e2;
        S2 += __shfl_xor_sync(FULL, S2, 16);
        S2 += __shfl_xor_sync(FULL, S2, 8);
        S2 += __shfl_xor_sync(FULL, S2, 4);
        S2 += __shfl_xor_sync(FULL, S2, 2);
        S2 += __shfl_xor_sync(FULL, S2, 1);
        const float en2 = e2 / S2;
        #pragma unroll
        for (int j = 0; j < 5; ++j) {
            float cf2 = __shfl_sync(FULL, en2, 2 * j + myh);
            acc[j] += cf2 * wv[j];
        }
    }
    rout_reduce_squash(s_red, s_v, s_scale, acc, tid, w, l, 1.f);

    if (tid < 160) g_v[b * 160 + tid] = s_v[tid];
    if (tid < NC) {
        float sq = 0.f;
        #pragma unroll
        for (int d = 0; d < DCD; ++d) { float x = s_v[tid * DCD + d]; sq += x * x; }
        out[b * NC + tid] = sqrtf(sq);
    }
}

// ---------------- masked decoder: 4 images per block ----------------
__global__ void decoder_kernel(const int* __restrict__ labels,
                               const float* __restrict__ w1, const float* __restrict__ bb1,
                               const float* __restrict__ w2, const float* __restrict__ bb2,
                               const float* __restrict__ w3, const float* __restrict__ bb3,
                               float* __restrict__ out) {
    __shared__ float h0[4][DCD];
    __shared__ float h1[4][512];
    __shared__ float h2[4][1024];
    __shared__ int   lab[4];
    const int t = threadIdx.x;
    const int b0 = blockIdx.x * 4;
    if (t < 4) lab[t] = labels[b0 + t];
    __syncthreads();
    if (t < 64) {
        int i = t >> 4, d = t & 15;
        h0[i][d] = g_v[(b0 + i) * 160 + lab[i] * DCD + d];
    }
    __syncthreads();
    for (int j = t; j < 512; j += 256) {
        float a[4];
        #pragma unroll
        for (int i = 0; i < 4; ++i) a[i] = bb1[j];
        #pragma unroll
        for (int k = 0; k < DCD; ++k) {
            #pragma unroll
            for (int i = 0; i < 4; ++i)
                a[i] += h0[i][k] * w1[(lab[i] * DCD + k) * 512 + j];
        }
        #pragma unroll
        for (int i = 0; i < 4; ++i) h1[i][j] = fmaxf(a[i], 0.f);
    }
    __syncthreads();
    for (int j = t; j < 1024; j += 256) {
        float a[4];
        #pragma unroll
        for (int i = 0; i < 4; ++i) a[i] = bb2[j];
        for (int k = 0; k < 512; ++k) {
            float wv = w2[k * 1024 + j];
            #pragma unroll
            for (int i = 0; i < 4; ++i) a[i] += h1[i][k] * wv;
        }
        #pragma unroll
        for (int i = 0; i < 4; ++i) h2[i][j] = fmaxf(a[i], 0.f);
    }
    __syncthreads();
    for (int j = t; j < 784; j += 256) {
        float a[4];
        #pragma unroll
        for (int i = 0; i < 4; ++i) a[i] = bb3[j];
        for (int k = 0; k < 1024; ++k) {
            float wv = w3[k * 784 + j];
            #pragma unroll
            for (int i = 0; i < 4; ++i) a[i] += h2[i][k] * wv;
        }
        #pragma unroll
        for (int i = 0; i < 4; ++i)
            out[BATCH * NC + (b0 + i) * 784 + j] = 1.f / (1.f + __expf(-a[i]));
    }
}

// ---------------- launch ----------------
extern "C" void kernel_launch(void* const* d_in, const int* in_sizes, int n_in,
                              void* d_out, int out_size) {
    const float* inputs  = (const float*)d_in[0];
    const int*   labels  = (const int*)d_in[1];
    const float* conv1_w = (const float*)d_in[2];
    const float* conv1_b = (const float*)d_in[3];
    const float* pc_w    = (const float*)d_in[4];
    const float* pc_b    = (const float*)d_in[5];
    const float* rw      = (const float*)d_in[6];
    const float* dw1     = (const float*)d_in[7];
    const float* db1     = (const float*)d_in[8];
    const float* dw2     = (const float*)d_in[9];
    const float* db2     = (const float*)d_in[10];
    const float* dw3     = (const float*)d_in[11];
    const float* db3     = (const float*)d_in[12];
    float* out = (float*)d_out;

    conv1_kernel<<<dim3(4, BATCH), 256>>>(inputs, conv1_w, conv1_b);

    convert_w_kernel<<<(C1 * KTOT / 4 + 255) / 256, 256>>>(pc_w);

    const int im2col_smem = KTOT * 2 * 2;  // 82944
    cudaFuncSetAttribute(im2col_kernel, cudaFuncAttributeMaxDynamicSharedMemorySize, im2col_smem);
    im2col_kernel<<<MTOT, 256, im2col_smem>>>();

    cudaFuncSetAttribute(gemm_kernel, cudaFuncAttributeMaxDynamicSharedMemorySize, GEMM_SMEM);
    gemm_kernel<<<dim3(144, 2), 256, GEMM_SMEM>>>(pc_b);

    squash_u_kernel<<<(BATCH * NPRIM) / 256, 256>>>();
    wu_kernel<<<NPRIM, 160>>>(rw);

    cudaFuncSetAttribute(routing_kernel, cudaFuncAttributeMaxDynamicSharedMemorySize, ROUT_SMEM);
    routing_kernel<<<BATCH, 320, ROUT_SMEM>>>(out);

    decoder_kernel<<<BATCH / 4, 256>>>(labels, dw1, db1, dw2, db2, dw3, db3, out);
}

// round 6
// speedup vs baseline: 4.6240x; 1.1920x over previous
#include <cuda_runtime.h>
#include <cuda_bf16.h>
#include <math.h>
#include <stdint.h>

#define BATCH 256
#define C1 256
#define IMGD 28
#define H1 20
#define NPRIM 1152
#define NC 10
#define PCD 8
#define DCD 16
#define KTOT 20736           // 81 r * 256 ic  (k = r*256 + ic)
#define MTOT 9216            // 256 b * 36 sp
#define KTILE 64
#define NKT (KTOT / KTILE)   // 324

// ---------------- scratch ----------------
__device__ float g_x[(size_t)BATCH * 400 * C1];      // conv1 out TRANSPOSED [b][px][ic]
__device__ float g_pc[(size_t)MTOT * C1];            // pc conv out [m][oc]
__device__ float g_u[BATCH * NPRIM * PCD];           // squashed, [n][b][p]
__device__ float g_WU[(size_t)BATCH * NPRIM * NC * DCD];
__device__ float g_v[BATCH * NC * DCD];
__device__ __align__(16) __nv_bfloat16 g_Ahi[(size_t)MTOT * KTOT];
__device__ __align__(16) __nv_bfloat16 g_Alo[(size_t)MTOT * KTOT];
__device__ __align__(16) __nv_bfloat16 g_Bhi[(size_t)C1 * KTOT];
__device__ __align__(16) __nv_bfloat16 g_Blo[(size_t)C1 * KTOT];

__device__ __forceinline__ uint32_t smem_u32(const void* p) {
    uint32_t a;
    asm("{ .reg .u64 t; cvta.to.shared.u64 t, %1; cvt.u32.u64 %0, t; }" : "=r"(a) : "l"(p));
    return a;
}
#define CP_ASYNC16(sa, ga) \
    asm volatile("cp.async.cg.shared.global [%0], [%1], 16;" :: "r"(sa), "l"(ga))
#define CP_COMMIT() asm volatile("cp.async.commit_group;" ::: "memory")
#define CP_WAIT1()  asm volatile("cp.async.wait_group 1;" ::: "memory")
#define CP_WAIT0()  asm volatile("cp.async.wait_group 0;" ::: "memory")
#define LDMX4(r0, r1, r2, r3, a) \
    asm volatile("ldmatrix.sync.aligned.m8n8.x4.shared.b16 {%0,%1,%2,%3}, [%4];" \
        : "=r"(r0), "=r"(r1), "=r"(r2), "=r"(r3) : "r"(a))
#define MMA16816(c, a, b0, b1) \
    asm volatile("mma.sync.aligned.m16n8k16.row.col.f32.bf16.bf16.f32 " \
        "{%0,%1,%2,%3},{%4,%5,%6,%7},{%8,%9},{%0,%1,%2,%3};" \
        : "+f"((c)[0]), "+f"((c)[1]), "+f"((c)[2]), "+f"((c)[3]) \
        : "r"((a)[0]), "r"((a)[1]), "r"((a)[2]), "r"((a)[3]), "r"(b0), "r"(b1))

// ---------------- conv1 + relu -> g_x[b][px][ic] ----------------
__global__ void conv1_kernel(const float* __restrict__ in,
                             const float* __restrict__ w,
                             const float* __restrict__ bias) {
    __shared__ float s_img[IMGD * IMGD];
    __shared__ float s_w[81 * 66];
    const int b = blockIdx.y, ocg = blockIdx.x, tid = threadIdx.x;
    const int oc0 = ocg * 64;
    for (int i = tid; i < IMGD * IMGD; i += 256) s_img[i] = in[b * IMGD * IMGD + i];
    for (int i = tid; i < 64 * 81; i += 256) {
        int o = i / 81, k = i % 81;
        s_w[k * 66 + o] = w[(oc0 + o) * 81 + k];
    }
    __syncthreads();
    const int ocp = tid & 31;        // lane = oc pair -> coalesced stores
    const int slot = tid >> 5;       // 0..7
    const float bv0 = bias[oc0 + 2 * ocp];
    const float bv1 = bias[oc0 + 2 * ocp + 1];
    for (int it = 0; it < 25; ++it) {
        const int px0 = 2 * (it * 8 + slot);
        const int oy = px0 / 20, ox = px0 % 20;
        float a00 = 0.f, a01 = 0.f, a10 = 0.f, a11 = 0.f;
        #pragma unroll 3
        for (int ky = 0; ky < 9; ++ky) {
            const float* r = &s_img[(oy + ky) * IMGD + ox];
            #pragma unroll
            for (int kx = 0; kx < 9; ++kx) {
                float2 wv = *(const float2*)&s_w[(ky * 9 + kx) * 66 + 2 * ocp];
                float i0 = r[kx], i1 = r[kx + 1];
                a00 += wv.x * i0; a01 += wv.x * i1;
                a10 += wv.y * i0; a11 += wv.y * i1;
            }
        }
        float* dst0 = &g_x[((size_t)b * 400 + px0) * C1 + oc0 + 2 * ocp];
        float2 v0 = {fmaxf(a00 + bv0, 0.f), fmaxf(a10 + bv1, 0.f)};
        float2 v1 = {fmaxf(a01 + bv0, 0.f), fmaxf(a11 + bv1, 0.f)};
        *(float2*)dst0 = v0;
        *(float2*)(dst0 + C1) = v1;
    }
}

// ---------------- split pc_w -> bf16 hi/lo, k = r*256 + ic ----------------
// grid 256 (oc), 256 threads (ic)
__global__ void convert_w_kernel(const float* __restrict__ w) {
    const int oc = blockIdx.x, ic = threadIdx.x;
    const float* src = w + (size_t)oc * KTOT + (size_t)ic * 81;
    __nv_bfloat16* dh = g_Bhi + (size_t)oc * KTOT + ic;
    __nv_bfloat16* dl = g_Blo + (size_t)oc * KTOT + ic;
    #pragma unroll 9
    for (int r = 0; r < 81; ++r) {
        float x = src[r];
        __nv_bfloat16 h = __float2bfloat16_rn(x);
        dh[r * 256] = h;
        dl[r * 256] = __float2bfloat16_rn(x - __bfloat162float(h));
    }
}

// ---------------- im2col: g_x[b][px][ic] -> A[m][k=r*256+ic] hi/lo ----------------
// grid MTOT, 256 threads. Thread t: ic pair (t&127)*2, r-half t>>7.
__global__ void im2col_kernel() {
    const int m = blockIdx.x, tid = threadIdx.x;
    const int b = m / 36, sp = m % 36;
    const int pbase = (2 * (sp / 6)) * 20 + 2 * (sp % 6);
    const int icp = (tid & 127) * 2;
    const int rh = tid >> 7;
    const float* xb = g_x + (size_t)b * 400 * C1;
    uint32_t* dh = (uint32_t*)(g_Ahi + (size_t)m * KTOT);
    uint32_t* dl = (uint32_t*)(g_Alo + (size_t)m * KTOT);
    #pragma unroll 4
    for (int it = 0; it < 41; ++it) {
        const int r = it * 2 + rh;
        if (r < 81) {
            const int ky = r / 9, kx = r % 9;
            const int pix = pbase + ky * 20 + kx;
            float2 xv = *(const float2*)&xb[(size_t)pix * C1 + icp];
            __nv_bfloat16 h0 = __float2bfloat16_rn(xv.x);
            __nv_bfloat16 h1 = __float2bfloat16_rn(xv.y);
            __nv_bfloat16 l0 = __float2bfloat16_rn(xv.x - __bfloat162float(h0));
            __nv_bfloat16 l1 = __float2bfloat16_rn(xv.y - __bfloat162float(h1));
            __nv_bfloat162 hp = {h0, h1}, lp = {l0, l1};
            const int ki = (r * 256 + icp) >> 1;
            dh[ki] = *(uint32_t*)&hp;
            dl[ki] = *(uint32_t*)&lp;
        }
    }
}

// ---------------- bf16x3 mma.sync GEMM: 64x128 tile, fused hi/lo, 2 CTA/SM ----------------
#define STG 49152
#define GEMM_SMEM (1024 + 2 * STG)

__global__ void __launch_bounds__(256, 2) gemm_kernel(const float* __restrict__ bias) {
    extern __shared__ char sm[];
    float* s_bias = (float*)sm;
    const uint32_t smb = smem_u32(sm);
    const int tid = threadIdx.x, lane = tid & 31, wid = tid >> 5;
    const int mtile = blockIdx.x, ntile = blockIdx.y;
    if (tid < 128) s_bias[tid] = bias[ntile * 128 + tid];

    const char* Ahi = (const char*)g_Ahi + (size_t)mtile * 64 * (KTOT * 2);
    const char* Alo = (const char*)g_Alo + (size_t)mtile * 64 * (KTOT * 2);
    const char* Bhi = (const char*)g_Bhi + (size_t)ntile * 128 * (KTOT * 2);
    const char* Blo = (const char*)g_Blo + (size_t)ntile * 128 * (KTOT * 2);

    int arow[2], aso[2], ach[2];
    #pragma unroll
    for (int i = 0; i < 2; ++i) {
        int lin = tid + i * 256;
        arow[i] = lin >> 3; ach[i] = lin & 7;
        aso[i] = arow[i] * 128 + ((ach[i] ^ (arow[i] & 7)) << 4);
    }
    int brow[4], bso[4], bch[4];
    #pragma unroll
    for (int i = 0; i < 4; ++i) {
        int lin = tid + i * 256;
        brow[i] = lin >> 3; bch[i] = lin & 7;
        bso[i] = brow[i] * 128 + ((bch[i] ^ (brow[i] & 7)) << 4);
    }

    const int warp_m = wid >> 2, warp_n = wid & 3;
    int a_off[2], a_sw[2];
    #pragma unroll
    for (int sub = 0; sub < 2; ++sub) {
        int row = warp_m * 32 + sub * 16 + (lane & 15);
        a_off[sub] = row * 128; a_sw[sub] = row & 7;
    }
    const int a_cb = lane >> 4;
    int b_off[2], b_sw[2];
    #pragma unroll
    for (int j = 0; j < 2; ++j) {
        int row = warp_n * 32 + j * 16 + ((lane >> 4) << 3) + (lane & 7);
        b_off[j] = row * 128; b_sw[j] = row & 7;
    }
    const int b_cb = (lane >> 3) & 1;

    float acc[2][4][4];
    #pragma unroll
    for (int m = 0; m < 2; ++m)
        #pragma unroll
        for (int j = 0; j < 4; ++j)
            #pragma unroll
            for (int q = 0; q < 4; ++q) acc[m][j][q] = 0.f;

    auto issue = [&](int kk, int buf) {
        const size_t kbyte = (size_t)kk * 128;
        const uint32_t sAh = smb + 1024 + buf * STG;
        const uint32_t sAl = sAh + 8192;
        const uint32_t sBh = sAh + 16384;
        const uint32_t sBl = sAh + 32768;
        #pragma unroll
        for (int i = 0; i < 2; ++i) {
            const size_t go = (size_t)arow[i] * (KTOT * 2) + kbyte + ach[i] * 16;
            CP_ASYNC16(sAh + aso[i], Ahi + go);
            CP_ASYNC16(sAl + aso[i], Alo + go);
        }
        #pragma unroll
        for (int i = 0; i < 4; ++i) {
            const size_t go = (size_t)brow[i] * (KTOT * 2) + kbyte + bch[i] * 16;
            CP_ASYNC16(sBh + bso[i], Bhi + go);
            CP_ASYNC16(sBl + bso[i], Blo + go);
        }
        CP_COMMIT();
    };

    issue(0, 0);
    for (int t = 0; t < NKT; ++t) {
        if (t + 1 < NKT) issue(t + 1, (t + 1) & 1);
        else CP_COMMIT();
        CP_WAIT1();
        __syncthreads();
        const uint32_t sAh = smb + 1024 + (t & 1) * STG;
        const uint32_t sAl = sAh + 8192;
        const uint32_t sBh = sAh + 16384;
        const uint32_t sBl = sAh + 32768;
        #pragma unroll
        for (int ks = 0; ks < 4; ++ks) {
            uint32_t ah[2][4], al[2][4], bh[2][4], bl[2][4];
            #pragma unroll
            for (int sub = 0; sub < 2; ++sub) {
                uint32_t co = ((((ks << 1) + a_cb) ^ a_sw[sub]) << 4);
                LDMX4(ah[sub][0], ah[sub][1], ah[sub][2], ah[sub][3], sAh + a_off[sub] + co);
                LDMX4(al[sub][0], al[sub][1], al[sub][2], al[sub][3], sAl + a_off[sub] + co);
            }
            #pragma unroll
            for (int j = 0; j < 2; ++j) {
                uint32_t co = ((((ks << 1) + b_cb) ^ b_sw[j]) << 4);
                LDMX4(bh[j][0], bh[j][1], bh[j][2], bh[j][3], sBh + b_off[j] + co);
                LDMX4(bl[j][0], bl[j][1], bl[j][2], bl[j][3], sBl + b_off[j] + co);
            }
            #pragma unroll
            for (int msub = 0; msub < 2; ++msub)
                #pragma unroll
                for (int j = 0; j < 2; ++j) {
                    MMA16816(acc[msub][2 * j],     ah[msub], bh[j][0], bh[j][1]);
                    MMA16816(acc[msub][2 * j + 1], ah[msub], bh[j][2], bh[j][3]);
                    MMA16816(acc[msub][2 * j],     ah[msub], bl[j][0], bl[j][1]);
                    MMA16816(acc[msub][2 * j + 1], ah[msub], bl[j][2], bl[j][3]);
                    MMA16816(acc[msub][2 * j],     al[msub], bh[j][0], bh[j][1]);
                    MMA16816(acc[msub][2 * j + 1], al[msub], bh[j][2], bh[j][3]);
                }
        }
        __syncthreads();
    }
    CP_WAIT0();

    const int r = lane >> 2, cpair = (lane & 3) * 2;
    #pragma unroll
    for (int msub = 0; msub < 2; ++msub) {
        const int gm0 = mtile * 64 + warp_m * 32 + msub * 16 + r;
        #pragma unroll
        for (int j = 0; j < 4; ++j) {
            const int ln = warp_n * 32 + j * 8 + cpair;
            const int gn = ntile * 128 + ln;
            const float b0 = s_bias[ln], b1 = s_bias[ln + 1];
            float2 v0 = {acc[msub][j][0] + b0, acc[msub][j][1] + b1};
            float2 v1 = {acc[msub][j][2] + b0, acc[msub][j][3] + b1};
            *(float2*)&g_pc[(size_t)gm0 * C1 + gn] = v0;
            *(float2*)&g_pc[(size_t)(gm0 + 8) * C1 + gn] = v1;
        }
    }
}

// ---------------- squash: warp-per-row coalesced ----------------
// grid 1152, 256 threads (8 warps, one g_pc row each)
__global__ void squash_u_kernel() {
    __shared__ float s[8][256];
    const int tid = threadIdx.x, w = tid >> 5, l = tid & 31;
    const int m = blockIdx.x * 8 + w;
    const float* row = g_pc + (size_t)m * C1;
    float4 r0 = ((const float4*)row)[l * 2];
    float4 r1 = ((const float4*)row)[l * 2 + 1];
    *(float4*)&s[w][l * 8]     = r0;
    *(float4*)&s[w][l * 8 + 4] = r1;
    __syncwarp();
    float v[PCD];
    float sq = 0.f;
    #pragma unroll
    for (int d = 0; d < PCD; ++d) {
        v[d] = s[w][d * 32 + l];
        sq += v[d] * v[d];
    }
    const float sc = sq / (1.f + sq) / sqrtf(sq + 1e-7f);
    const int b = m / 36, sp = m % 36;
    const int n = l * 36 + sp;               // capsule index (m32 = l)
    float4 o0 = {v[0] * sc, v[1] * sc, v[2] * sc, v[3] * sc};
    float4 o1 = {v[4] * sc, v[5] * sc, v[6] * sc, v[7] * sc};
    float* dst = g_u + ((size_t)n * BATCH + b) * PCD;
    *(float4*)dst = o0;
    *(float4*)(dst + 4) = o1;
}

// ---------------- u_hat ----------------
__global__ void wu_kernel(const float* __restrict__ W) {
    __shared__ float s_u[64 * PCD];
    const int n = blockIdx.x;
    const int t = threadIdx.x;
    float wr[PCD];
    #pragma unroll
    for (int p = 0; p < PCD; ++p) wr[p] = W[n * (NC * DCD * PCD) + t * PCD + p];
    for (int b0 = 0; b0 < BATCH; b0 += 64) {
        __syncthreads();
        const uint4* src = (const uint4*)(g_u + ((size_t)n * BATCH + b0) * PCD);
        for (int i = t; i < 128; i += 160) ((uint4*)s_u)[i] = src[i];
        __syncthreads();
        for (int bb = 0; bb < 64; ++bb) {
            const float* up = &s_u[bb * PCD];
            float dot = 0.f;
            #pragma unroll
            for (int p = 0; p < PCD; ++p) dot += wr[p] * up[p];
            g_WU[((size_t)((b0 + bb) * NPRIM + n)) * 160 + t] = dot;
        }
    }
}

// ---------------- dynamic routing: warp-per-n, 3 WU passes ----------------
#define ROUT_SMEM ((11520 + 1600 + 160 + 16) * 4)

__device__ __forceinline__ void rout_reduce_squash(
    float* s_red, float* s_v, float* s_scale, const float* acc,
    int tid, int w, int l, float cs) {
    #pragma unroll
    for (int j = 0; j < 5; ++j) s_red[w * 160 + 32 * j + l] = acc[j];
    __syncthreads();
    if (tid < 160) {
        float v = 0.f;
        #pragma unroll
        for (int ww = 0; ww < 10; ++ww) v += s_red[ww * 160 + tid];
        s_v[tid] = v * cs;
    }
    __syncthreads();
    if (tid < NC) {
        float sq = 0.f;
        #pragma unroll
        for (int d = 0; d < DCD; ++d) { float x = s_v[tid * DCD + d]; sq += x * x; }
        s_scale[tid] = sq / (1.f + sq) / sqrtf(sq + 1e-7f);
    }
    __syncthreads();
    if (tid < 160) s_v[tid] *= s_scale[tid >> 4];
    __syncthreads();
}

__global__ void routing_kernel(float* __restrict__ out) {
    extern __shared__ float smf[];
    float* s_b     = smf;
    float* s_red   = smf + 11520;
    float* s_v     = smf + 13120;
    float* s_scale = smf + 13280;
    const int b = blockIdx.x, tid = threadIdx.x;
    const int w = tid >> 5, l = tid & 31;
    const int myh = l >> 4;
    const size_t wub = (size_t)b * NPRIM * 160;
    const unsigned FULL = 0xffffffffu;
    float acc[5];

    #pragma unroll
    for (int j = 0; j < 5; ++j) acc[j] = 0.f;
    for (int n = w; n < NPRIM; n += 10) {
        const float* row = g_WU + wub + (size_t)n * 160;
        #pragma unroll
        for (int j = 0; j < 5; ++j) acc[j] += row[l + 32 * j];
    }
    rout_reduce_squash(s_red, s_v, s_scale, acc, tid, w, l, 0.1f);

    #pragma unroll
    for (int j = 0; j < 5; ++j) acc[j] = 0.f;
    for (int n = w; n < NPRIM; n += 10) {
        const float* row = g_WU + wub + (size_t)n * 160;
        float wv[5], t[5];
        #pragma unroll
        for (int j = 0; j < 5; ++j) wv[j] = row[l + 32 * j];
        #pragma unroll
        for (int j = 0; j < 5; ++j) t[j] = s_v[l + 32 * j] * wv[j];
        #pragma unroll
        for (int j = 0; j < 5; ++j) {
            t[j] += __shfl_xor_sync(FULL, t[j], 8);
            t[j] += __shfl_xor_sync(FULL, t[j], 4);
            t[j] += __shfl_xor_sync(FULL, t[j], 2);
            t[j] += __shfl_xor_sync(FULL, t[j], 1);
            t[j] *= 0.1f;
        }
        float o[5];
        #pragma unroll
        for (int j = 0; j < 5; ++j) o[j] = __shfl_xor_sync(FULL, t[j], 16);
        float selt = t[0], selo = o[0];
        #pragma unroll
        for (int jj = 1; jj < 5; ++jj) {
            bool p = ((l >> 1) == jj);
            selt = p ? t[jj] : selt;
            selo = p ? o[jj] : selo;
        }
        const float bv = (l & 1) ? selo : selt;
        if (l < NC) s_b[n * NC + l] = bv;
        float m = (l < NC) ? bv : -1e30f;
        m = fmaxf(m, __shfl_xor_sync(FULL, m, 16));
        m = fmaxf(m, __shfl_xor_sync(FULL, m, 8));
        m = fmaxf(m, __shfl_xor_sync(FULL, m, 4));
        m = fmaxf(m, __shfl_xor_sync(FULL, m, 2));
        m = fmaxf(m, __shfl_xor_sync(FULL, m, 1));
        float e = (l < NC) ? __expf(bv - m) : 0.f;
        float S = e;
        S += __shfl_xor_sync(FULL, S, 16);
        S += __shfl_xor_sync(FULL, S, 8);
        S += __shfl_xor_sync(FULL, S, 4);
        S += __shfl_xor_sync(FULL, S, 2);
        S += __shfl_xor_sync(FULL, S, 1);
        const float en = e / S;
        #pragma unroll
        for (int j = 0; j < 5; ++j) {
            float cf = __shfl_sync(FULL, en, 2 * j + myh);
            acc[j] += cf * wv[j];
        }
    }
    rout_reduce_squash(s_red, s_v, s_scale, acc, tid, w, l, 1.f);

    #pragma unroll
    for (int j = 0; j < 5; ++j) acc[j] = 0.f;
    for (int n = w; n < NPRIM; n += 10) {
        const float* row = g_WU + wub + (size_t)n * 160;
        float wv[5];
        #pragma unroll
        for (int j = 0; j < 5; ++j) wv[j] = row[l + 32 * j];
        const float bv1 = (l < NC) ? s_b[n * NC + l] : 0.f;
        float m1 = (l < NC) ? bv1 : -1e30f;
        m1 = fmaxf(m1, __shfl_xor_sync(FULL, m1, 16));
        m1 = fmaxf(m1, __shfl_xor_sync(FULL, m1, 8));
        m1 = fmaxf(m1, __shfl_xor_sync(FULL, m1, 4));
        m1 = fmaxf(m1, __shfl_xor_sync(FULL, m1, 2));
        m1 = fmaxf(m1, __shfl_xor_sync(FULL, m1, 1));
        float e1 = (l < NC) ? __expf(bv1 - m1) : 0.f;
        float S1 = e1;
        S1 += __shfl_xor_sync(FULL, S1, 16);
        S1 += __shfl_xor_sync(FULL, S1, 8);
        S1 += __shfl_xor_sync(FULL, S1, 4);
        S1 += __shfl_xor_sync(FULL, S1, 2);
        S1 += __shfl_xor_sync(FULL, S1, 1);
        const float en1 = e1 / S1;
        float t2[5];
        #pragma unroll
        for (int j = 0; j < 5; ++j) {
            float cf1 = __shfl_sync(FULL, en1, 2 * j + myh);
            t2[j] = s_v[l + 32 * j] * cf1 * wv[j];
            t2[j] += __shfl_xor_sync(FULL, t2[j], 8);
            t2[j] += __shfl_xor_sync(FULL, t2[j], 4);
            t2[j] += __shfl_xor_sync(FULL, t2[j], 2);
            t2[j] += __shfl_xor_sync(FULL, t2[j], 1);
        }
        float o2[5];
        #pragma unroll
        for (int j = 0; j < 5; ++j) o2[j] = __shfl_xor_sync(FULL, t2[j], 16);
        float selt = t2[0], selo = o2[0];
        #pragma unroll
        for (int jj = 1; jj < 5; ++jj) {
            bool p = ((l >> 1) == jj);
            selt = p ? t2[jj] : selt;
            selo = p ? o2[jj] : selo;
        }
        const float b2v = bv1 + ((l & 1) ? selo : selt);
        float m2 = (l < NC) ? b2v : -1e30f;
        m2 = fmaxf(m2, __shfl_xor_sync(FULL, m2, 16));
        m2 = fmaxf(m2, __shfl_xor_sync(FULL, m2, 8));
        m2 = fmaxf(m2, __shfl_xor_sync(FULL, m2, 4));
        m2 = fmaxf(m2, __shfl_xor_sync(FULL, m2, 2));
        m2 = fmaxf(m2, __shfl_xor_sync(FULL, m2, 1));
        float e2 = (l < NC) ? __expf(b2v - m2) : 0.f;
        float S2 = e2;
        S2 += __shfl_xor_sync(FULL, S2, 16);
        S2 += __shfl_xor_sync(FULL, S2, 8);
        S2 += __shfl_xor_sync(FULL, S2, 4);
        S2 += __shfl_xor_sync(FULL, S2, 2);
        S2 += __shfl_xor_sync(FULL, S2, 1);
        const float en2 = e2 / S2;
        #pragma unroll
        for (int j = 0; j < 5; ++j) {
            float cf2 = __shfl_sync(FULL, en2, 2 * j + myh);
            acc[j] += cf2 * wv[j];
        }
    }
    rout_reduce_squash(s_red, s_v, s_scale, acc, tid, w, l, 1.f);

    if (tid < 160) g_v[b * 160 + tid] = s_v[tid];
    if (tid < NC) {
        float sq = 0.f;
        #pragma unroll
        for (int d = 0; d < DCD; ++d) { float x = s_v[tid * DCD + d]; sq += x * x; }
        out[b * NC + tid] = sqrtf(sq);
    }
}

// ---------------- masked decoder: 4 images per block ----------------
__global__ void decoder_kernel(const int* __restrict__ labels,
                               const float* __restrict__ w1, const float* __restrict__ bb1,
                               const float* __restrict__ w2, const float* __restrict__ bb2,
                               const float* __restrict__ w3, const float* __restrict__ bb3,
                               float* __restrict__ out) {
    __shared__ float h0[4][DCD];
    __shared__ float h1[4][512];
    __shared__ float h2[4][1024];
    __shared__ int   lab[4];
    const int t = threadIdx.x;
    const int b0 = blockIdx.x * 4;
    if (t < 4) lab[t] = labels[b0 + t];
    __syncthreads();
    if (t < 64) {
        int i = t >> 4, d = t & 15;
        h0[i][d] = g_v[(b0 + i) * 160 + lab[i] * DCD + d];
    }
    __syncthreads();
    for (int j = t; j < 512; j += 256) {
        float a[4];
        #pragma unroll
        for (int i = 0; i < 4; ++i) a[i] = bb1[j];
        #pragma unroll
        for (int k = 0; k < DCD; ++k) {
            #pragma unroll
            for (int i = 0; i < 4; ++i)
                a[i] += h0[i][k] * w1[(lab[i] * DCD + k) * 512 + j];
        }
        #pragma unroll
        for (int i = 0; i < 4; ++i) h1[i][j] = fmaxf(a[i], 0.f);
    }
    __syncthreads();
    for (int j = t; j < 1024; j += 256) {
        float a[4];
        #pragma unroll
        for (int i = 0; i < 4; ++i) a[i] = bb2[j];
        for (int k = 0; k < 512; ++k) {
            float wv = w2[k * 1024 + j];
            #pragma unroll
            for (int i = 0; i < 4; ++i) a[i] += h1[i][k] * wv;
        }
        #pragma unroll
        for (int i = 0; i < 4; ++i) h2[i][j] = fmaxf(a[i], 0.f);
    }
    __syncthreads();
    for (int j = t; j < 784; j += 256) {
        float a[4];
        #pragma unroll
        for (int i = 0; i < 4; ++i) a[i] = bb3[j];
        for (int k = 0; k < 1024; ++k) {
            float wv = w3[k * 784 + j];
            #pragma unroll
            for (int i = 0; i < 4; ++i) a[i] += h2[i][k] * wv;
        }
        #pragma unroll
        for (int i = 0; i < 4; ++i)
            out[BATCH * NC + (b0 + i) * 784 + j] = 1.f / (1.f + __expf(-a[i]));
    }
}

// ---------------- launch ----------------
extern "C" void kernel_launch(void* const* d_in, const int* in_sizes, int n_in,
                              void* d_out, int out_size) {
    const float* inputs  = (const float*)d_in[0];
    const int*   labels  = (const int*)d_in[1];
    const float* conv1_w = (const float*)d_in[2];
    const float* conv1_b = (const float*)d_in[3];
    const float* pc_w    = (const float*)d_in[4];
    const float* pc_b    = (const float*)d_in[5];
    const float* rw      = (const float*)d_in[6];
    const float* dw1     = (const float*)d_in[7];
    const float* db1     = (const float*)d_in[8];
    const float* dw2     = (const float*)d_in[9];
    const float* db2     = (const float*)d_in[10];
    const float* dw3     = (const float*)d_in[11];
    const float* db3     = (const float*)d_in[12];
    float* out = (float*)d_out;

    conv1_kernel<<<dim3(4, BATCH), 256>>>(inputs, conv1_w, conv1_b);
    convert_w_kernel<<<C1, 256>>>(pc_w);
    im2col_kernel<<<MTOT, 256>>>();

    cudaFuncSetAttribute(gemm_kernel, cudaFuncAttributeMaxDynamicSharedMemorySize, GEMM_SMEM);
    gemm_kernel<<<dim3(144, 2), 256, GEMM_SMEM>>>(pc_b);

    squash_u_kernel<<<NPRIM, 256>>>();
    wu_kernel<<<NPRIM, 160>>>(rw);

    cudaFuncSetAttribute(routing_kernel, cudaFuncAttributeMaxDynamicSharedMemorySize, ROUT_SMEM);
    routing_kernel<<<BATCH, 320, ROUT_SMEM>>>(out);

    decoder_kernel<<<BATCH / 4, 256>>>(labels, dw1, db1, dw2, db2, dw3, db3, out);
}

// round 7
// speedup vs baseline: 5.0292x; 1.0876x over previous
#include <cuda_runtime.h>
#include <cuda_bf16.h>
#include <math.h>
#include <stdint.h>

#define BATCH 256
#define C1 256
#define IMGD 28
#define NPRIM 1152
#define NC 10
#define PCD 8
#define DCD 16
#define KTOT 20736           // 81 r * 256 ic  (k = r*256 + ic)
#define MTOT 9216            // 256 b * 36 sp
#define NKT (KTOT / 64)      // 324

// ---------------- scratch ----------------
__device__ __align__(16) __nv_bfloat16 g_xh[(size_t)BATCH * 400 * C1];  // conv1 out hi [b][px][ic]
__device__ __align__(16) __nv_bfloat16 g_xl[(size_t)BATCH * 400 * C1];  // conv1 out lo
__device__ __align__(16) __nv_bfloat16 g_Bhi[(size_t)C1 * KTOT];
__device__ __align__(16) __nv_bfloat16 g_Blo[(size_t)C1 * KTOT];
__device__ float g_pc[(size_t)MTOT * C1];            // pc conv out [m][oc]
__device__ float g_u[BATCH * NPRIM * PCD];           // squashed, [n][b][p]
__device__ float g_WU[(size_t)BATCH * NPRIM * NC * DCD];
__device__ float g_v[BATCH * NC * DCD];

__device__ __forceinline__ uint32_t smem_u32(const void* p) {
    uint32_t a;
    asm("{ .reg .u64 t; cvta.to.shared.u64 t, %1; cvt.u32.u64 %0, t; }" : "=r"(a) : "l"(p));
    return a;
}
#define CP_ASYNC16(sa, ga) \
    asm volatile("cp.async.cg.shared.global [%0], [%1], 16;" :: "r"(sa), "l"(ga))
#define CP_COMMIT() asm volatile("cp.async.commit_group;" ::: "memory")
#define CP_WAIT1()  asm volatile("cp.async.wait_group 1;" ::: "memory")
#define CP_WAIT0()  asm volatile("cp.async.wait_group 0;" ::: "memory")
#define LDMX4(r0, r1, r2, r3, a) \
    asm volatile("ldmatrix.sync.aligned.m8n8.x4.shared.b16 {%0,%1,%2,%3}, [%4];" \
        : "=r"(r0), "=r"(r1), "=r"(r2), "=r"(r3) : "r"(a))
#define MMA16816(c, a, b0, b1) \
    asm volatile("mma.sync.aligned.m16n8k16.row.col.f32.bf16.bf16.f32 " \
        "{%0,%1,%2,%3},{%4,%5,%6,%7},{%8,%9},{%0,%1,%2,%3};" \
        : "+f"((c)[0]), "+f"((c)[1]), "+f"((c)[2]), "+f"((c)[3]) \
        : "r"((a)[0]), "r"((a)[1]), "r"((a)[2]), "r"((a)[3]), "r"(b0), "r"(b1))

// ---------------- conv1 + relu -> bf16 hi/lo [b][px][ic] ----------------
__global__ void conv1_kernel(const float* __restrict__ in,
                             const float* __restrict__ w,
                             const float* __restrict__ bias) {
    __shared__ float s_img[IMGD * IMGD];
    __shared__ float s_w[81 * 66];
    const int b = blockIdx.y, ocg = blockIdx.x, tid = threadIdx.x;
    const int oc0 = ocg * 64;
    for (int i = tid; i < IMGD * IMGD; i += 256) s_img[i] = in[b * IMGD * IMGD + i];
    for (int i = tid; i < 64 * 81; i += 256) {
        int o = i / 81, k = i % 81;
        s_w[k * 66 + o] = w[(oc0 + o) * 81 + k];
    }
    __syncthreads();
    const int ocp = tid & 31;        // lane = oc pair -> coalesced stores
    const int slot = tid >> 5;       // 0..7
    const float bv0 = bias[oc0 + 2 * ocp];
    const float bv1 = bias[oc0 + 2 * ocp + 1];
    for (int it = 0; it < 25; ++it) {
        const int px0 = 2 * (it * 8 + slot);
        const int oy = px0 / 20, ox = px0 % 20;
        float a00 = 0.f, a01 = 0.f, a10 = 0.f, a11 = 0.f;
        #pragma unroll 3
        for (int ky = 0; ky < 9; ++ky) {
            const float* r = &s_img[(oy + ky) * IMGD + ox];
            #pragma unroll
            for (int kx = 0; kx < 9; ++kx) {
                float2 wv = *(const float2*)&s_w[(ky * 9 + kx) * 66 + 2 * ocp];
                float i0 = r[kx], i1 = r[kx + 1];
                a00 += wv.x * i0; a01 += wv.x * i1;
                a10 += wv.y * i0; a11 += wv.y * i1;
            }
        }
        const float x00 = fmaxf(a00 + bv0, 0.f), x10 = fmaxf(a10 + bv1, 0.f);
        const float x01 = fmaxf(a01 + bv0, 0.f), x11 = fmaxf(a11 + bv1, 0.f);
        const size_t e0 = ((size_t)b * 400 + px0) * C1 + oc0 + 2 * ocp;
        __nv_bfloat16 h0 = __float2bfloat16_rn(x00), h1 = __float2bfloat16_rn(x10);
        __nv_bfloat16 h2 = __float2bfloat16_rn(x01), h3 = __float2bfloat16_rn(x11);
        __nv_bfloat162 hp0 = {h0, h1}, hp1 = {h2, h3};
        __nv_bfloat162 lp0 = {__float2bfloat16_rn(x00 - __bfloat162float(h0)),
                              __float2bfloat16_rn(x10 - __bfloat162float(h1))};
        __nv_bfloat162 lp1 = {__float2bfloat16_rn(x01 - __bfloat162float(h2)),
                              __float2bfloat16_rn(x11 - __bfloat162float(h3))};
        *(__nv_bfloat162*)&g_xh[e0]      = hp0;
        *(__nv_bfloat162*)&g_xh[e0 + C1] = hp1;
        *(__nv_bfloat162*)&g_xl[e0]      = lp0;
        *(__nv_bfloat162*)&g_xl[e0 + C1] = lp1;
    }
}

// ---------------- split pc_w -> bf16 hi/lo, k = r*256 + ic ----------------
__global__ void convert_w_kernel(const float* __restrict__ w) {
    const int oc = blockIdx.x, ic = threadIdx.x;
    const float* src = w + (size_t)oc * KTOT + (size_t)ic * 81;
    __nv_bfloat16* dh = g_Bhi + (size_t)oc * KTOT + ic;
    __nv_bfloat16* dl = g_Blo + (size_t)oc * KTOT + ic;
    #pragma unroll 9
    for (int r = 0; r < 81; ++r) {
        float x = src[r];
        __nv_bfloat16 h = __float2bfloat16_rn(x);
        dh[r * 256] = h;
        dl[r * 256] = __float2bfloat16_rn(x - __bfloat162float(h));
    }
}

// ---------------- implicit bf16x3 GEMM: A gathered from g_xh/g_xl ----------------
#define STG 49152
#define GEMM_SMEM (1024 + 2 * STG)

__global__ void __launch_bounds__(256, 2) gemm_kernel(const float* __restrict__ bias) {
    extern __shared__ char sm[];
    float* s_bias = (float*)sm;
    const uint32_t smb = smem_u32(sm);
    const int tid = threadIdx.x, lane = tid & 31, wid = tid >> 5;
    const int mtile = blockIdx.x, ntile = blockIdx.y;
    if (tid < 128) s_bias[tid] = bias[ntile * 128 + tid];

    const char* Bhi = (const char*)g_Bhi + (size_t)ntile * 128 * (KTOT * 2);
    const char* Blo = (const char*)g_Blo + (size_t)ntile * 128 * (KTOT * 2);

    // A gather geometry: 2 chunks per thread (512 chunks = 64 rows x 8)
    int abase[2], aso2[2];
    #pragma unroll
    for (int i = 0; i < 2; ++i) {
        const int lin = tid + i * 256;
        const int ar = lin >> 3, ch = lin & 7;
        const int m = mtile * 64 + ar;
        const int bb = m / 36, sp = m - bb * 36;
        const int pbase = (2 * (sp / 6)) * 20 + 2 * (sp % 6);
        abase[i] = ((bb * 400 + pbase) << 8) + ch * 8;   // element offset (bf16)
        aso2[i] = ar * 128 + ((ch ^ (ar & 7)) << 4);
    }
    // B geometry: 4 chunks per thread
    int brow[4], bso[4], bch[4];
    #pragma unroll
    for (int i = 0; i < 4; ++i) {
        int lin = tid + i * 256;
        brow[i] = lin >> 3; bch[i] = lin & 7;
        bso[i] = brow[i] * 128 + ((bch[i] ^ (brow[i] & 7)) << 4);
    }

    const int warp_m = wid >> 2, warp_n = wid & 3;
    int a_off[2], a_sw[2];
    #pragma unroll
    for (int sub = 0; sub < 2; ++sub) {
        int row = warp_m * 32 + sub * 16 + (lane & 15);
        a_off[sub] = row * 128; a_sw[sub] = row & 7;
    }
    const int a_cb = lane >> 4;
    int b_off[2], b_sw[2];
    #pragma unroll
    for (int j = 0; j < 2; ++j) {
        int row = warp_n * 32 + j * 16 + ((lane >> 4) << 3) + (lane & 7);
        b_off[j] = row * 128; b_sw[j] = row & 7;
    }
    const int b_cb = (lane >> 3) & 1;

    float acc[2][4][4];
    #pragma unroll
    for (int m = 0; m < 2; ++m)
        #pragma unroll
        for (int j = 0; j < 4; ++j)
            #pragma unroll
            for (int q = 0; q < 4; ++q) acc[m][j][q] = 0.f;

    auto issue = [&](int kk, int buf) {
        const uint32_t sAh = smb + 1024 + buf * STG;
        const uint32_t sAl = sAh + 8192;
        const uint32_t sBh = sAh + 16384;
        const uint32_t sBl = sAh + 32768;
        const int r = kk >> 2, icq = kk & 3;
        const int dy = (r * 57) >> 9;           // r/9 for r<81
        const int poff = ((dy * 20 + (r - dy * 9)) << 8) + (icq << 6);
        #pragma unroll
        for (int i = 0; i < 2; ++i) {
            const size_t e = (size_t)(abase[i] + poff) * 2;
            CP_ASYNC16(sAh + aso2[i], (const char*)g_xh + e);
            CP_ASYNC16(sAl + aso2[i], (const char*)g_xl + e);
        }
        const size_t kbyte = (size_t)kk * 128;
        #pragma unroll
        for (int i = 0; i < 4; ++i) {
            const size_t go = (size_t)brow[i] * (KTOT * 2) + kbyte + bch[i] * 16;
            CP_ASYNC16(sBh + bso[i], Bhi + go);
            CP_ASYNC16(sBl + bso[i], Blo + go);
        }
        CP_COMMIT();
    };

    issue(0, 0);
    for (int t = 0; t < NKT; ++t) {
        if (t + 1 < NKT) issue(t + 1, (t + 1) & 1);
        else CP_COMMIT();
        CP_WAIT1();
        __syncthreads();
        const uint32_t sAh = smb + 1024 + (t & 1) * STG;
        const uint32_t sAl = sAh + 8192;
        const uint32_t sBh = sAh + 16384;
        const uint32_t sBl = sAh + 32768;
        #pragma unroll
        for (int ks = 0; ks < 4; ++ks) {
            uint32_t ah[2][4], al[2][4], bh[2][4], bl[2][4];
            #pragma unroll
            for (int sub = 0; sub < 2; ++sub) {
                uint32_t co = ((((ks << 1) + a_cb) ^ a_sw[sub]) << 4);
                LDMX4(ah[sub][0], ah[sub][1], ah[sub][2], ah[sub][3], sAh + a_off[sub] + co);
                LDMX4(al[sub][0], al[sub][1], al[sub][2], al[sub][3], sAl + a_off[sub] + co);
            }
            #pragma unroll
            for (int j = 0; j < 2; ++j) {
                uint32_t co = ((((ks << 1) + b_cb) ^ b_sw[j]) << 4);
                LDMX4(bh[j][0], bh[j][1], bh[j][2], bh[j][3], sBh + b_off[j] + co);
                LDMX4(bl[j][0], bl[j][1], bl[j][2], bl[j][3], sBl + b_off[j] + co);
            }
            #pragma unroll
            for (int msub = 0; msub < 2; ++msub)
                #pragma unroll
                for (int j = 0; j < 2; ++j) {
                    MMA16816(acc[msub][2 * j],     ah[msub], bh[j][0], bh[j][1]);
                    MMA16816(acc[msub][2 * j + 1], ah[msub], bh[j][2], bh[j][3]);
                    MMA16816(acc[msub][2 * j],     ah[msub], bl[j][0], bl[j][1]);
                    MMA16816(acc[msub][2 * j + 1], ah[msub], bl[j][2], bl[j][3]);
                    MMA16816(acc[msub][2 * j],     al[msub], bh[j][0], bh[j][1]);
                    MMA16816(acc[msub][2 * j + 1], al[msub], bh[j][2], bh[j][3]);
                }
        }
        __syncthreads();
    }
    CP_WAIT0();

    const int r = lane >> 2, cpair = (lane & 3) * 2;
    #pragma unroll
    for (int msub = 0; msub < 2; ++msub) {
        const int gm0 = mtile * 64 + warp_m * 32 + msub * 16 + r;
        #pragma unroll
        for (int j = 0; j < 4; ++j) {
            const int ln = warp_n * 32 + j * 8 + cpair;
            const int gn = ntile * 128 + ln;
            const float b0 = s_bias[ln], b1 = s_bias[ln + 1];
            float2 v0 = {acc[msub][j][0] + b0, acc[msub][j][1] + b1};
            float2 v1 = {acc[msub][j][2] + b0, acc[msub][j][3] + b1};
            *(float2*)&g_pc[(size_t)gm0 * C1 + gn] = v0;
            *(float2*)&g_pc[(size_t)(gm0 + 8) * C1 + gn] = v1;
        }
    }
}

// ---------------- squash: warp-per-row coalesced ----------------
__global__ void squash_u_kernel() {
    __shared__ float s[8][256];
    const int tid = threadIdx.x, w = tid >> 5, l = tid & 31;
    const int m = blockIdx.x * 8 + w;
    const float* row = g_pc + (size_t)m * C1;
    float4 r0 = ((const float4*)row)[l * 2];
    float4 r1 = ((const float4*)row)[l * 2 + 1];
    *(float4*)&s[w][l * 8]     = r0;
    *(float4*)&s[w][l * 8 + 4] = r1;
    __syncwarp();
    float v[PCD];
    float sq = 0.f;
    #pragma unroll
    for (int d = 0; d < PCD; ++d) {
        v[d] = s[w][d * 32 + l];
        sq += v[d] * v[d];
    }
    const float sc = sq / (1.f + sq) / sqrtf(sq + 1e-7f);
    const int b = m / 36, sp = m % 36;
    const int n = l * 36 + sp;
    float4 o0 = {v[0] * sc, v[1] * sc, v[2] * sc, v[3] * sc};
    float4 o1 = {v[4] * sc, v[5] * sc, v[6] * sc, v[7] * sc};
    float* dst = g_u + ((size_t)n * BATCH + b) * PCD;
    *(float4*)dst = o0;
    *(float4*)(dst + 4) = o1;
}

// ---------------- u_hat ----------------
__global__ void wu_kernel(const float* __restrict__ W) {
    __shared__ float s_u[64 * PCD];
    const int n = blockIdx.x;
    const int t = threadIdx.x;
    float wr[PCD];
    #pragma unroll
    for (int p = 0; p < PCD; ++p) wr[p] = W[n * (NC * DCD * PCD) + t * PCD + p];
    for (int b0 = 0; b0 < BATCH; b0 += 64) {
        __syncthreads();
        const uint4* src = (const uint4*)(g_u + ((size_t)n * BATCH + b0) * PCD);
        for (int i = t; i < 128; i += 160) ((uint4*)s_u)[i] = src[i];
        __syncthreads();
        for (int bb = 0; bb < 64; ++bb) {
            const float* up = &s_u[bb * PCD];
            float dot = 0.f;
            #pragma unroll
            for (int p = 0; p < PCD; ++p) dot += wr[p] * up[p];
            g_WU[((size_t)((b0 + bb) * NPRIM + n)) * 160 + t] = dot;
        }
    }
}

// ---------------- dynamic routing: warp-per-n, 3 WU passes ----------------
#define ROUT_SMEM ((11520 + 1600 + 160 + 16) * 4)

__device__ __forceinline__ void rout_reduce_squash(
    float* s_red, float* s_v, float* s_scale, const float* acc,
    int tid, int w, int l, float cs) {
    #pragma unroll
    for (int j = 0; j < 5; ++j) s_red[w * 160 + 32 * j + l] = acc[j];
    __syncthreads();
    if (tid < 160) {
        float v = 0.f;
        #pragma unroll
        for (int ww = 0; ww < 10; ++ww) v += s_red[ww * 160 + tid];
        s_v[tid] = v * cs;
    }
    __syncthreads();
    if (tid < NC) {
        float sq = 0.f;
        #pragma unroll
        for (int d = 0; d < DCD; ++d) { float x = s_v[tid * DCD + d]; sq += x * x; }
        s_scale[tid] = sq / (1.f + sq) / sqrtf(sq + 1e-7f);
    }
    __syncthreads();
    if (tid < 160) s_v[tid] *= s_scale[tid >> 4];
    __syncthreads();
}

__global__ void routing_kernel(float* __restrict__ out) {
    extern __shared__ float smf[];
    float* s_b     = smf;
    float* s_red   = smf + 11520;
    float* s_v     = smf + 13120;
    float* s_scale = smf + 13280;
    const int b = blockIdx.x, tid = threadIdx.x;
    const int w = tid >> 5, l = tid & 31;
    const int myh = l >> 4;
    const size_t wub = (size_t)b * NPRIM * 160;
    const unsigned FULL = 0xffffffffu;
    float acc[5];

    #pragma unroll
    for (int j = 0; j < 5; ++j) acc[j] = 0.f;
    for (int n = w; n < NPRIM; n += 10) {
        const float* row = g_WU + wub + (size_t)n * 160;
        #pragma unroll
        for (int j = 0; j < 5; ++j) acc[j] += row[l + 32 * j];
    }
    rout_reduce_squash(s_red, s_v, s_scale, acc, tid, w, l, 0.1f);

    #pragma unroll
    for (int j = 0; j < 5; ++j) acc[j] = 0.f;
    for (int n = w; n < NPRIM; n += 10) {
        const float* row = g_WU + wub + (size_t)n * 160;
        float wv[5], t[5];
        #pragma unroll
        for (int j = 0; j < 5; ++j) wv[j] = row[l + 32 * j];
        #pragma unroll
        for (int j = 0; j < 5; ++j) t[j] = s_v[l + 32 * j] * wv[j];
        #pragma unroll
        for (int j = 0; j < 5; ++j) {
            t[j] += __shfl_xor_sync(FULL, t[j], 8);
            t[j] += __shfl_xor_sync(FULL, t[j], 4);
            t[j] += __shfl_xor_sync(FULL, t[j], 2);
            t[j] += __shfl_xor_sync(FULL, t[j], 1);
            t[j] *= 0.1f;
        }
        float o[5];
        #pragma unroll
        for (int j = 0; j < 5; ++j) o[j] = __shfl_xor_sync(FULL, t[j], 16);
        float selt = t[0], selo = o[0];
        #pragma unroll
        for (int jj = 1; jj < 5; ++jj) {
            bool p = ((l >> 1) == jj);
            selt = p ? t[jj] : selt;
            selo = p ? o[jj] : selo;
        }
        const float bv = (l & 1) ? selo : selt;
        if (l < NC) s_b[n * NC + l] = bv;
        float m = (l < NC) ? bv : -1e30f;
        m = fmaxf(m, __shfl_xor_sync(FULL, m, 16));
        m = fmaxf(m, __shfl_xor_sync(FULL, m, 8));
        m = fmaxf(m, __shfl_xor_sync(FULL, m, 4));
        m = fmaxf(m, __shfl_xor_sync(FULL, m, 2));
        m = fmaxf(m, __shfl_xor_sync(FULL, m, 1));
        float e = (l < NC) ? __expf(bv - m) : 0.f;
        float S = e;
        S += __shfl_xor_sync(FULL, S, 16);
        S += __shfl_xor_sync(FULL, S, 8);
        S += __shfl_xor_sync(FULL, S, 4);
        S += __shfl_xor_sync(FULL, S, 2);
        S += __shfl_xor_sync(FULL, S, 1);
        const float en = e / S;
        #pragma unroll
        for (int j = 0; j < 5; ++j) {
            float cf = __shfl_sync(FULL, en, 2 * j + myh);
            acc[j] += cf * wv[j];
        }
    }
    rout_reduce_squash(s_red, s_v, s_scale, acc, tid, w, l, 1.f);

    #pragma unroll
    for (int j = 0; j < 5; ++j) acc[j] = 0.f;
    for (int n = w; n < NPRIM; n += 10) {
        const float* row = g_WU + wub + (size_t)n * 160;
        float wv[5];
        #pragma unroll
        for (int j = 0; j < 5; ++j) wv[j] = row[l + 32 * j];
        const float bv1 = (l < NC) ? s_b[n * NC + l] : 0.f;
        float m1 = (l < NC) ? bv1 : -1e30f;
        m1 = fmaxf(m1, __shfl_xor_sync(FULL, m1, 16));
        m1 = fmaxf(m1, __shfl_xor_sync(FULL, m1, 8));
        m1 = fmaxf(m1, __shfl_xor_sync(FULL, m1, 4));
        m1 = fmaxf(m1, __shfl_xor_sync(FULL, m1, 2));
        m1 = fmaxf(m1, __shfl_xor_sync(FULL, m1, 1));
        float e1 = (l < NC) ? __expf(bv1 - m1) : 0.f;
        float S1 = e1;
        S1 += __shfl_xor_sync(FULL, S1, 16);
        S1 += __shfl_xor_sync(FULL, S1, 8);
        S1 += __shfl_xor_sync(FULL, S1, 4);
        S1 += __shfl_xor_sync(FULL, S1, 2);
        S1 += __shfl_xor_sync(FULL, S1, 1);
        const float en1 = e1 / S1;
        float t2[5];
        #pragma unroll
        for (int j = 0; j < 5; ++j) {
            float cf1 = __shfl_sync(FULL, en1, 2 * j + myh);
            t2[j] = s_v[l + 32 * j] * cf1 * wv[j];
            t2[j] += __shfl_xor_sync(FULL, t2[j], 8);
            t2[j] += __shfl_xor_sync(FULL, t2[j], 4);
            t2[j] += __shfl_xor_sync(FULL, t2[j], 2);
            t2[j] += __shfl_xor_sync(FULL, t2[j], 1);
        }
        float o2[5];
        #pragma unroll
        for (int j = 0; j < 5; ++j) o2[j] = __shfl_xor_sync(FULL, t2[j], 16);
        float selt = t2[0], selo = o2[0];
        #pragma unroll
        for (int jj = 1; jj < 5; ++jj) {
            bool p = ((l >> 1) == jj);
            selt = p ? t2[jj] : selt;
            selo = p ? o2[jj] : selo;
        }
        const float b2v = bv1 + ((l & 1) ? selo : selt);
        float m2 = (l < NC) ? b2v : -1e30f;
        m2 = fmaxf(m2, __shfl_xor_sync(FULL, m2, 16));
        m2 = fmaxf(m2, __shfl_xor_sync(FULL, m2, 8));
        m2 = fmaxf(m2, __shfl_xor_sync(FULL, m2, 4));
        m2 = fmaxf(m2, __shfl_xor_sync(FULL, m2, 2));
        m2 = fmaxf(m2, __shfl_xor_sync(FULL, m2, 1));
        float e2 = (l < NC) ? __expf(b2v - m2) : 0.f;
        float S2 = e2;
        S2 += __shfl_xor_sync(FULL, S2, 16);
        S2 += __shfl_xor_sync(FULL, S2, 8);
        S2 += __shfl_xor_sync(FULL, S2, 4);
        S2 += __shfl_xor_sync(FULL, S2, 2);
        S2 += __shfl_xor_sync(FULL, S2, 1);
        const float en2 = e2 / S2;
        #pragma unroll
        for (int j = 0; j < 5; ++j) {
            float cf2 = __shfl_sync(FULL, en2, 2 * j + myh);
            acc[j] += cf2 * wv[j];
        }
    }
    rout_reduce_squash(s_red, s_v, s_scale, acc, tid, w, l, 1.f);

    if (tid < 160) g_v[b * 160 + tid] = s_v[tid];
    if (tid < NC) {
        float sq = 0.f;
        #pragma unroll
        for (int d = 0; d < DCD; ++d) { float x = s_v[tid * DCD + d]; sq += x * x; }
        out[b * NC + tid] = sqrtf(sq);
    }
}

// ---------------- masked decoder: 4 images per block ----------------
__global__ void decoder_kernel(const int* __restrict__ labels,
                               const float* __restrict__ w1, const float* __restrict__ bb1,
                               const float* __restrict__ w2, const float* __restrict__ bb2,
                               const float* __restrict__ w3, const float* __restrict__ bb3,
                               float* __restrict__ out) {
    __shared__ float h0[4][DCD];
    __shared__ float h1[4][512];
    __shared__ float h2[4][1024];
    __shared__ int   lab[4];
    const int t = threadIdx.x;
    const int b0 = blockIdx.x * 4;
    if (t < 4) lab[t] = labels[b0 + t];
    __syncthreads();
    if (t < 64) {
        int i = t >> 4, d = t & 15;
        h0[i][d] = g_v[(b0 + i) * 160 + lab[i] * DCD + d];
    }
    __syncthreads();
    for (int j = t; j < 512; j += 256) {
        float a[4];
        #pragma unroll
        for (int i = 0; i < 4; ++i) a[i] = bb1[j];
        #pragma unroll
        for (int k = 0; k < DCD; ++k) {
            #pragma unroll
            for (int i = 0; i < 4; ++i)
                a[i] += h0[i][k] * w1[(lab[i] * DCD + k) * 512 + j];
        }
        #pragma unroll
        for (int i = 0; i < 4; ++i) h1[i][j] = fmaxf(a[i], 0.f);
    }
    __syncthreads();
    for (int j = t; j < 1024; j += 256) {
        float a[4];
        #pragma unroll
        for (int i = 0; i < 4; ++i) a[i] = bb2[j];
        for (int k = 0; k < 512; ++k) {
            float wv = w2[k * 1024 + j];
            #pragma unroll
            for (int i = 0; i < 4; ++i) a[i] += h1[i][k] * wv;
        }
        #pragma unroll
        for (int i = 0; i < 4; ++i) h2[i][j] = fmaxf(a[i], 0.f);
    }
    __syncthreads();
    for (int j = t; j < 784; j += 256) {
        float a[4];
        #pragma unroll
        for (int i = 0; i < 4; ++i) a[i] = bb3[j];
        for (int k = 0; k < 1024; ++k) {
            float wv = w3[k * 784 + j];
            #pragma unroll
            for (int i = 0; i < 4; ++i) a[i] += h2[i][k] * wv;
        }
        #pragma unroll
        for (int i = 0; i < 4; ++i)
            out[BATCH * NC + (b0 + i) * 784 + j] = 1.f / (1.f + __expf(-a[i]));
    }
}

// ---------------- launch ----------------
extern "C" void kernel_launch(void* const* d_in, const int* in_sizes, int n_in,
                              void* d_out, int out_size) {
    const float* inputs  = (const float*)d_in[0];
    const int*   labels  = (const int*)d_in[1];
    const float* conv1_w = (const float*)d_in[2];
    const float* conv1_b = (const float*)d_in[3];
    const float* pc_w    = (const float*)d_in[4];
    const float* pc_b    = (const float*)d_in[5];
    const float* rw      = (const float*)d_in[6];
    const float* dw1     = (const float*)d_in[7];
    const float* db1     = (const float*)d_in[8];
    const float* dw2     = (const float*)d_in[9];
    const float* db2     = (const float*)d_in[10];
    const float* dw3     = (const float*)d_in[11];
    const float* db3     = (const float*)d_in[12];
    float* out = (float*)d_out;

    convert_w_kernel<<<C1, 256>>>(pc_w);
    conv1_kernel<<<dim3(4, BATCH), 256>>>(inputs, conv1_w, conv1_b);

    cudaFuncSetAttribute(gemm_kernel, cudaFuncAttributeMaxDynamicSharedMemorySize, GEMM_SMEM);
    gemm_kernel<<<dim3(144, 2), 256, GEMM_SMEM>>>(pc_b);

    squash_u_kernel<<<NPRIM, 256>>>();
    wu_kernel<<<NPRIM, 160>>>(rw);

    cudaFuncSetAttribute(routing_kernel, cudaFuncAttributeMaxDynamicSharedMemorySize, ROUT_SMEM);
    routing_kernel<<<BATCH, 320, ROUT_SMEM>>>(out);

    decoder_kernel<<<BATCH / 4, 256>>>(labels, dw1, db1, dw2, db2, dw3, db3, out);
}

// round 9
// speedup vs baseline: 6.7314x; 1.3384x over previous
#include <cuda_runtime.h>
#include <cuda_fp16.h>
#include <math.h>
#include <stdint.h>

#define BATCH 256
#define C1 256
#define IMGD 28
#define NPRIM 1152
#define NC 10
#define PCD 8
#define DCD 16
#define KTOT 20736           // 81 r * 256 ic  (k = r*256 + ic)
#define MTOT 9216            // 256 b * 36 sp
#define NKT (KTOT / 64)      // 324

// ---------------- scratch ----------------
__device__ __align__(16) __half g_xh[(size_t)BATCH * 400 * C1];  // conv1 out fp16 [b][px][ic]
__device__ __align__(16) __half g_Bh[(size_t)C1 * KTOT];          // pc_w fp16 [oc][k]
__device__ float g_pc[(size_t)MTOT * C1];            // pc conv out [m][oc]
__device__ float g_u[BATCH * NPRIM * PCD];           // squashed, [n][b][p]
__device__ float g_WU[(size_t)BATCH * NPRIM * NC * DCD];
__device__ float g_v[BATCH * NC * DCD];

__device__ __forceinline__ uint32_t smem_u32(const void* p) {
    uint32_t a;
    asm("{ .reg .u64 t; cvta.to.shared.u64 t, %1; cvt.u32.u64 %0, t; }" : "=r"(a) : "l"(p));
    return a;
}
#define CP_ASYNC16(sa, ga) \
    asm volatile("cp.async.cg.shared.global [%0], [%1], 16;" :: "r"(sa), "l"(ga))
#define CP_COMMIT() asm volatile("cp.async.commit_group;" ::: "memory")
#define CP_WAIT2()  asm volatile("cp.async.wait_group 2;" ::: "memory")
#define CP_WAIT0()  asm volatile("cp.async.wait_group 0;" ::: "memory")
#define LDMX4(r0, r1, r2, r3, a) \
    asm volatile("ldmatrix.sync.aligned.m8n8.x4.shared.b16 {%0,%1,%2,%3}, [%4];" \
        : "=r"(r0), "=r"(r1), "=r"(r2), "=r"(r3) : "r"(a))
#define MMAF16(c, a, b0, b1) \
    asm volatile("mma.sync.aligned.m16n8k16.row.col.f32.f16.f16.f32 " \
        "{%0,%1,%2,%3},{%4,%5,%6,%7},{%8,%9},{%0,%1,%2,%3};" \
        : "+f"((c)[0]), "+f"((c)[1]), "+f"((c)[2]), "+f"((c)[3]) \
        : "r"((a)[0]), "r"((a)[1]), "r"((a)[2]), "r"((a)[3]), "r"(b0), "r"(b1))

// ---------------- conv1 + relu -> fp16 [b][px][ic] ----------------
__global__ void conv1_kernel(const float* __restrict__ in,
                             const float* __restrict__ w,
                             const float* __restrict__ bias) {
    __shared__ float s_img[IMGD * IMGD];
    __shared__ float s_w[81 * 66];
    const int b = blockIdx.y, ocg = blockIdx.x, tid = threadIdx.x;
    const int oc0 = ocg * 64;
    for (int i = tid; i < IMGD * IMGD; i += 256) s_img[i] = in[b * IMGD * IMGD + i];
    for (int i = tid; i < 64 * 81; i += 256) {
        int o = i / 81, k = i % 81;
        s_w[k * 66 + o] = w[(oc0 + o) * 81 + k];
    }
    __syncthreads();
    const int ocp = tid & 31;
    const int slot = tid >> 5;
    const float bv0 = bias[oc0 + 2 * ocp];
    const float bv1 = bias[oc0 + 2 * ocp + 1];
    for (int it = 0; it < 25; ++it) {
        const int px0 = 2 * (it * 8 + slot);
        const int oy = px0 / 20, ox = px0 % 20;
        float a00 = 0.f, a01 = 0.f, a10 = 0.f, a11 = 0.f;
        #pragma unroll 3
        for (int ky = 0; ky < 9; ++ky) {
            const float* r = &s_img[(oy + ky) * IMGD + ox];
            #pragma unroll
            for (int kx = 0; kx < 9; ++kx) {
                float2 wv = *(const float2*)&s_w[(ky * 9 + kx) * 66 + 2 * ocp];
                float i0 = r[kx], i1 = r[kx + 1];
                a00 += wv.x * i0; a01 += wv.x * i1;
                a10 += wv.y * i0; a11 += wv.y * i1;
            }
        }
        const size_t e0 = ((size_t)b * 400 + px0) * C1 + oc0 + 2 * ocp;
        __half2 p0 = {__float2half_rn(fmaxf(a00 + bv0, 0.f)),
                      __float2half_rn(fmaxf(a10 + bv1, 0.f))};
        __half2 p1 = {__float2half_rn(fmaxf(a01 + bv0, 0.f)),
                      __float2half_rn(fmaxf(a11 + bv1, 0.f))};
        *(__half2*)&g_xh[e0]      = p0;
        *(__half2*)&g_xh[e0 + C1] = p1;
    }
}

// ---------------- pc_w -> fp16, k = r*256 + ic ----------------
__global__ void convert_w_kernel(const float* __restrict__ w) {
    const int oc = blockIdx.x, ic = threadIdx.x;
    const float* src = w + (size_t)oc * KTOT + (size_t)ic * 81;
    __half* dh = g_Bh + (size_t)oc * KTOT + ic;
    #pragma unroll 9
    for (int r = 0; r < 81; ++r) dh[r * 256] = __float2half_rn(src[r]);
}

// ---------------- implicit fp16 GEMM, 4-stage pipeline, 1 sync/iter ----------------
#define STG 24576
#define GEMM_SMEM (1024 + 4 * STG)

__global__ void __launch_bounds__(256, 2) gemm_kernel(const float* __restrict__ bias) {
    extern __shared__ char sm[];
    float* s_bias = (float*)sm;
    const uint32_t smb = smem_u32(sm);
    const int tid = threadIdx.x, lane = tid & 31, wid = tid >> 5;
    const int mtile = blockIdx.x, ntile = blockIdx.y;
    if (tid < 128) s_bias[tid] = bias[ntile * 128 + tid];

    const char* Bh = (const char*)g_Bh + (size_t)ntile * 128 * (KTOT * 2);

    // A gather geometry: 2 chunks per thread
    int abase[2], aso2[2];
    #pragma unroll
    for (int i = 0; i < 2; ++i) {
        const int lin = tid + i * 256;
        const int ar = lin >> 3, ch = lin & 7;
        const int m = mtile * 64 + ar;
        const int bb = m / 36, sp = m - bb * 36;
        const int pbase = (2 * (sp / 6)) * 20 + 2 * (sp % 6);
        abase[i] = ((bb * 400 + pbase) << 8) + ch * 8;   // element offset (fp16)
        aso2[i] = ar * 128 + ((ch ^ (ar & 7)) << 4);
    }
    // B geometry: 4 chunks per thread
    int brow[4], bso[4], bch[4];
    #pragma unroll
    for (int i = 0; i < 4; ++i) {
        int lin = tid + i * 256;
        brow[i] = lin >> 3; bch[i] = lin & 7;
        bso[i] = brow[i] * 128 + ((bch[i] ^ (brow[i] & 7)) << 4);
    }

    const int warp_m = wid >> 2, warp_n = wid & 3;
    int a_off[2], a_sw[2];
    #pragma unroll
    for (int sub = 0; sub < 2; ++sub) {
        int row = warp_m * 32 + sub * 16 + (lane & 15);
        a_off[sub] = row * 128; a_sw[sub] = row & 7;
    }
    const int a_cb = lane >> 4;
    int b_off[2], b_sw[2];
    #pragma unroll
    for (int j = 0; j < 2; ++j) {
        int row = warp_n * 32 + j * 16 + ((lane >> 4) << 3) + (lane & 7);
        b_off[j] = row * 128; b_sw[j] = row & 7;
    }
    const int b_cb = (lane >> 3) & 1;

    float acc[2][4][4];
    #pragma unroll
    for (int m = 0; m < 2; ++m)
        #pragma unroll
        for (int j = 0; j < 4; ++j)
            #pragma unroll
            for (int q = 0; q < 4; ++q) acc[m][j][q] = 0.f;

    auto issue = [&](int kk, int buf) {
        const uint32_t sA = smb + 1024 + buf * STG;
        const uint32_t sB = sA + 8192;
        const int r = kk >> 2, icq = kk & 3;
        const int dy = (r * 57) >> 9;           // r/9 for r<81
        const int poff = ((dy * 20 + (r - dy * 9)) << 8) + (icq << 6);
        #pragma unroll
        for (int i = 0; i < 2; ++i) {
            const size_t e = (size_t)(abase[i] + poff) * 2;
            CP_ASYNC16(sA + aso2[i], (const char*)g_xh + e);
        }
        const size_t kbyte = (size_t)kk * 128;
        #pragma unroll
        for (int i = 0; i < 4; ++i) {
            const size_t go = (size_t)brow[i] * (KTOT * 2) + kbyte + bch[i] * 16;
            CP_ASYNC16(sB + bso[i], Bh + go);
        }
        CP_COMMIT();
    };

    issue(0, 0); issue(1, 1); issue(2, 2);

    for (int t = 0; t < NKT; ++t) {
        CP_WAIT2();            // stage t arrived (3 groups in flight max)
        __syncthreads();       // also orders overwrite of buf (t+3)&3 (= buf t-1)
        if (t + 3 < NKT) issue(t + 3, (t + 3) & 3);
        else CP_COMMIT();      // keep group count aligned
        const uint32_t sA = smb + 1024 + (t & 3) * STG;
        const uint32_t sB = sA + 8192;
        #pragma unroll
        for (int ks = 0; ks < 4; ++ks) {
            uint32_t a[2][4], bfr[2][4];
            #pragma unroll
            for (int sub = 0; sub < 2; ++sub) {
                uint32_t co = ((((ks << 1) + a_cb) ^ a_sw[sub]) << 4);
                LDMX4(a[sub][0], a[sub][1], a[sub][2], a[sub][3], sA + a_off[sub] + co);
            }
            #pragma unroll
            for (int j = 0; j < 2; ++j) {
                uint32_t co = ((((ks << 1) + b_cb) ^ b_sw[j]) << 4);
                LDMX4(bfr[j][0], bfr[j][1], bfr[j][2], bfr[j][3], sB + b_off[j] + co);
            }
            #pragma unroll
            for (int msub = 0; msub < 2; ++msub)
                #pragma unroll
                for (int j = 0; j < 2; ++j) {
                    MMAF16(acc[msub][2 * j],     a[msub], bfr[j][0], bfr[j][1]);
                    MMAF16(acc[msub][2 * j + 1], a[msub], bfr[j][2], bfr[j][3]);
                }
        }
    }
    CP_WAIT0();

    const int r = lane >> 2, cpair = (lane & 3) * 2;
    #pragma unroll
    for (int msub = 0; msub < 2; ++msub) {
        const int gm0 = mtile * 64 + warp_m * 32 + msub * 16 + r;
        #pragma unroll
        for (int j = 0; j < 4; ++j) {
            const int ln = warp_n * 32 + j * 8 + cpair;
            const int gn = ntile * 128 + ln;
            const float b0 = s_bias[ln], b1 = s_bias[ln + 1];
            float2 v0 = {acc[msub][j][0] + b0, acc[msub][j][1] + b1};
            float2 v1 = {acc[msub][j][2] + b0, acc[msub][j][3] + b1};
            *(float2*)&g_pc[(size_t)gm0 * C1 + gn] = v0;
            *(float2*)&g_pc[(size_t)(gm0 + 8) * C1 + gn] = v1;
        }
    }
}

// ---------------- squash: warp-per-row coalesced ----------------
__global__ void squash_u_kernel() {
    __shared__ float s[8][256];
    const int tid = threadIdx.x, w = tid >> 5, l = tid & 31;
    const int m = blockIdx.x * 8 + w;
    const float* row = g_pc + (size_t)m * C1;
    float4 r0 = ((const float4*)row)[l * 2];
    float4 r1 = ((const float4*)row)[l * 2 + 1];
    *(float4*)&s[w][l * 8]     = r0;
    *(float4*)&s[w][l * 8 + 4] = r1;
    __syncwarp();
    float v[PCD];
    float sq = 0.f;
    #pragma unroll
    for (int d = 0; d < PCD; ++d) {
        v[d] = s[w][d * 32 + l];
        sq += v[d] * v[d];
    }
    const float sc = sq / (1.f + sq) / sqrtf(sq + 1e-7f);
    const int b = m / 36, sp = m % 36;
    const int n = l * 36 + sp;
    float4 o0 = {v[0] * sc, v[1] * sc, v[2] * sc, v[3] * sc};
    float4 o1 = {v[4] * sc, v[5] * sc, v[6] * sc, v[7] * sc};
    float* dst = g_u + ((size_t)n * BATCH + b) * PCD;
    *(float4*)dst = o0;
    *(float4*)(dst + 4) = o1;
}

// ---------------- u_hat ----------------
__global__ void wu_kernel(const float* __restrict__ W) {
    __shared__ float s_u[64 * PCD];
    const int n = blockIdx.x;
    const int t = threadIdx.x;
    float wr[PCD];
    #pragma unroll
    for (int p = 0; p < PCD; ++p) wr[p] = W[n * (NC * DCD * PCD) + t * PCD + p];
    for (int b0 = 0; b0 < BATCH; b0 += 64) {
        __syncthreads();
        const uint4* src = (const uint4*)(g_u + ((size_t)n * BATCH + b0) * PCD);
        for (int i = t; i < 128; i += 160) ((uint4*)s_u)[i] = src[i];
        __syncthreads();
        for (int bb = 0; bb < 64; ++bb) {
            const float* up = &s_u[bb * PCD];
            float dot = 0.f;
            #pragma unroll
            for (int p = 0; p < PCD; ++p) dot += wr[p] * up[p];
            g_WU[((size_t)((b0 + bb) * NPRIM + n)) * 160 + t] = dot;
        }
    }
}

// ---------------- dynamic routing: warp-per-n, 3 WU passes ----------------
#define ROUT_SMEM ((11520 + 1600 + 160 + 16) * 4)

__device__ __forceinline__ void rout_reduce_squash(
    float* s_red, float* s_v, float* s_scale, const float* acc,
    int tid, int w, int l, float cs) {
    #pragma unroll
    for (int j = 0; j < 5; ++j) s_red[w * 160 + 32 * j + l] = acc[j];
    __syncthreads();
    if (tid < 160) {
        float v = 0.f;
        #pragma unroll
        for (int ww = 0; ww < 10; ++ww) v += s_red[ww * 160 + tid];
        s_v[tid] = v * cs;
    }
    __syncthreads();
    if (tid < NC) {
        float sq = 0.f;
        #pragma unroll
        for (int d = 0; d < DCD; ++d) { float x = s_v[tid * DCD + d]; sq += x * x; }
        s_scale[tid] = sq / (1.f + sq) / sqrtf(sq + 1e-7f);
    }
    __syncthreads();
    if (tid < 160) s_v[tid] *= s_scale[tid >> 4];
    __syncthreads();
}

__global__ void routing_kernel(float* __restrict__ out) {
    extern __shared__ float smf[];
    float* s_b     = smf;
    float* s_red   = smf + 11520;
    float* s_v     = smf + 13120;
    float* s_scale = smf + 13280;
    const int b = blockIdx.x, tid = threadIdx.x;
    const int w = tid >> 5, l = tid & 31;
    const int myh = l >> 4;
    const size_t wub = (size_t)b * NPRIM * 160;
    const unsigned FULL = 0xffffffffu;
    float acc[5];

    #pragma unroll
    for (int j = 0; j < 5; ++j) acc[j] = 0.f;
    for (int n = w; n < NPRIM; n += 10) {
        const float* row = g_WU + wub + (size_t)n * 160;
        #pragma unroll
        for (int j = 0; j < 5; ++j) acc[j] += row[l + 32 * j];
    }
    rout_reduce_squash(s_red, s_v, s_scale, acc, tid, w, l, 0.1f);

    #pragma unroll
    for (int j = 0; j < 5; ++j) acc[j] = 0.f;
    for (int n = w; n < NPRIM; n += 10) {
        const float* row = g_WU + wub + (size_t)n * 160;
        float wv[5], t[5];
        #pragma unroll
        for (int j = 0; j < 5; ++j) wv[j] = row[l + 32 * j];
        #pragma unroll
        for (int j = 0; j < 5; ++j) t[j] = s_v[l + 32 * j] * wv[j];
        #pragma unroll
        for (int j = 0; j < 5; ++j) {
            t[j] += __shfl_xor_sync(FULL, t[j], 8);
            t[j] += __shfl_xor_sync(FULL, t[j], 4);
            t[j] += __shfl_xor_sync(FULL, t[j], 2);
            t[j] += __shfl_xor_sync(FULL, t[j], 1);
            t[j] *= 0.1f;
        }
        float o[5];
        #pragma unroll
        for (int j = 0; j < 5; ++j) o[j] = __shfl_xor_sync(FULL, t[j], 16);
        float selt = t[0], selo = o[0];
        #pragma unroll
        for (int jj = 1; jj < 5; ++jj) {
            bool p = ((l >> 1) == jj);
            selt = p ? t[jj] : selt;
            selo = p ? o[jj] : selo;
        }
        const float bv = (l & 1) ? selo : selt;
        if (l < NC) s_b[n * NC + l] = bv;
        float m = (l < NC) ? bv : -1e30f;
        m = fmaxf(m, __shfl_xor_sync(FULL, m, 16));
        m = fmaxf(m, __shfl_xor_sync(FULL, m, 8));
        m = fmaxf(m, __shfl_xor_sync(FULL, m, 4));
        m = fmaxf(m, __shfl_xor_sync(FULL, m, 2));
        m = fmaxf(m, __shfl_xor_sync(FULL, m, 1));
        float e = (l < NC) ? __expf(bv - m) : 0.f;
        float S = e;
        S += __shfl_xor_sync(FULL, S, 16);
        S += __shfl_xor_sync(FULL, S, 8);
        S += __shfl_xor_sync(FULL, S, 4);
        S += __shfl_xor_sync(FULL, S, 2);
        S += __shfl_xor_sync(FULL, S, 1);
        const float en = e / S;
        #pragma unroll
        for (int j = 0; j < 5; ++j) {
            float cf = __shfl_sync(FULL, en, 2 * j + myh);
            acc[j] += cf * wv[j];
        }
    }
    rout_reduce_squash(s_red, s_v, s_scale, acc, tid, w, l, 1.f);

    #pragma unroll
    for (int j = 0; j < 5; ++j) acc[j] = 0.f;
    for (int n = w; n < NPRIM; n += 10) {
        const float* row = g_WU + wub + (size_t)n * 160;
        float wv[5];
        #pragma unroll
        for (int j = 0; j < 5; ++j) wv[j] = row[l + 32 * j];
        const float bv1 = (l < NC) ? s_b[n * NC + l] : 0.f;
        float m1 = (l < NC) ? bv1 : -1e30f;
        m1 = fmaxf(m1, __shfl_xor_sync(FULL, m1, 16));
        m1 = fmaxf(m1, __shfl_xor_sync(FULL, m1, 8));
        m1 = fmaxf(m1, __shfl_xor_sync(FULL, m1, 4));
        m1 = fmaxf(m1, __shfl_xor_sync(FULL, m1, 2));
        m1 = fmaxf(m1, __shfl_xor_sync(FULL, m1, 1));
        float e1 = (l < NC) ? __expf(bv1 - m1) : 0.f;
        float S1 = e1;
        S1 += __shfl_xor_sync(FULL, S1, 16);
        S1 += __shfl_xor_sync(FULL, S1, 8);
        S1 += __shfl_xor_sync(FULL, S1, 4);
        S1 += __shfl_xor_sync(FULL, S1, 2);
        S1 += __shfl_xor_sync(FULL, S1, 1);
        const float en1 = e1 / S1;
        float t2[5];
        #pragma unroll
        for (int j = 0; j < 5; ++j) {
            float cf1 = __shfl_sync(FULL, en1, 2 * j + myh);
            t2[j] = s_v[l + 32 * j] * cf1 * wv[j];
            t2[j] += __shfl_xor_sync(FULL, t2[j], 8);
            t2[j] += __shfl_xor_sync(FULL, t2[j], 4);
            t2[j] += __shfl_xor_sync(FULL, t2[j], 2);
            t2[j] += __shfl_xor_sync(FULL, t2[j], 1);
        }
        float o2[5];
        #pragma unroll
        for (int j = 0; j < 5; ++j) o2[j] = __shfl_xor_sync(FULL, t2[j], 16);
        float selt = t2[0], selo = o2[0];
        #pragma unroll
        for (int jj = 1; jj < 5; ++jj) {
            bool p = ((l >> 1) == jj);
            selt = p ? t2[jj] : selt;
            selo = p ? o2[jj] : selo;
        }
        const float b2v = bv1 + ((l & 1) ? selo : selt);
        float m2 = (l < NC) ? b2v : -1e30f;
        m2 = fmaxf(m2, __shfl_xor_sync(FULL, m2, 16));
        m2 = fmaxf(m2, __shfl_xor_sync(FULL, m2, 8));
        m2 = fmaxf(m2, __shfl_xor_sync(FULL, m2, 4));
        m2 = fmaxf(m2, __shfl_xor_sync(FULL, m2, 2));
        m2 = fmaxf(m2, __shfl_xor_sync(FULL, m2, 1));
        float e2 = (l < NC) ? __expf(b2v - m2) : 0.f;
        float S2 = e2;
        S2 += __shfl_xor_sync(FULL, S2, 16);
        S2 += __shfl_xor_sync(FULL, S2, 8);
        S2 += __shfl_xor_sync(FULL, S2, 4);
        S2 += __shfl_xor_sync(FULL, S2, 2);
        S2 += __shfl_xor_sync(FULL, S2, 1);
        const float en2 = e2 / S2;
        #pragma unroll
        for (int j = 0; j < 5; ++j) {
            float cf2 = __shfl_sync(FULL, en2, 2 * j + myh);
            acc[j] += cf2 * wv[j];
        }
    }
    rout_reduce_squash(s_red, s_v, s_scale, acc, tid, w, l, 1.f);

    if (tid < 160) g_v[b * 160 + tid] = s_v[tid];
    if (tid < NC) {
        float sq = 0.f;
        #pragma unroll
        for (int d = 0; d < DCD; ++d) { float x = s_v[tid * DCD + d]; sq += x * x; }
        out[b * NC + tid] = sqrtf(sq);
    }
}

// ---------------- masked decoder: 4 images per block ----------------
__global__ void decoder_kernel(const int* __restrict__ labels,
                               const float* __restrict__ w1, const float* __restrict__ bb1,
                               const float* __restrict__ w2, const float* __restrict__ bb2,
                               const float* __restrict__ w3, const float* __restrict__ bb3,
                               float* __restrict__ out) {
    __shared__ float h0[4][DCD];
    __shared__ float h1[4][512];
    __shared__ float h2[4][1024];
    __shared__ int   lab[4];
    const int t = threadIdx.x;
    const int b0 = blockIdx.x * 4;
    if (t < 4) lab[t] = labels[b0 + t];
    __syncthreads();
    if (t < 64) {
        int i = t >> 4, d = t & 15;
        h0[i][d] = g_v[(b0 + i) * 160 + lab[i] * DCD + d];
    }
    __syncthreads();
    for (int j = t; j < 512; j += 256) {
        float a[4];
        #pragma unroll
        for (int i = 0; i < 4; ++i) a[i] = bb1[j];
        #pragma unroll
        for (int k = 0; k < DCD; ++k) {
            #pragma unroll
            for (int i = 0; i < 4; ++i)
                a[i] += h0[i][k] * w1[(lab[i] * DCD + k) * 512 + j];
        }
        #pragma unroll
        for (int i = 0; i < 4; ++i) h1[i][j] = fmaxf(a[i], 0.f);
    }
    __syncthreads();
    for (int j = t; j < 1024; j += 256) {
        float a[4];
        #pragma unroll
        for (int i = 0; i < 4; ++i) a[i] = bb2[j];
        for (int k = 0; k < 512; ++k) {
            float wv = w2[k * 1024 + j];
            #pragma unroll
            for (int i = 0; i < 4; ++i) a[i] += h1[i][k] * wv;
        }
        #pragma unroll
        for (int i = 0; i < 4; ++i) h2[i][j] = fmaxf(a[i], 0.f);
    }
    __syncthreads();
    for (int j = t; j < 784; j += 256) {
        float a[4];
        #pragma unroll
        for (int i = 0; i < 4; ++i) a[i] = bb3[j];
        for (int k = 0; k < 1024; ++k) {
            float wv = w3[k * 784 + j];
            #pragma unroll
            for (int i = 0; i < 4; ++i) a[i] += h2[i][k] * wv;
        }
        #pragma unroll
        for (int i = 0; i < 4; ++i)
            out[BATCH * NC + (b0 + i) * 784 + j] = 1.f / (1.f + __expf(-a[i]));
    }
}

// ---------------- launch ----------------
extern "C" void kernel_launch(void* const* d_in, const int* in_sizes, int n_in,
                              void* d_out, int out_size) {
    const float* inputs  = (const float*)d_in[0];
    const int*   labels  = (const int*)d_in[1];
    const float* conv1_w = (const float*)d_in[2];
    const float* conv1_b = (const float*)d_in[3];
    const float* pc_w    = (const float*)d_in[4];
    const float* pc_b    = (const float*)d_in[5];
    const float* rw      = (const float*)d_in[6];
    const float* dw1     = (const float*)d_in[7];
    const float* db1     = (const float*)d_in[8];
    const float* dw2     = (const float*)d_in[9];
    const float* db2     = (const float*)d_in[10];
    const float* dw3     = (const float*)d_in[11];
    const float* db3     = (const float*)d_in[12];
    float* out = (float*)d_out;

    convert_w_kernel<<<C1, 256>>>(pc_w);
    conv1_kernel<<<dim3(4, BATCH), 256>>>(inputs, conv1_w, conv1_b);

    cudaFuncSetAttribute(gemm_kernel, cudaFuncAttributeMaxDynamicSharedMemorySize, GEMM_SMEM);
    gemm_kernel<<<dim3(144, 2), 256, GEMM_SMEM>>>(pc_b);

    squash_u_kernel<<<NPRIM, 256>>>();
    wu_kernel<<<NPRIM, 160>>>(rw);

    cudaFuncSetAttribute(routing_kernel, cudaFuncAttributeMaxDynamicSharedMemorySize, ROUT_SMEM);
    routing_kernel<<<BATCH, 320, ROUT_SMEM>>>(out);

    decoder_kernel<<<BATCH / 4, 256>>>(labels, dw1, db1, dw2, db2, dw3, db3, out);
}

// round 10
// speedup vs baseline: 6.8480x; 1.0173x over previous
#include <cuda_runtime.h>
#include <cuda_fp16.h>
#include <math.h>
#include <stdint.h>

#define BATCH 256
#define C1 256
#define IMGD 28
#define NPRIM 1152
#define NC 10
#define PCD 8
#define DCD 16
#define KTOT 20736           // 81 r * 256 ic  (k = r*256 + ic)
#define MTOT 9216            // 256 b * 36 sp
#define NKT (KTOT / 64)      // 324

// ---------------- scratch ----------------
__device__ __align__(16) __half g_xh[(size_t)BATCH * 400 * C1];  // conv1 out fp16 [b][px][ic]
__device__ __align__(16) __half g_Bh[(size_t)C1 * KTOT];         // pc_w fp16 [oc][k]
__device__ float g_pc[(size_t)MTOT * C1];                        // pc conv out [m][oc]
__device__ float g_u[BATCH * NPRIM * PCD];                       // squashed, [n][b][p]
__device__ __align__(16) __half g_WUh[(size_t)BATCH * NPRIM * NC * DCD];  // u_hat fp16
__device__ float g_v[BATCH * NC * DCD];
__device__ __align__(16) __half g_w2h[512 * 1024];
__device__ __align__(16) __half g_w3h[1024 * 784];

__device__ __forceinline__ uint32_t smem_u32(const void* p) {
    uint32_t a;
    asm("{ .reg .u64 t; cvta.to.shared.u64 t, %1; cvt.u32.u64 %0, t; }" : "=r"(a) : "l"(p));
    return a;
}
#define CP_ASYNC16(sa, ga) \
    asm volatile("cp.async.cg.shared.global [%0], [%1], 16;" :: "r"(sa), "l"(ga))
#define CP_COMMIT() asm volatile("cp.async.commit_group;" ::: "memory")
#define CP_WAIT2()  asm volatile("cp.async.wait_group 2;" ::: "memory")
#define CP_WAIT0()  asm volatile("cp.async.wait_group 0;" ::: "memory")
#define LDMX4(r0, r1, r2, r3, a) \
    asm volatile("ldmatrix.sync.aligned.m8n8.x4.shared.b16 {%0,%1,%2,%3}, [%4];" \
        : "=r"(r0), "=r"(r1), "=r"(r2), "=r"(r3) : "r"(a))
#define MMAF16(c, a, b0, b1) \
    asm volatile("mma.sync.aligned.m16n8k16.row.col.f32.f16.f16.f32 " \
        "{%0,%1,%2,%3},{%4,%5,%6,%7},{%8,%9},{%0,%1,%2,%3};" \
        : "+f"((c)[0]), "+f"((c)[1]), "+f"((c)[2]), "+f"((c)[3]) \
        : "r"((a)[0]), "r"((a)[1]), "r"((a)[2]), "r"((a)[3]), "r"(b0), "r"(b1))

// ---------------- conv1 + relu -> fp16 [b][px][ic] ----------------
__global__ void conv1_kernel(const float* __restrict__ in,
                             const float* __restrict__ w,
                             const float* __restrict__ bias) {
    __shared__ float s_img[IMGD * IMGD];
    __shared__ float s_w[81 * 66];
    const int b = blockIdx.y, ocg = blockIdx.x, tid = threadIdx.x;
    const int oc0 = ocg * 64;
    for (int i = tid; i < IMGD * IMGD; i += 256) s_img[i] = in[b * IMGD * IMGD + i];
    for (int i = tid; i < 64 * 81; i += 256) {
        int o = i / 81, k = i % 81;
        s_w[k * 66 + o] = w[(oc0 + o) * 81 + k];
    }
    __syncthreads();
    const int ocp = tid & 31;
    const int slot = tid >> 5;
    const float bv0 = bias[oc0 + 2 * ocp];
    const float bv1 = bias[oc0 + 2 * ocp + 1];
    for (int it = 0; it < 25; ++it) {
        const int px0 = 2 * (it * 8 + slot);
        const int oy = px0 / 20, ox = px0 % 20;
        float a00 = 0.f, a01 = 0.f, a10 = 0.f, a11 = 0.f;
        #pragma unroll 3
        for (int ky = 0; ky < 9; ++ky) {
            const float* r = &s_img[(oy + ky) * IMGD + ox];
            #pragma unroll
            for (int kx = 0; kx < 9; ++kx) {
                float2 wv = *(const float2*)&s_w[(ky * 9 + kx) * 66 + 2 * ocp];
                float i0 = r[kx], i1 = r[kx + 1];
                a00 += wv.x * i0; a01 += wv.x * i1;
                a10 += wv.y * i0; a11 += wv.y * i1;
            }
        }
        const size_t e0 = ((size_t)b * 400 + px0) * C1 + oc0 + 2 * ocp;
        __half2 p0 = {__float2half_rn(fmaxf(a00 + bv0, 0.f)),
                      __float2half_rn(fmaxf(a10 + bv1, 0.f))};
        __half2 p1 = {__float2half_rn(fmaxf(a01 + bv0, 0.f)),
                      __float2half_rn(fmaxf(a11 + bv1, 0.f))};
        *(__half2*)&g_xh[e0]      = p0;
        *(__half2*)&g_xh[e0 + C1] = p1;
    }
}

// ---------------- pc_w -> fp16, k = r*256 + ic ----------------
__global__ void convert_w_kernel(const float* __restrict__ w) {
    const int oc = blockIdx.x, ic = threadIdx.x;
    const float* src = w + (size_t)oc * KTOT + (size_t)ic * 81;
    __half* dh = g_Bh + (size_t)oc * KTOT + ic;
    #pragma unroll 9
    for (int r = 0; r < 81; ++r) dh[r * 256] = __float2half_rn(src[r]);
}

// ---------------- decoder w2/w3 -> fp16 ----------------
__global__ void convert_dec_kernel(const float* __restrict__ w2,
                                   const float* __restrict__ w3) {
    const int i = blockIdx.x * 256 + threadIdx.x;
    if (i < 512 * 1024) g_w2h[i] = __float2half_rn(w2[i]);
    if (i < 1024 * 784) g_w3h[i] = __float2half_rn(w3[i]);
}

// ---------------- implicit fp16 GEMM: 128x128 tile, 512 threads, 4-stage ----------------
#define STG 32768
#define GEMM_SMEM (1024 + 4 * STG)

__global__ void __launch_bounds__(512, 1) gemm_kernel(const float* __restrict__ bias) {
    extern __shared__ char sm[];
    float* s_bias = (float*)sm;
    const uint32_t smb = smem_u32(sm);
    const int tid = threadIdx.x, lane = tid & 31, wid = tid >> 5;   // 16 warps
    const int mtile = blockIdx.x, ntile = blockIdx.y;
    if (tid < 128) s_bias[tid] = bias[ntile * 128 + tid];

    const char* Bh = (const char*)g_Bh + (size_t)ntile * 128 * (KTOT * 2);

    // A gather geometry: 2 chunks per thread (1024 chunks = 128 rows x 8)
    int abase[2], aso2[2];
    #pragma unroll
    for (int i = 0; i < 2; ++i) {
        const int lin = tid + i * 512;
        const int ar = lin >> 3, ch = lin & 7;
        const int m = mtile * 128 + ar;
        const int bb = m / 36, sp = m - bb * 36;
        const int pbase = (2 * (sp / 6)) * 20 + 2 * (sp % 6);
        abase[i] = ((bb * 400 + pbase) << 8) + ch * 8;   // element offset (fp16)
        aso2[i] = ar * 128 + ((ch ^ (ar & 7)) << 4);
    }
    // B geometry: 2 chunks per thread
    int brow[2], bso[2], bch[2];
    #pragma unroll
    for (int i = 0; i < 2; ++i) {
        int lin = tid + i * 512;
        brow[i] = lin >> 3; bch[i] = lin & 7;
        bso[i] = brow[i] * 128 + ((bch[i] ^ (brow[i] & 7)) << 4);
    }

    const int warp_m = wid >> 2, warp_n = wid & 3;    // 4x4 warps, warp tile 32x32
    int a_off[2], a_sw[2];
    #pragma unroll
    for (int sub = 0; sub < 2; ++sub) {
        int row = warp_m * 32 + sub * 16 + (lane & 15);
        a_off[sub] = row * 128; a_sw[sub] = row & 7;
    }
    const int a_cb = lane >> 4;
    int b_off[2], b_sw[2];
    #pragma unroll
    for (int j = 0; j < 2; ++j) {
        int row = warp_n * 32 + j * 16 + ((lane >> 4) << 3) + (lane & 7);
        b_off[j] = row * 128; b_sw[j] = row & 7;
    }
    const int b_cb = (lane >> 3) & 1;

    float acc[2][4][4];
    #pragma unroll
    for (int m = 0; m < 2; ++m)
        #pragma unroll
        for (int j = 0; j < 4; ++j)
            #pragma unroll
            for (int q = 0; q < 4; ++q) acc[m][j][q] = 0.f;

    auto issue = [&](int kk, int buf) {
        const uint32_t sA = smb + 1024 + buf * STG;
        const uint32_t sB = sA + 16384;
        const int r = kk >> 2, icq = kk & 3;
        const int dy = (r * 57) >> 9;           // r/9 for r<81
        const int poff = ((dy * 20 + (r - dy * 9)) << 8) + (icq << 6);
        #pragma unroll
        for (int i = 0; i < 2; ++i) {
            const size_t e = (size_t)(abase[i] + poff) * 2;
            CP_ASYNC16(sA + aso2[i], (const char*)g_xh + e);
        }
        const size_t kbyte = (size_t)kk * 128;
        #pragma unroll
        for (int i = 0; i < 2; ++i) {
            const size_t go = (size_t)brow[i] * (KTOT * 2) + kbyte + bch[i] * 16;
            CP_ASYNC16(sB + bso[i], Bh + go);
        }
        CP_COMMIT();
    };

    issue(0, 0); issue(1, 1); issue(2, 2);

    for (int t = 0; t < NKT; ++t) {
        CP_WAIT2();
        __syncthreads();
        if (t + 3 < NKT) issue(t + 3, (t + 3) & 3);
        else CP_COMMIT();
        const uint32_t sA = smb + 1024 + (t & 3) * STG;
        const uint32_t sB = sA + 16384;
        #pragma unroll
        for (int ks = 0; ks < 4; ++ks) {
            uint32_t a[2][4], bfr[2][4];
            #pragma unroll
            for (int sub = 0; sub < 2; ++sub) {
                uint32_t co = ((((ks << 1) + a_cb) ^ a_sw[sub]) << 4);
                LDMX4(a[sub][0], a[sub][1], a[sub][2], a[sub][3], sA + a_off[sub] + co);
            }
            #pragma unroll
            for (int j = 0; j < 2; ++j) {
                uint32_t co = ((((ks << 1) + b_cb) ^ b_sw[j]) << 4);
                LDMX4(bfr[j][0], bfr[j][1], bfr[j][2], bfr[j][3], sB + b_off[j] + co);
            }
            #pragma unroll
            for (int msub = 0; msub < 2; ++msub)
                #pragma unroll
                for (int j = 0; j < 2; ++j) {
                    MMAF16(acc[msub][2 * j],     a[msub], bfr[j][0], bfr[j][1]);
                    MMAF16(acc[msub][2 * j + 1], a[msub], bfr[j][2], bfr[j][3]);
                }
        }
    }
    CP_WAIT0();

    const int r = lane >> 2, cpair = (lane & 3) * 2;
    #pragma unroll
    for (int msub = 0; msub < 2; ++msub) {
        const int gm0 = mtile * 128 + warp_m * 32 + msub * 16 + r;
        #pragma unroll
        for (int j = 0; j < 4; ++j) {
            const int ln = warp_n * 32 + j * 8 + cpair;
            const int gn = ntile * 128 + ln;
            const float b0 = s_bias[ln], b1 = s_bias[ln + 1];
            float2 v0 = {acc[msub][j][0] + b0, acc[msub][j][1] + b1};
            float2 v1 = {acc[msub][j][2] + b0, acc[msub][j][3] + b1};
            *(float2*)&g_pc[(size_t)gm0 * C1 + gn] = v0;
            *(float2*)&g_pc[(size_t)(gm0 + 8) * C1 + gn] = v1;
        }
    }
}

// ---------------- squash: warp-per-row coalesced ----------------
__global__ void squash_u_kernel() {
    __shared__ float s[8][256];
    const int tid = threadIdx.x, w = tid >> 5, l = tid & 31;
    const int m = blockIdx.x * 8 + w;
    const float* row = g_pc + (size_t)m * C1;
    float4 r0 = ((const float4*)row)[l * 2];
    float4 r1 = ((const float4*)row)[l * 2 + 1];
    *(float4*)&s[w][l * 8]     = r0;
    *(float4*)&s[w][l * 8 + 4] = r1;
    __syncwarp();
    float v[PCD];
    float sq = 0.f;
    #pragma unroll
    for (int d = 0; d < PCD; ++d) {
        v[d] = s[w][d * 32 + l];
        sq += v[d] * v[d];
    }
    const float sc = sq / (1.f + sq) / sqrtf(sq + 1e-7f);
    const int b = m / 36, sp = m % 36;
    const int n = l * 36 + sp;
    float4 o0 = {v[0] * sc, v[1] * sc, v[2] * sc, v[3] * sc};
    float4 o1 = {v[4] * sc, v[5] * sc, v[6] * sc, v[7] * sc};
    float* dst = g_u + ((size_t)n * BATCH + b) * PCD;
    *(float4*)dst = o0;
    *(float4*)(dst + 4) = o1;
}

// ---------------- u_hat -> fp16 ----------------
__global__ void wu_kernel(const float* __restrict__ W) {
    __shared__ float s_u[64 * PCD];
    const int n = blockIdx.x;
    const int t = threadIdx.x;
    float wr[PCD];
    #pragma unroll
    for (int p = 0; p < PCD; ++p) wr[p] = W[n * (NC * DCD * PCD) + t * PCD + p];
    for (int b0 = 0; b0 < BATCH; b0 += 64) {
        __syncthreads();
        const uint4* src = (const uint4*)(g_u + ((size_t)n * BATCH + b0) * PCD);
        for (int i = t; i < 128; i += 160) ((uint4*)s_u)[i] = src[i];
        __syncthreads();
        for (int bb = 0; bb < 64; ++bb) {
            const float* up = &s_u[bb * PCD];
            float dot = 0.f;
            #pragma unroll
            for (int p = 0; p < PCD; ++p) dot += wr[p] * up[p];
            g_WUh[((size_t)((b0 + bb) * NPRIM + n)) * 160 + t] = __float2half_rn(dot);
        }
    }
}

// ---------------- dynamic routing: warp-per-n, 3 WU passes (fp16 WU) ----------------
#define ROUT_SMEM ((11520 + 1600 + 160 + 16) * 4)

__device__ __forceinline__ void rout_reduce_squash(
    float* s_red, float* s_v, float* s_scale, const float* acc,
    int tid, int w, int l, float cs) {
    #pragma unroll
    for (int j = 0; j < 5; ++j) s_red[w * 160 + 32 * j + l] = acc[j];
    __syncthreads();
    if (tid < 160) {
        float v = 0.f;
        #pragma unroll
        for (int ww = 0; ww < 10; ++ww) v += s_red[ww * 160 + tid];
        s_v[tid] = v * cs;
    }
    __syncthreads();
    if (tid < NC) {
        float sq = 0.f;
        #pragma unroll
        for (int d = 0; d < DCD; ++d) { float x = s_v[tid * DCD + d]; sq += x * x; }
        s_scale[tid] = sq / (1.f + sq) / sqrtf(sq + 1e-7f);
    }
    __syncthreads();
    if (tid < 160) s_v[tid] *= s_scale[tid >> 4];
    __syncthreads();
}

__global__ void routing_kernel(float* __restrict__ out) {
    extern __shared__ float smf[];
    float* s_b     = smf;
    float* s_red   = smf + 11520;
    float* s_v     = smf + 13120;
    float* s_scale = smf + 13280;
    const int b = blockIdx.x, tid = threadIdx.x;
    const int w = tid >> 5, l = tid & 31;
    const int myh = l >> 4;
    const size_t wub = (size_t)b * NPRIM * 160;
    const unsigned FULL = 0xffffffffu;
    float acc[5];

    #pragma unroll
    for (int j = 0; j < 5; ++j) acc[j] = 0.f;
    for (int n = w; n < NPRIM; n += 10) {
        const __half* row = g_WUh + wub + (size_t)n * 160;
        #pragma unroll
        for (int j = 0; j < 5; ++j) acc[j] += __half2float(row[l + 32 * j]);
    }
    rout_reduce_squash(s_red, s_v, s_scale, acc, tid, w, l, 0.1f);

    #pragma unroll
    for (int j = 0; j < 5; ++j) acc[j] = 0.f;
    for (int n = w; n < NPRIM; n += 10) {
        const __half* row = g_WUh + wub + (size_t)n * 160;
        float wv[5], t[5];
        #pragma unroll
        for (int j = 0; j < 5; ++j) wv[j] = __half2float(row[l + 32 * j]);
        #pragma unroll
        for (int j = 0; j < 5; ++j) t[j] = s_v[l + 32 * j] * wv[j];
        #pragma unroll
        for (int j = 0; j < 5; ++j) {
            t[j] += __shfl_xor_sync(FULL, t[j], 8);
            t[j] += __shfl_xor_sync(FULL, t[j], 4);
            t[j] += __shfl_xor_sync(FULL, t[j], 2);
            t[j] += __shfl_xor_sync(FULL, t[j], 1);
            t[j] *= 0.1f;
        }
        float o[5];
        #pragma unroll
        for (int j = 0; j < 5; ++j) o[j] = __shfl_xor_sync(FULL, t[j], 16);
        float selt = t[0], selo = o[0];
        #pragma unroll
        for (int jj = 1; jj < 5; ++jj) {
            bool p = ((l >> 1) == jj);
            selt = p ? t[jj] : selt;
            selo = p ? o[jj] : selo;
        }
        const float bv = (l & 1) ? selo : selt;
        if (l < NC) s_b[n * NC + l] = bv;
        float m = (l < NC) ? bv : -1e30f;
        m = fmaxf(m, __shfl_xor_sync(FULL, m, 16));
        m = fmaxf(m, __shfl_xor_sync(FULL, m, 8));
        m = fmaxf(m, __shfl_xor_sync(FULL, m, 4));
        m = fmaxf(m, __shfl_xor_sync(FULL, m, 2));
        m = fmaxf(m, __shfl_xor_sync(FULL, m, 1));
        float e = (l < NC) ? __expf(bv - m) : 0.f;
        float S = e;
        S += __shfl_xor_sync(FULL, S, 16);
        S += __shfl_xor_sync(FULL, S, 8);
        S += __shfl_xor_sync(FULL, S, 4);
        S += __shfl_xor_sync(FULL, S, 2);
        S += __shfl_xor_sync(FULL, S, 1);
        const float en = e / S;
        #pragma unroll
        for (int j = 0; j < 5; ++j) {
            float cf = __shfl_sync(FULL, en, 2 * j + myh);
            acc[j] += cf * wv[j];
        }
    }
    rout_reduce_squash(s_red, s_v, s_scale, acc, tid, w, l, 1.f);

    #pragma unroll
    for (int j = 0; j < 5; ++j) acc[j] = 0.f;
    for (int n = w; n < NPRIM; n += 10) {
        const __half* row = g_WUh + wub + (size_t)n * 160;
        float wv[5];
        #pragma unroll
        for (int j = 0; j < 5; ++j) wv[j] = __half2float(row[l + 32 * j]);
        const float bv1 = (l < NC) ? s_b[n * NC + l] : 0.f;
        float m1 = (l < NC) ? bv1 : -1e30f;
        m1 = fmaxf(m1, __shfl_xor_sync(FULL, m1, 16));
        m1 = fmaxf(m1, __shfl_xor_sync(FULL, m1, 8));
        m1 = fmaxf(m1, __shfl_xor_sync(FULL, m1, 4));
        m1 = fmaxf(m1, __shfl_xor_sync(FULL, m1, 2));
        m1 = fmaxf(m1, __shfl_xor_sync(FULL, m1, 1));
        float e1 = (l < NC) ? __expf(bv1 - m1) : 0.f;
        float S1 = e1;
        S1 += __shfl_xor_sync(FULL, S1, 16);
        S1 += __shfl_xor_sync(FULL, S1, 8);
        S1 += __shfl_xor_sync(FULL, S1, 4);
        S1 += __shfl_xor_sync(FULL, S1, 2);
        S1 += __shfl_xor_sync(FULL, S1, 1);
        const float en1 = e1 / S1;
        float t2[5];
        #pragma unroll
        for (int j = 0; j < 5; ++j) {
            float cf1 = __shfl_sync(FULL, en1, 2 * j + myh);
            t2[j] = s_v[l + 32 * j] * cf1 * wv[j];
            t2[j] += __shfl_xor_sync(FULL, t2[j], 8);
            t2[j] += __shfl_xor_sync(FULL, t2[j], 4);
            t2[j] += __shfl_xor_sync(FULL, t2[j], 2);
            t2[j] += __shfl_xor_sync(FULL, t2[j], 1);
        }
        float o2[5];
        #pragma unroll
        for (int j = 0; j < 5; ++j) o2[j] = __shfl_xor_sync(FULL, t2[j], 16);
        float selt = t2[0], selo = o2[0];
        #pragma unroll
        for (int jj = 1; jj < 5; ++jj) {
            bool p = ((l >> 1) == jj);
            selt = p ? t2[jj] : selt;
            selo = p ? o2[jj] : selo;
        }
        const float b2v = bv1 + ((l & 1) ? selo : selt);
        float m2 = (l < NC) ? b2v : -1e30f;
        m2 = fmaxf(m2, __shfl_xor_sync(FULL, m2, 16));
        m2 = fmaxf(m2, __shfl_xor_sync(FULL, m2, 8));
        m2 = fmaxf(m2, __shfl_xor_sync(FULL, m2, 4));
        m2 = fmaxf(m2, __shfl_xor_sync(FULL, m2, 2));
        m2 = fmaxf(m2, __shfl_xor_sync(FULL, m2, 1));
        float e2 = (l < NC) ? __expf(b2v - m2) : 0.f;
        float S2 = e2;
        S2 += __shfl_xor_sync(FULL, S2, 16);
        S2 += __shfl_xor_sync(FULL, S2, 8);
        S2 += __shfl_xor_sync(FULL, S2, 4);
        S2 += __shfl_xor_sync(FULL, S2, 2);
        S2 += __shfl_xor_sync(FULL, S2, 1);
        const float en2 = e2 / S2;
        #pragma unroll
        for (int j = 0; j < 5; ++j) {
            float cf2 = __shfl_sync(FULL, en2, 2 * j + myh);
            acc[j] += cf2 * wv[j];
        }
    }
    rout_reduce_squash(s_red, s_v, s_scale, acc, tid, w, l, 1.f);

    if (tid < 160) g_v[b * 160 + tid] = s_v[tid];
    if (tid < NC) {
        float sq = 0.f;
        #pragma unroll
        for (int d = 0; d < DCD; ++d) { float x = s_v[tid * DCD + d]; sq += x * x; }
        out[b * NC + tid] = sqrtf(sq);
    }
}

// ---------------- masked decoder: 4 images per block, fp16 weights ----------------
__global__ void decoder_kernel(const int* __restrict__ labels,
                               const float* __restrict__ w1, const float* __restrict__ bb1,
                               const float* __restrict__ bb2,
                               const float* __restrict__ bb3,
                               float* __restrict__ out) {
    __shared__ float h0[4][DCD];
    __shared__ float h1[4][512];
    __shared__ float h2[4][1024];
    __shared__ int   lab[4];
    const int t = threadIdx.x;
    const int b0 = blockIdx.x * 4;
    if (t < 4) lab[t] = labels[b0 + t];
    __syncthreads();
    if (t < 64) {
        int i = t >> 4, d = t & 15;
        h0[i][d] = g_v[(b0 + i) * 160 + lab[i] * DCD + d];
    }
    __syncthreads();
    for (int j = t; j < 512; j += 256) {
        float a[4];
        #pragma unroll
        for (int i = 0; i < 4; ++i) a[i] = bb1[j];
        #pragma unroll
        for (int k = 0; k < DCD; ++k) {
            #pragma unroll
            for (int i = 0; i < 4; ++i)
                a[i] += h0[i][k] * w1[(lab[i] * DCD + k) * 512 + j];
        }
        #pragma unroll
        for (int i = 0; i < 4; ++i) h1[i][j] = fmaxf(a[i], 0.f);
    }
    __syncthreads();
    for (int j = t; j < 1024; j += 256) {
        float a[4];
        #pragma unroll
        for (int i = 0; i < 4; ++i) a[i] = bb2[j];
        for (int k = 0; k < 512; ++k) {
            float wv = __half2float(g_w2h[k * 1024 + j]);
            #pragma unroll
            for (int i = 0; i < 4; ++i) a[i] += h1[i][k] * wv;
        }
        #pragma unroll
        for (int i = 0; i < 4; ++i) h2[i][j] = fmaxf(a[i], 0.f);
    }
    __syncthreads();
    for (int j = t; j < 784; j += 256) {
        float a[4];
        #pragma unroll
        for (int i = 0; i < 4; ++i) a[i] = bb3[j];
        for (int k = 0; k < 1024; ++k) {
            float wv = __half2float(g_w3h[k * 784 + j]);
            #pragma unroll
            for (int i = 0; i < 4; ++i) a[i] += h2[i][k] * wv;
        }
        #pragma unroll
        for (int i = 0; i < 4; ++i)
            out[BATCH * NC + (b0 + i) * 784 + j] = 1.f / (1.f + __expf(-a[i]));
    }
}

// ---------------- launch ----------------
extern "C" void kernel_launch(void* const* d_in, const int* in_sizes, int n_in,
                              void* d_out, int out_size) {
    const float* inputs  = (const float*)d_in[0];
    const int*   labels  = (const int*)d_in[1];
    const float* conv1_w = (const float*)d_in[2];
    const float* conv1_b = (const float*)d_in[3];
    const float* pc_w    = (const float*)d_in[4];
    const float* pc_b    = (const float*)d_in[5];
    const float* rw      = (const float*)d_in[6];
    const float* dw1     = (const float*)d_in[7];
    const float* db1     = (const float*)d_in[8];
    const float* dw2     = (const float*)d_in[9];
    const float* db2     = (const float*)d_in[10];
    const float* dw3     = (const float*)d_in[11];
    const float* db3     = (const float*)d_in[12];
    float* out = (float*)d_out;

    convert_w_kernel<<<C1, 256>>>(pc_w);
    convert_dec_kernel<<<(1024 * 784 + 255) / 256, 256>>>(dw2, dw3);
    conv1_kernel<<<dim3(4, BATCH), 256>>>(inputs, conv1_w, conv1_b);

    cudaFuncSetAttribute(gemm_kernel, cudaFuncAttributeMaxDynamicSharedMemorySize, GEMM_SMEM);
    gemm_kernel<<<dim3(72, 2), 512, GEMM_SMEM>>>(pc_b);

    squash_u_kernel<<<NPRIM, 256>>>();
    wu_kernel<<<NPRIM, 160>>>(rw);

    cudaFuncSetAttribute(routing_kernel, cudaFuncAttributeMaxDynamicSharedMemorySize, ROUT_SMEM);
    routing_kernel<<<BATCH, 320, ROUT_SMEM>>>(out);

    decoder_kernel<<<BATCH / 4, 256>>>(labels, dw1, db1, db2, db3, out);
}

// round 12
// speedup vs baseline: 8.9153x; 1.3019x over previous
#include <cuda_runtime.h>
#include <cuda_fp16.h>
#include <math.h>
#include <stdint.h>

#define BATCH 256
#define C1 256
#define IMGD 28
#define NPRIM 1152
#define NC 10
#define PCD 8
#define DCD 16
#define KTOT 20736           // 81 r * 256 ic  (k = r*256 + ic)
#define MTOT 9216            // 256 b * 36 sp
#define NKT (KTOT / 64)      // 324

// ---------------- scratch ----------------
__device__ __align__(16) __half g_xh[(size_t)BATCH * 400 * C1];  // conv1 out fp16 [b][px][ic]
__device__ __align__(16) __half g_Bh[(size_t)C1 * KTOT];         // pc_w fp16 [oc][k]
__device__ __align__(16) __half g_c1w[256 * 128];                // conv1_w fp16 [oc][k pad 128]
__device__ float g_pc[(size_t)MTOT * C1];                        // pc conv out [m][oc]
__device__ float g_u[BATCH * NPRIM * PCD];                       // squashed, [n][b][p]
__device__ __align__(16) __half g_WUh[(size_t)BATCH * NPRIM * NC * DCD];  // u_hat fp16
__device__ float g_v[BATCH * NC * DCD];
__device__ __align__(16) __half g_w2h[512 * 1024];
__device__ __align__(16) __half g_w3h[1024 * 784];

__device__ __forceinline__ uint32_t smem_u32(const void* p) {
    uint32_t a;
    asm("{ .reg .u64 t; cvta.to.shared.u64 t, %1; cvt.u32.u64 %0, t; }" : "=r"(a) : "l"(p));
    return a;
}
#define CP_ASYNC16(sa, ga) \
    asm volatile("cp.async.cg.shared.global [%0], [%1], 16;" :: "r"(sa), "l"(ga))
#define CP_COMMIT() asm volatile("cp.async.commit_group;" ::: "memory")
#define CP_WAIT2()  asm volatile("cp.async.wait_group 2;" ::: "memory")
#define CP_WAIT0()  asm volatile("cp.async.wait_group 0;" ::: "memory")
#define LDMX4(r0, r1, r2, r3, a) \
    asm volatile("ldmatrix.sync.aligned.m8n8.x4.shared.b16 {%0,%1,%2,%3}, [%4];" \
        : "=r"(r0), "=r"(r1), "=r"(r2), "=r"(r3) : "r"(a))
#define MMAF16(c, a, b0, b1) \
    asm volatile("mma.sync.aligned.m16n8k16.row.col.f32.f16.f16.f32 " \
        "{%0,%1,%2,%3},{%4,%5,%6,%7},{%8,%9},{%0,%1,%2,%3};" \
        : "+f"((c)[0]), "+f"((c)[1]), "+f"((c)[2]), "+f"((c)[3]) \
        : "r"((a)[0]), "r"((a)[1]), "r"((a)[2]), "r"((a)[3]), "r"(b0), "r"(b1))

// ---------------- conv1_w -> fp16, [oc][128] zero-padded ----------------
__global__ void convert_c1w_kernel(const float* __restrict__ w) {
    const int oc = blockIdx.x, k = threadIdx.x;   // 128 threads
    g_c1w[oc * 128 + k] = (k < 81) ? __float2half_rn(w[oc * 81 + k]) : __half(0);
}

// ---------------- conv1 as implicit GEMM: M=102400, N=256, K=81->128 ----------------
// grid (800 mtile, 2 ntile), 512 threads, 4x4 warps, warp tile 32x32
#define C1_SMEM (8192 + 65536)

__global__ void __launch_bounds__(512, 2) conv1_gemm_kernel(const float* __restrict__ in,
                                                            const float* __restrict__ bias) {
    extern __shared__ char sm[];
    float* s_bias = (float*)sm;
    float* s_img = (float*)(sm + 1024);            // 2 x 784 floats
    const uint32_t smb = smem_u32(sm);
    const int tid = threadIdx.x, lane = tid & 31, wid = tid >> 5;
    const int mtile = blockIdx.x, ntile = blockIdx.y;
    if (tid < 128) s_bias[tid] = bias[ntile * 128 + tid];

    const int m0 = mtile * 128;
    const int b0 = m0 / 400;
    const int b1 = (b0 + 1 < BATCH) ? b0 + 1 : b0;

    // B tile: 128 oc x 128 k fp16, 2 k-chunks, swizzled cp.async
    #pragma unroll
    for (int i = 0; i < 4; ++i) {
        const int lin = tid + i * 512;             // 0..2047
        const int row = lin >> 4, c16 = lin & 15;
        const int kc = c16 >> 3, ch = c16 & 7;
        const uint32_t dst = smb + 8192 + kc * 32768 + 16384
                           + row * 128 + ((ch ^ (row & 7)) << 4);
        const size_t src = (size_t)(ntile * 128 + row) * 256 + kc * 128 + ch * 16;
        CP_ASYNC16(dst, (const char*)g_c1w + src);
    }
    CP_COMMIT();

    // load source images
    for (int i = tid; i < 2 * 784; i += 512) {
        const int im = (i >= 784);
        s_img[i] = in[(im ? b1 : b0) * 784 + (i - im * 784)];
    }
    __syncthreads();

    // A tile: im2col on the fly (row = output pixel, col = tap k), zero pad k>=81
    {
        const int row = tid >> 2;                  // 0..127
        const int cb = (tid & 3) * 32;             // col base
        const int m = m0 + row;
        const int bb = m / 400, px = m - bb * 400;
        const int ibase = ((bb == b0) ? 0 : 784) + (px / 20) * 28 + (px % 20);
        #pragma unroll
        for (int p = 0; p < 16; ++p) {
            const int k0 = cb + 2 * p;
            float v0 = 0.f, v1 = 0.f;
            if (k0 < 81) {
                int ky = (k0 * 57) >> 9, kx = k0 - ky * 9;
                v0 = s_img[ibase + ky * 28 + kx];
            }
            if (k0 + 1 < 81) {
                int ky = ((k0 + 1) * 57) >> 9, kx = k0 + 1 - ky * 9;
                v1 = s_img[ibase + ky * 28 + kx];
            }
            const int within = k0 & 63;
            const int off = 8192 + (k0 >> 6) * 32768 + row * 128
                          + (((within >> 3) ^ (row & 7)) << 4) + (within & 7) * 2;
            *(__half2*)(sm + off) = __floats2half2_rn(v0, v1);
        }
    }
    CP_WAIT0();
    __syncthreads();

    const int warp_m = wid >> 2, warp_n = wid & 3;
    int a_off[2], a_sw[2];
    #pragma unroll
    for (int sub = 0; sub < 2; ++sub) {
        int row = warp_m * 32 + sub * 16 + (lane & 15);
        a_off[sub] = row * 128; a_sw[sub] = row & 7;
    }
    const int a_cb = lane >> 4;
    int b_off[2], b_sw[2];
    #pragma unroll
    for (int j = 0; j < 2; ++j) {
        int row = warp_n * 32 + j * 16 + ((lane >> 4) << 3) + (lane & 7);
        b_off[j] = row * 128; b_sw[j] = row & 7;
    }
    const int b_cb = (lane >> 3) & 1;

    float acc[2][4][4];
    #pragma unroll
    for (int m = 0; m < 2; ++m)
        #pragma unroll
        for (int j = 0; j < 4; ++j)
            #pragma unroll
            for (int q = 0; q < 4; ++q) acc[m][j][q] = 0.f;

    #pragma unroll
    for (int t = 0; t < 2; ++t) {
        const uint32_t sA = smb + 8192 + t * 32768;
        const uint32_t sB = sA + 16384;
        #pragma unroll
        for (int ks = 0; ks < 4; ++ks) {
            uint32_t a[2][4], bfr[2][4];
            #pragma unroll
            for (int sub = 0; sub < 2; ++sub) {
                uint32_t co = ((((ks << 1) + a_cb) ^ a_sw[sub]) << 4);
                LDMX4(a[sub][0], a[sub][1], a[sub][2], a[sub][3], sA + a_off[sub] + co);
            }
            #pragma unroll
            for (int j = 0; j < 2; ++j) {
                uint32_t co = ((((ks << 1) + b_cb) ^ b_sw[j]) << 4);
                LDMX4(bfr[j][0], bfr[j][1], bfr[j][2], bfr[j][3], sB + b_off[j] + co);
            }
            #pragma unroll
            for (int msub = 0; msub < 2; ++msub)
                #pragma unroll
                for (int j = 0; j < 2; ++j) {
                    MMAF16(acc[msub][2 * j],     a[msub], bfr[j][0], bfr[j][1]);
                    MMAF16(acc[msub][2 * j + 1], a[msub], bfr[j][2], bfr[j][3]);
                }
        }
    }

    // epilogue: relu(x + bias) -> fp16 g_xh[m][oc]
    const int r = lane >> 2, cpair = (lane & 3) * 2;
    #pragma unroll
    for (int msub = 0; msub < 2; ++msub) {
        const int gm0 = m0 + warp_m * 32 + msub * 16 + r;
        #pragma unroll
        for (int j = 0; j < 4; ++j) {
            const int ln = warp_n * 32 + j * 8 + cpair;
            const int gn = ntile * 128 + ln;
            const float bb0 = s_bias[ln], bb1 = s_bias[ln + 1];
            __half2 v0 = __floats2half2_rn(fmaxf(acc[msub][j][0] + bb0, 0.f),
                                           fmaxf(acc[msub][j][1] + bb1, 0.f));
            __half2 v1 = __floats2half2_rn(fmaxf(acc[msub][j][2] + bb0, 0.f),
                                           fmaxf(acc[msub][j][3] + bb1, 0.f));
            *(__half2*)&g_xh[(size_t)gm0 * C1 + gn] = v0;
            *(__half2*)&g_xh[(size_t)(gm0 + 8) * C1 + gn] = v1;
        }
    }
}

// ---------------- pc_w -> fp16, k = r*256 + ic ----------------
__global__ void convert_w_kernel(const float* __restrict__ w) {
    const int oc = blockIdx.x, ic = threadIdx.x;
    const float* src = w + (size_t)oc * KTOT + (size_t)ic * 81;
    __half* dh = g_Bh + (size_t)oc * KTOT + ic;
    #pragma unroll 9
    for (int r = 0; r < 81; ++r) dh[r * 256] = __float2half_rn(src[r]);
}

// ---------------- decoder w2/w3 -> fp16 ----------------
__global__ void convert_dec_kernel(const float* __restrict__ w2,
                                   const float* __restrict__ w3) {
    const int i = blockIdx.x * 256 + threadIdx.x;
    if (i < 512 * 1024) g_w2h[i] = __float2half_rn(w2[i]);
    if (i < 1024 * 784) g_w3h[i] = __float2half_rn(w3[i]);
}

// ---------------- implicit fp16 GEMM: 128x128 tile, 512 threads, 4-stage ----------------
#define STG 32768
#define GEMM_SMEM (1024 + 4 * STG)

__global__ void __launch_bounds__(512, 1) gemm_kernel(const float* __restrict__ bias) {
    extern __shared__ char sm[];
    float* s_bias = (float*)sm;
    const uint32_t smb = smem_u32(sm);
    const int tid = threadIdx.x, lane = tid & 31, wid = tid >> 5;
    const int mtile = blockIdx.x, ntile = blockIdx.y;
    if (tid < 128) s_bias[tid] = bias[ntile * 128 + tid];

    const char* Bh = (const char*)g_Bh + (size_t)ntile * 128 * (KTOT * 2);

    int abase[2], aso2[2];
    #pragma unroll
    for (int i = 0; i < 2; ++i) {
        const int lin = tid + i * 512;
        const int ar = lin >> 3, ch = lin & 7;
        const int m = mtile * 128 + ar;
        const int bb = m / 36, sp = m - bb * 36;
        const int pbase = (2 * (sp / 6)) * 20 + 2 * (sp % 6);
        abase[i] = ((bb * 400 + pbase) << 8) + ch * 8;
        aso2[i] = ar * 128 + ((ch ^ (ar & 7)) << 4);
    }
    int brow[2], bso[2], bch[2];
    #pragma unroll
    for (int i = 0; i < 2; ++i) {
        int lin = tid + i * 512;
        brow[i] = lin >> 3; bch[i] = lin & 7;
        bso[i] = brow[i] * 128 + ((bch[i] ^ (brow[i] & 7)) << 4);
    }

    const int warp_m = wid >> 2, warp_n = wid & 3;
    int a_off[2], a_sw[2];
    #pragma unroll
    for (int sub = 0; sub < 2; ++sub) {
        int row = warp_m * 32 + sub * 16 + (lane & 15);
        a_off[sub] = row * 128; a_sw[sub] = row & 7;
    }
    const int a_cb = lane >> 4;
    int b_off[2], b_sw[2];
    #pragma unroll
    for (int j = 0; j < 2; ++j) {
        int row = warp_n * 32 + j * 16 + ((lane >> 4) << 3) + (lane & 7);
        b_off[j] = row * 128; b_sw[j] = row & 7;
    }
    const int b_cb = (lane >> 3) & 1;

    float acc[2][4][4];
    #pragma unroll
    for (int m = 0; m < 2; ++m)
        #pragma unroll
        for (int j = 0; j < 4; ++j)
            #pragma unroll
            for (int q = 0; q < 4; ++q) acc[m][j][q] = 0.f;

    auto issue = [&](int kk, int buf) {
        const uint32_t sA = smb + 1024 + buf * STG;
        const uint32_t sB = sA + 16384;
        const int r = kk >> 2, icq = kk & 3;
        const int dy = (r * 57) >> 9;
        const int poff = ((dy * 20 + (r - dy * 9)) << 8) + (icq << 6);
        #pragma unroll
        for (int i = 0; i < 2; ++i) {
            const size_t e = (size_t)(abase[i] + poff) * 2;
            CP_ASYNC16(sA + aso2[i], (const char*)g_xh + e);
        }
        const size_t kbyte = (size_t)kk * 128;
        #pragma unroll
        for (int i = 0; i < 2; ++i) {
            const size_t go = (size_t)brow[i] * (KTOT * 2) + kbyte + bch[i] * 16;
            CP_ASYNC16(sB + bso[i], Bh + go);
        }
        CP_COMMIT();
    };

    issue(0, 0); issue(1, 1); issue(2, 2);

    for (int t = 0; t < NKT; ++t) {
        CP_WAIT2();
        __syncthreads();
        if (t + 3 < NKT) issue(t + 3, (t + 3) & 3);
        else CP_COMMIT();
        const uint32_t sA = smb + 1024 + (t & 3) * STG;
        const uint32_t sB = sA + 16384;
        #pragma unroll
        for (int ks = 0; ks < 4; ++ks) {
            uint32_t a[2][4], bfr[2][4];
            #pragma unroll
            for (int sub = 0; sub < 2; ++sub) {
                uint32_t co = ((((ks << 1) + a_cb) ^ a_sw[sub]) << 4);
                LDMX4(a[sub][0], a[sub][1], a[sub][2], a[sub][3], sA + a_off[sub] + co);
            }
            #pragma unroll
            for (int j = 0; j < 2; ++j) {
                uint32_t co = ((((ks << 1) + b_cb) ^ b_sw[j]) << 4);
                LDMX4(bfr[j][0], bfr[j][1], bfr[j][2], bfr[j][3], sB + b_off[j] + co);
            }
            #pragma unroll
            for (int msub = 0; msub < 2; ++msub)
                #pragma unroll
                for (int j = 0; j < 2; ++j) {
                    MMAF16(acc[msub][2 * j],     a[msub], bfr[j][0], bfr[j][1]);
                    MMAF16(acc[msub][2 * j + 1], a[msub], bfr[j][2], bfr[j][3]);
                }
        }
    }
    CP_WAIT0();

    const int r = lane >> 2, cpair = (lane & 3) * 2;
    #pragma unroll
    for (int msub = 0; msub < 2; ++msub) {
        const int gm0 = mtile * 128 + warp_m * 32 + msub * 16 + r;
        #pragma unroll
        for (int j = 0; j < 4; ++j) {
            const int ln = warp_n * 32 + j * 8 + cpair;
            const int gn = ntile * 128 + ln;
            const float b0 = s_bias[ln], b1 = s_bias[ln + 1];
            float2 v0 = {acc[msub][j][0] + b0, acc[msub][j][1] + b1};
            float2 v1 = {acc[msub][j][2] + b0, acc[msub][j][3] + b1};
            *(float2*)&g_pc[(size_t)gm0 * C1 + gn] = v0;
            *(float2*)&g_pc[(size_t)(gm0 + 8) * C1 + gn] = v1;
        }
    }
}

// ---------------- squash: warp-per-row coalesced ----------------
__global__ void squash_u_kernel() {
    __shared__ float s[8][256];
    const int tid = threadIdx.x, w = tid >> 5, l = tid & 31;
    const int m = blockIdx.x * 8 + w;
    const float* row = g_pc + (size_t)m * C1;
    float4 r0 = ((const float4*)row)[l * 2];
    float4 r1 = ((const float4*)row)[l * 2 + 1];
    *(float4*)&s[w][l * 8]     = r0;
    *(float4*)&s[w][l * 8 + 4] = r1;
    __syncwarp();
    float v[PCD];
    float sq = 0.f;
    #pragma unroll
    for (int d = 0; d < PCD; ++d) {
        v[d] = s[w][d * 32 + l];
        sq += v[d] * v[d];
    }
    const float sc = sq / (1.f + sq) / sqrtf(sq + 1e-7f);
    const int b = m / 36, sp = m % 36;
    const int n = l * 36 + sp;
    float4 o0 = {v[0] * sc, v[1] * sc, v[2] * sc, v[3] * sc};
    float4 o1 = {v[4] * sc, v[5] * sc, v[6] * sc, v[7] * sc};
    float* dst = g_u + ((size_t)n * BATCH + b) * PCD;
    *(float4*)dst = o0;
    *(float4*)(dst + 4) = o1;
}

// ---------------- u_hat -> fp16 ----------------
__global__ void wu_kernel(const float* __restrict__ W) {
    __shared__ float s_u[64 * PCD];
    const int n = blockIdx.x;
    const int t = threadIdx.x;
    float wr[PCD];
    #pragma unroll
    for (int p = 0; p < PCD; ++p) wr[p] = W[n * (NC * DCD * PCD) + t * PCD + p];
    for (int b0 = 0; b0 < BATCH; b0 += 64) {
        __syncthreads();
        const uint4* src = (const uint4*)(g_u + ((size_t)n * BATCH + b0) * PCD);
        for (int i = t; i < 128; i += 160) ((uint4*)s_u)[i] = src[i];
        __syncthreads();
        for (int bb = 0; bb < 64; ++bb) {
            const float* up = &s_u[bb * PCD];
            float dot = 0.f;
            #pragma unroll
            for (int p = 0; p < PCD; ++p) dot += wr[p] * up[p];
            g_WUh[((size_t)((b0 + bb) * NPRIM + n)) * 160 + t] = __float2half_rn(dot);
        }
    }
}

// ---------------- dynamic routing: warp-per-n, 3 WU passes (fp16 WU) ----------------
#define ROUT_SMEM ((11520 + 1600 + 160 + 16) * 4)

__device__ __forceinline__ void rout_reduce_squash(
    float* s_red, float* s_v, float* s_scale, const float* acc,
    int tid, int w, int l, float cs) {
    #pragma unroll
    for (int j = 0; j < 5; ++j) s_red[w * 160 + 32 * j + l] = acc[j];
    __syncthreads();
    if (tid < 160) {
        float v = 0.f;
        #pragma unroll
        for (int ww = 0; ww < 10; ++ww) v += s_red[ww * 160 + tid];
        s_v[tid] = v * cs;
    }
    __syncthreads();
    if (tid < NC) {
        float sq = 0.f;
        #pragma unroll
        for (int d = 0; d < DCD; ++d) { float x = s_v[tid * DCD + d]; sq += x * x; }
        s_scale[tid] = sq / (1.f + sq) / sqrtf(sq + 1e-7f);
    }
    __syncthreads();
    if (tid < 160) s_v[tid] *= s_scale[tid >> 4];
    __syncthreads();
}

__global__ void routing_kernel(float* __restrict__ out) {
    extern __shared__ float smf[];
    float* s_b     = smf;
    float* s_red   = smf + 11520;
    float* s_v     = smf + 13120;
    float* s_scale = smf + 13280;
    const int b = blockIdx.x, tid = threadIdx.x;
    const int w = tid >> 5, l = tid & 31;
    const int myh = l >> 4;
    const size_t wub = (size_t)b * NPRIM * 160;
    const unsigned FULL = 0xffffffffu;
    float acc[5];

    #pragma unroll
    for (int j = 0; j < 5; ++j) acc[j] = 0.f;
    for (int n = w; n < NPRIM; n += 10) {
        const __half* row = g_WUh + wub + (size_t)n * 160;
        #pragma unroll
        for (int j = 0; j < 5; ++j) acc[j] += __half2float(row[l + 32 * j]);
    }
    rout_reduce_squash(s_red, s_v, s_scale, acc, tid, w, l, 0.1f);

    #pragma unroll
    for (int j = 0; j < 5; ++j) acc[j] = 0.f;
    for (int n = w; n < NPRIM; n += 10) {
        const __half* row = g_WUh + wub + (size_t)n * 160;
        float wv[5], t[5];
        #pragma unroll
        for (int j = 0; j < 5; ++j) wv[j] = __half2float(row[l + 32 * j]);
        #pragma unroll
        for (int j = 0; j < 5; ++j) t[j] = s_v[l + 32 * j] * wv[j];
        #pragma unroll
        for (int j = 0; j < 5; ++j) {
            t[j] += __shfl_xor_sync(FULL, t[j], 8);
            t[j] += __shfl_xor_sync(FULL, t[j], 4);
            t[j] += __shfl_xor_sync(FULL, t[j], 2);
            t[j] += __shfl_xor_sync(FULL, t[j], 1);
            t[j] *= 0.1f;
        }
        float o[5];
        #pragma unroll
        for (int j = 0; j < 5; ++j) o[j] = __shfl_xor_sync(FULL, t[j], 16);
        float selt = t[0], selo = o[0];
        #pragma unroll
        for (int jj = 1; jj < 5; ++jj) {
            bool p = ((l >> 1) == jj);
            selt = p ? t[jj] : selt;
            selo = p ? o[jj] : selo;
        }
        const float bv = (l & 1) ? selo : selt;
        if (l < NC) s_b[n * NC + l] = bv;
        float m = (l < NC) ? bv : -1e30f;
        m = fmaxf(m, __shfl_xor_sync(FULL, m, 16));
        m = fmaxf(m, __shfl_xor_sync(FULL, m, 8));
        m = fmaxf(m, __shfl_xor_sync(FULL, m, 4));
        m = fmaxf(m, __shfl_xor_sync(FULL, m, 2));
        m = fmaxf(m, __shfl_xor_sync(FULL, m, 1));
        float e = (l < NC) ? __expf(bv - m) : 0.f;
        float S = e;
        S += __shfl_xor_sync(FULL, S, 16);
        S += __shfl_xor_sync(FULL, S, 8);
        S += __shfl_xor_sync(FULL, S, 4);
        S += __shfl_xor_sync(FULL, S, 2);
        S += __shfl_xor_sync(FULL, S, 1);
        const float en = e / S;
        #pragma unroll
        for (int j = 0; j < 5; ++j) {
            float cf = __shfl_sync(FULL, en, 2 * j + myh);
            acc[j] += cf * wv[j];
        }
    }
    rout_reduce_squash(s_red, s_v, s_scale, acc, tid, w, l, 1.f);

    #pragma unroll
    for (int j = 0; j < 5; ++j) acc[j] = 0.f;
    for (int n = w; n < NPRIM; n += 10) {
        const __half* row = g_WUh + wub + (size_t)n * 160;
        float wv[5];
        #pragma unroll
        for (int j = 0; j < 5; ++j) wv[j] = __half2float(row[l + 32 * j]);
        const float bv1 = (l < NC) ? s_b[n * NC + l] : 0.f;
        float m1 = (l < NC) ? bv1 : -1e30f;
        m1 = fmaxf(m1, __shfl_xor_sync(FULL, m1, 16));
        m1 = fmaxf(m1, __shfl_xor_sync(FULL, m1, 8));
        m1 = fmaxf(m1, __shfl_xor_sync(FULL, m1, 4));
        m1 = fmaxf(m1, __shfl_xor_sync(FULL, m1, 2));
        m1 = fmaxf(m1, __shfl_xor_sync(FULL, m1, 1));
        float e1 = (l < NC) ? __expf(bv1 - m1) : 0.f;
        float S1 = e1;
        S1 += __shfl_xor_sync(FULL, S1, 16);
        S1 += __shfl_xor_sync(FULL, S1, 8);
        S1 += __shfl_xor_sync(FULL, S1, 4);
        S1 += __shfl_xor_sync(FULL, S1, 2);
        S1 += __shfl_xor_sync(FULL, S1, 1);
        const float en1 = e1 / S1;
        float t2[5];
        #pragma unroll
        for (int j = 0; j < 5; ++j) {
            float cf1 = __shfl_sync(FULL, en1, 2 * j + myh);
            t2[j] = s_v[l + 32 * j] * cf1 * wv[j];
            t2[j] += __shfl_xor_sync(FULL, t2[j], 8);
            t2[j] += __shfl_xor_sync(FULL, t2[j], 4);
            t2[j] += __shfl_xor_sync(FULL, t2[j], 2);
            t2[j] += __shfl_xor_sync(FULL, t2[j], 1);
        }
        float o2[5];
        #pragma unroll
        for (int j = 0; j < 5; ++j) o2[j] = __shfl_xor_sync(FULL, t2[j], 16);
        float selt = t2[0], selo = o2[0];
        #pragma unroll
        for (int jj = 1; jj < 5; ++jj) {
            bool p = ((l >> 1) == jj);
            selt = p ? t2[jj] : selt;
            selo = p ? o2[jj] : selo;
        }
        const float b2v = bv1 + ((l & 1) ? selo : selt);
        float m2 = (l < NC) ? b2v : -1e30f;
        m2 = fmaxf(m2, __shfl_xor_sync(FULL, m2, 16));
        m2 = fmaxf(m2, __shfl_xor_sync(FULL, m2, 8));
        m2 = fmaxf(m2, __shfl_xor_sync(FULL, m2, 4));
        m2 = fmaxf(m2, __shfl_xor_sync(FULL, m2, 2));
        m2 = fmaxf(m2, __shfl_xor_sync(FULL, m2, 1));
        float e2 = (l < NC) ? __expf(b2v - m2) : 0.f;
        float S2 = e2;
        S2 += __shfl_xor_sync(FULL, S2, 16);
        S2 += __shfl_xor_sync(FULL, S2, 8);
        S2 += __shfl_xor_sync(FULL, S2, 4);
        S2 += __shfl_xor_sync(FULL, S2, 2);
        S2 += __shfl_xor_sync(FULL, S2, 1);
        const float en2 = e2 / S2;
        #pragma unroll
        for (int j = 0; j < 5; ++j) {
            float cf2 = __shfl_sync(FULL, en2, 2 * j + myh);
            acc[j] += cf2 * wv[j];
        }
    }
    rout_reduce_squash(s_red, s_v, s_scale, acc, tid, w, l, 1.f);

    if (tid < 160) g_v[b * 160 + tid] = s_v[tid];
    if (tid < NC) {
        float sq = 0.f;
        #pragma unroll
        for (int d = 0; d < DCD; ++d) { float x = s_v[tid * DCD + d]; sq += x * x; }
        out[b * NC + tid] = sqrtf(sq);
    }
}

// ---------------- masked decoder: 2 images per block, fp16 weights ----------------
__global__ void decoder_kernel(const int* __restrict__ labels,
                               const float* __restrict__ w1, const float* __restrict__ bb1,
                               const float* __restrict__ bb2,
                               const float* __restrict__ bb3,
                               float* __restrict__ out) {
    __shared__ float h0[2][DCD];
    __shared__ float h1[2][512];
    __shared__ float h2[2][1024];
    __shared__ int   lab[2];
    const int t = threadIdx.x;
    const int b0 = blockIdx.x * 2;
    if (t < 2) lab[t] = labels[b0 + t];
    __syncthreads();
    if (t < 32) {
        int i = t >> 4, d = t & 15;
        h0[i][d] = g_v[(b0 + i) * 160 + lab[i] * DCD + d];
    }
    __syncthreads();
    for (int j = t; j < 512; j += 256) {
        float a[2];
        #pragma unroll
        for (int i = 0; i < 2; ++i) a[i] = bb1[j];
        #pragma unroll
        for (int k = 0; k < DCD; ++k) {
            #pragma unroll
            for (int i = 0; i < 2; ++i)
                a[i] += h0[i][k] * w1[(lab[i] * DCD + k) * 512 + j];
        }
        #pragma unroll
        for (int i = 0; i < 2; ++i) h1[i][j] = fmaxf(a[i], 0.f);
    }
    __syncthreads();
    for (int j = t; j < 1024; j += 256) {
        float a[2];
        #pragma unroll
        for (int i = 0; i < 2; ++i) a[i] = bb2[j];
        for (int k = 0; k < 512; ++k) {
            float wv = __half2float(g_w2h[k * 1024 + j]);
            #pragma unroll
            for (int i = 0; i < 2; ++i) a[i] += h1[i][k] * wv;
        }
        #pragma unroll
        for (int i = 0; i < 2; ++i) h2[i][j] = fmaxf(a[i], 0.f);
    }
    __syncthreads();
    for (int j = t; j < 784; j += 256) {
        float a[2];
        #pragma unroll
        for (int i = 0; i < 2; ++i) a[i] = bb3[j];
        for (int k = 0; k < 1024; ++k) {
            float wv = __half2float(g_w3h[k * 784 + j]);
            #pragma unroll
            for (int i = 0; i < 2; ++i) a[i] += h2[i][k] * wv;
        }
        #pragma unroll
        for (int i = 0; i < 2; ++i)
            out[BATCH * NC + (b0 + i) * 784 + j] = 1.f / (1.f + __expf(-a[i]));
    }
}

// ---------------- launch ----------------
extern "C" void kernel_launch(void* const* d_in, const int* in_sizes, int n_in,
                              void* d_out, int out_size) {
    const float* inputs  = (const float*)d_in[0];
    const int*   labels  = (const int*)d_in[1];
    const float* conv1_w = (const float*)d_in[2];
    const float* conv1_b = (const float*)d_in[3];
    const float* pc_w    = (const float*)d_in[4];
    const float* pc_b    = (const float*)d_in[5];
    const float* rw      = (const float*)d_in[6];
    const float* dw1     = (const float*)d_in[7];
    const float* db1     = (const float*)d_in[8];
    const float* dw2     = (const float*)d_in[9];
    const float* db2     = (const float*)d_in[10];
    const float* dw3     = (const float*)d_in[11];
    const float* db3     = (const float*)d_in[12];
    float* out = (float*)d_out;

    convert_c1w_kernel<<<256, 128>>>(conv1_w);
    convert_w_kernel<<<C1, 256>>>(pc_w);
    convert_dec_kernel<<<(1024 * 784 + 255) / 256, 256>>>(dw2, dw3);

    cudaFuncSetAttribute(conv1_gemm_kernel, cudaFuncAttributeMaxDynamicSharedMemorySize, C1_SMEM);
    conv1_gemm_kernel<<<dim3(800, 2), 512, C1_SMEM>>>(inputs, conv1_b);

    cudaFuncSetAttribute(gemm_kernel, cudaFuncAttributeMaxDynamicSharedMemorySize, GEMM_SMEM);
    gemm_kernel<<<dim3(72, 2), 512, GEMM_SMEM>>>(pc_b);

    squash_u_kernel<<<NPRIM, 256>>>();
    wu_kernel<<<NPRIM, 160>>>(rw);

    cudaFuncSetAttribute(routing_kernel, cudaFuncAttributeMaxDynamicSharedMemorySize, ROUT_SMEM);
    routing_kernel<<<BATCH, 320, ROUT_SMEM>>>(out);

    decoder_kernel<<<BATCH / 2, 256>>>(labels, dw1, db1, db2, db3, out);
}